// round 3
// baseline (speedup 1.0000x reference)
#include <cuda_runtime.h>
#include <cuda_bf16.h>
#include <math.h>

// Problem constants
#define BB   4
#define HH   16
#define LL   2048
#define DD   1024
#define HD   64      // head dim
#define CH   128     // chunk
#define NC   16      // chunks per sequence
#define MM   (BB*LL) // 8192 rows

// ---------------- scratch (device globals; no runtime allocation) ----------------
__device__ float g_q[BB*HH*LL*HD];     // (B,H,L,d)
__device__ float g_k[BB*HH*LL*HD];
__device__ float g_v[BB*HH*LL*HD];
__device__ float g_S[BB*HH*NC*HD*HD];  // per-chunk kv state -> exclusive prefix
__device__ float g_z[BB*HH*NC*HD];     // per-chunk k_sum -> exclusive prefix
__device__ float g_o[BB*LL*DD];        // attention output in (B,L,D)

// ---------------- packed fp32x2 helpers (Blackwell dual-FP32) ----------------
__device__ __forceinline__ unsigned long long pack2(float lo, float hi) {
    unsigned long long r;
    asm("mov.b64 %0, {%1, %2};" : "=l"(r) : "f"(lo), "f"(hi));
    return r;
}
__device__ __forceinline__ void unpack2(unsigned long long v, float& lo, float& hi) {
    asm("mov.b64 {%0, %1}, %2;" : "=f"(lo), "=f"(hi) : "l"(v));
}
__device__ __forceinline__ void ffma2(unsigned long long& d, unsigned long long a, unsigned long long b) {
    asm("fma.rn.f32x2 %0, %1, %2, %0;" : "+l"(d) : "l"(a), "l"(b));
}

// =======================================================================
// GEMM: Y = A @ W^T + bias   (A: M x 1024 row-major, W: 1024 x 1024 row-major)
// qkv_mode=1: grid.x = 24 (3 weights x 8 n-blocks); silu for q,k; scatter
//             into (B,H,L,d) layout of g_q/g_k/g_v.
// qkv_mode=0: grid.x = 8; A = g_o; plain row-major output to outp.
// 128x128x32 tiles, 256 threads, 8x8 microtile via packed f32x2 FMA.
// =======================================================================
__global__ __launch_bounds__(256, 2) void gemm_kernel(
    const float* __restrict__ Ain,
    const float* __restrict__ W0, const float* __restrict__ W1, const float* __restrict__ W2,
    const float* __restrict__ b0, const float* __restrict__ b1, const float* __restrict__ b2,
    float* __restrict__ outp, int qkv_mode)
{
    __shared__ float As[32 * 128];
    __shared__ float Bs[32 * 128];

    const int bnx = blockIdx.x;
    const float* A;
    const float* W;
    const float* bias;
    float* out;
    int do_silu, scatter, n0;

    if (qkv_mode) {
        int w = bnx >> 3;
        W    = (w == 0) ? W0 : (w == 1) ? W1 : W2;
        bias = (w == 0) ? b0 : (w == 1) ? b1 : b2;
        out  = (w == 0) ? g_q : (w == 1) ? g_k : g_v;
        do_silu = (w < 2);
        scatter = 1;
        n0 = (bnx & 7) * 128;
        A = Ain;
    } else {
        W = W0; bias = b0; out = outp;
        do_silu = 0; scatter = 0;
        n0 = bnx * 128;
        A = g_o;
    }

    const int m0 = blockIdx.y * 128;
    const int tid = threadIdx.x;
    const int tx = tid & 15, ty = tid >> 4;

    unsigned long long c2[8][4];
#pragma unroll
    for (int ii = 0; ii < 8; ii++)
#pragma unroll
        for (int jj = 0; jj < 4; jj++) c2[ii][jj] = 0ull;

    for (int k0 = 0; k0 < 1024; k0 += 32) {
        // Cooperative load + transpose into smem: warp covers 32 consecutive
        // rows at a fixed 4-wide k-group -> conflict-free scalar stores.
#pragma unroll
        for (int i = 0; i < 4; i++) {
            int idx = tid + i * 256;
            int r  = idx & 127;
            int kg = idx >> 7;      // 0..7
            float4 av = *reinterpret_cast<const float4*>(A + (size_t)(m0 + r) * 1024 + k0 + kg * 4);
            float4 wv = *reinterpret_cast<const float4*>(W + (size_t)(n0 + r) * 1024 + k0 + kg * 4);
            int kb = kg * 4;
            As[(kb + 0) * 128 + r] = av.x;
            As[(kb + 1) * 128 + r] = av.y;
            As[(kb + 2) * 128 + r] = av.z;
            As[(kb + 3) * 128 + r] = av.w;
            Bs[(kb + 0) * 128 + r] = wv.x;
            Bs[(kb + 1) * 128 + r] = wv.y;
            Bs[(kb + 2) * 128 + r] = wv.z;
            Bs[(kb + 3) * 128 + r] = wv.w;
        }
        __syncthreads();

#pragma unroll 8
        for (int kk = 0; kk < 32; kk++) {
            const float* ap = &As[kk * 128 + ty * 8];
            float4 a0 = *reinterpret_cast<const float4*>(ap);
            float4 a1 = *reinterpret_cast<const float4*>(ap + 4);
            const unsigned long long* bp =
                reinterpret_cast<const unsigned long long*>(&Bs[kk * 128 + tx * 8]);
            unsigned long long bb0 = bp[0], bb1 = bp[1], bb2 = bp[2], bb3 = bp[3];
            unsigned long long ad[8];
            ad[0] = pack2(a0.x, a0.x); ad[1] = pack2(a0.y, a0.y);
            ad[2] = pack2(a0.z, a0.z); ad[3] = pack2(a0.w, a0.w);
            ad[4] = pack2(a1.x, a1.x); ad[5] = pack2(a1.y, a1.y);
            ad[6] = pack2(a1.z, a1.z); ad[7] = pack2(a1.w, a1.w);
#pragma unroll
            for (int ii = 0; ii < 8; ii++) {
                ffma2(c2[ii][0], ad[ii], bb0);
                ffma2(c2[ii][1], ad[ii], bb1);
                ffma2(c2[ii][2], ad[ii], bb2);
                ffma2(c2[ii][3], ad[ii], bb3);
            }
        }
        __syncthreads();
    }

    // Epilogue
#pragma unroll
    for (int ii = 0; ii < 8; ii++) {
        int m = m0 + ty * 8 + ii;
        int bidx = m >> 11;       // batch
        int l    = m & 2047;      // position
#pragma unroll
        for (int jj = 0; jj < 4; jj++) {
            float lo, hi;
            unpack2(c2[ii][jj], lo, hi);
            int n = n0 + tx * 8 + jj * 2;
            lo += bias[n];
            hi += bias[n + 1];
            if (do_silu) {
                lo = lo / (1.f + expf(-lo));
                hi = hi / (1.f + expf(-hi));
            }
            if (scatter) {
                int h = n >> 6, i2 = n & 63;   // pair never straddles a head (even-aligned)
                float* p = out + ((size_t)((bidx << 4) | h) * 2048 + l) * 64 + i2;
                p[0] = lo; p[1] = hi;
            } else {
                out[(size_t)m * 1024 + n]     = lo;
                out[(size_t)m * 1024 + n + 1] = hi;
            }
        }
    }
}

// =======================================================================
// Per-chunk state: kv[d][e] = sum_t k[t][d]*v[t][e], ksum[d] = sum_t k[t][d]
// grid = B*H*NC = 1024 blocks, 256 threads, dyn smem 64KB
// =======================================================================
__global__ __launch_bounds__(256) void chunk_state_kernel()
{
    extern __shared__ float sm[];
    float* ks  = sm;         // [t][d] 128x64
    float* vsm = sm + 8192;  // [t][e] 128x64

    int cid = blockIdx.x;
    int bh = cid >> 4, nch = cid & 15;
    size_t base = ((size_t)bh * LL + (size_t)nch * CH) * HD;
    int tid = threadIdx.x;

    const float4* kg4 = reinterpret_cast<const float4*>(g_k + base);
    const float4* vg4 = reinterpret_cast<const float4*>(g_v + base);
    for (int i4 = tid; i4 < 2048; i4 += 256) {
        reinterpret_cast<float4*>(ks)[i4]  = kg4[i4];
        reinterpret_cast<float4*>(vsm)[i4] = vg4[i4];
    }
    __syncthreads();

    int tx = tid & 15, ty = tid >> 4;
    int i0 = ty * 4, j0 = tx * 4;
    float c[4][4] = {};
#pragma unroll 4
    for (int t = 0; t < 128; t++) {
        float4 a = *reinterpret_cast<const float4*>(&ks[t * 64 + i0]);
        float4 b = *reinterpret_cast<const float4*>(&vsm[t * 64 + j0]);
        float av[4] = {a.x, a.y, a.z, a.w};
        float bv[4] = {b.x, b.y, b.z, b.w};
#pragma unroll
        for (int ii = 0; ii < 4; ii++)
#pragma unroll
            for (int jj = 0; jj < 4; jj++) c[ii][jj] += av[ii] * bv[jj];
    }
    float* Sp = g_S + (size_t)cid * 4096;
#pragma unroll
    for (int ii = 0; ii < 4; ii++) {
        float4 o4 = make_float4(c[ii][0], c[ii][1], c[ii][2], c[ii][3]);
        *reinterpret_cast<float4*>(&Sp[(i0 + ii) * 64 + j0]) = o4;
    }
    if (tid < 64) {
        float s = 0.f;
#pragma unroll 4
        for (int t = 0; t < 128; t++) s += ks[t * 64 + tid];
        g_z[(size_t)cid * 64 + tid] = s;
    }
}

// =======================================================================
// Exclusive prefix over the NC=16 chunks of S and z. grid = B*H = 64.
// =======================================================================
__global__ __launch_bounds__(256) void prefix_kernel()
{
    int bh = blockIdx.x;
    int tid = threadIdx.x;
    for (int e = tid; e < 4096; e += 256) {
        float run = 0.f;
#pragma unroll
        for (int n = 0; n < NC; n++) {
            size_t idx = ((size_t)bh * NC + n) * 4096 + e;
            float t = g_S[idx];
            g_S[idx] = run;
            run += t;
        }
    }
    if (tid < 64) {
        float run = 0.f;
#pragma unroll
        for (int n = 0; n < NC; n++) {
            size_t idx = ((size_t)bh * NC + n) * 64 + tid;
            float t = g_z[idx];
            g_z[idx] = run;
            run += t;
        }
    }
}

// =======================================================================
// Intra-chunk attention. grid = B*H*NC = 1024 blocks, 256 threads.
// scores = tril(q k^T); den = rowsum(scores) + q.z; num = scores@v + q@S;
// out = num / max(den, 1e-3)  -> g_o in (B,L,D) layout.
// =======================================================================
__global__ __launch_bounds__(256) void intra_kernel()
{
    extern __shared__ float sm[];
    const int LDT  = 132;  // padded stride for qT/kT (transposed [d][t])
    const int LDS2 = 129;  // padded stride for scores^T [j][i]
    float* qT  = sm;                 // 64*132
    float* kT  = qT + 64 * LDT;      // 64*132
    float* vs  = kT + 64 * LDT;      // 128*64
    float* scT = vs + 128 * 64;      // 128*129
    float* Ss  = scT + 128 * LDS2;   // 64*64
    float* zs  = Ss + 64 * 64;       // 64
    float* den = zs + 64;            // 128

    int cid = blockIdx.x;
    int bh = cid >> 4, nch = cid & 15;
    size_t base = ((size_t)bh * LL + (size_t)nch * CH) * HD;
    const float* qg  = g_q + base;
    const float* kgp = g_k + base;
    const float* vgp = g_v + base;
    int tid = threadIdx.x;

    for (int idx = tid; idx < 8192; idx += 256) {
        int t = idx >> 6, i = idx & 63;
        qT[i * LDT + t] = qg[idx];
        kT[i * LDT + t] = kgp[idx];
        vs[idx] = vgp[idx];
    }
    for (int idx = tid; idx < 4096; idx += 256) Ss[idx] = g_S[(size_t)cid * 4096 + idx];
    if (tid < 64) zs[tid] = g_z[(size_t)cid * 64 + tid];
    __syncthreads();

    const int tx = tid & 15, ty = tid >> 4;

    // ---- phase 1: masked scores -> scT[j][i] ----
    {
        float c[8][8];
#pragma unroll
        for (int ii = 0; ii < 8; ii++)
#pragma unroll
            for (int jj = 0; jj < 8; jj++) c[ii][jj] = 0.f;
        int i0 = ty * 8, j0 = tx * 8;
#pragma unroll 4
        for (int kk = 0; kk < 64; kk++) {
            float4 a0 = *reinterpret_cast<const float4*>(&qT[kk * LDT + i0]);
            float4 a1 = *reinterpret_cast<const float4*>(&qT[kk * LDT + i0 + 4]);
            float4 b0 = *reinterpret_cast<const float4*>(&kT[kk * LDT + j0]);
            float4 b1 = *reinterpret_cast<const float4*>(&kT[kk * LDT + j0 + 4]);
            float a[8] = {a0.x, a0.y, a0.z, a0.w, a1.x, a1.y, a1.z, a1.w};
            float b[8] = {b0.x, b0.y, b0.z, b0.w, b1.x, b1.y, b1.z, b1.w};
#pragma unroll
            for (int ii = 0; ii < 8; ii++)
#pragma unroll
                for (int jj = 0; jj < 8; jj++) c[ii][jj] += a[ii] * b[jj];
        }
#pragma unroll
        for (int jj = 0; jj < 8; jj++) {
            int j = j0 + jj;
#pragma unroll
            for (int ii = 0; ii < 8; ii++) {
                int i = i0 + ii;
                scT[j * LDS2 + i] = (j <= i) ? c[ii][jj] : 0.f;
            }
        }
    }
    __syncthreads();

    // ---- phase 1.5: denominators ----
    if (tid < 128) {
        float s = 0.f;
        for (int j = 0; j < 128; j++) s += scT[j * LDS2 + tid];
        float s2 = 0.f;
        for (int dd = 0; dd < 64; dd++) s2 += qT[dd * LDT + tid] * zs[dd];
        den[tid] = fmaxf(s + s2, 1e-3f);
    }
    __syncthreads();

    // ---- phase 2: num = scores@v + q@S ; out = num/den ----
    {
        int ex = tid & 15, iy = tid >> 4;
        int i0 = iy * 8, e0 = ex * 4;
        float c[8][4];
#pragma unroll
        for (int ii = 0; ii < 8; ii++)
#pragma unroll
            for (int jj = 0; jj < 4; jj++) c[ii][jj] = 0.f;

#pragma unroll 4
        for (int j = 0; j < 128; j++) {
            float4 b = *reinterpret_cast<const float4*>(&vs[j * 64 + e0]);
#pragma unroll
            for (int ii = 0; ii < 8; ii++) {
                float a = scT[j * LDS2 + i0 + ii];
                c[ii][0] += a * b.x; c[ii][1] += a * b.y;
                c[ii][2] += a * b.z; c[ii][3] += a * b.w;
            }
        }
#pragma unroll 4
        for (int dd = 0; dd < 64; dd++) {
            float4 b  = *reinterpret_cast<const float4*>(&Ss[dd * 64 + e0]);
            float4 a0 = *reinterpret_cast<const float4*>(&qT[dd * LDT + i0]);
            float4 a1 = *reinterpret_cast<const float4*>(&qT[dd * LDT + i0 + 4]);
            float a[8] = {a0.x, a0.y, a0.z, a0.w, a1.x, a1.y, a1.z, a1.w};
#pragma unroll
            for (int ii = 0; ii < 8; ii++) {
                c[ii][0] += a[ii] * b.x; c[ii][1] += a[ii] * b.y;
                c[ii][2] += a[ii] * b.z; c[ii][3] += a[ii] * b.w;
            }
        }
        int bidx = bh >> 4, h = bh & 15;
#pragma unroll
        for (int ii = 0; ii < 8; ii++) {
            int i = i0 + ii;
            float r = 1.f / den[i];
            int l = nch * CH + i;
            float4 o4 = make_float4(c[ii][0] * r, c[ii][1] * r, c[ii][2] * r, c[ii][3] * r);
            *reinterpret_cast<float4*>(&g_o[((size_t)bidx * LL + l) * DD + h * 64 + e0]) = o4;
        }
    }
}

// =======================================================================
extern "C" void kernel_launch(void* const* d_in, const int* in_sizes, int n_in,
                              void* d_out, int out_size)
{
    const float* x  = (const float*)d_in[0];
    const float* Wq = (const float*)d_in[1];
    const float* bq = (const float*)d_in[2];
    const float* Wk = (const float*)d_in[3];
    const float* bk = (const float*)d_in[4];
    const float* Wv = (const float*)d_in[5];
    const float* bv = (const float*)d_in[6];
    const float* Wo = (const float*)d_in[7];
    const float* bo = (const float*)d_in[8];
    float* out = (float*)d_out;

    static const int INTRA_SMEM = (64 * 132 * 2 + 128 * 64 + 128 * 129 + 64 * 64 + 64 + 128) * 4;
    cudaFuncSetAttribute(chunk_state_kernel, cudaFuncAttributeMaxDynamicSharedMemorySize, 65536);
    cudaFuncSetAttribute(intra_kernel, cudaFuncAttributeMaxDynamicSharedMemorySize, INTRA_SMEM);

    // 1) fused QKV projection (3 weights in one launch): 24 n-blocks x 64 m-blocks
    gemm_kernel<<<dim3(24, 64), 256>>>(x, Wq, Wk, Wv, bq, bk, bv, nullptr, 1);

    // 2) per-chunk kv state + k sums
    chunk_state_kernel<<<BB * HH * NC, 256, 65536>>>();

    // 3) exclusive prefix over chunks
    prefix_kernel<<<BB * HH, 256>>>();

    // 4) intra-chunk attention
    intra_kernel<<<BB * HH * NC, 256, INTRA_SMEM>>>();

    // 5) output projection
    gemm_kernel<<<dim3(8, 64), 256>>>(nullptr, Wo, Wo, Wo, bo, bo, bo, out, 0);
}

// round 6
// speedup vs baseline: 2.3518x; 2.3518x over previous
#include <cuda_runtime.h>
#include <cuda_bf16.h>
#include <math.h>
#include <stdint.h>

// Problem constants
#define BB   4
#define HH   16
#define LL   2048
#define DD   1024
#define HD   64
#define CH   128
#define NC   16

// ---------------- scratch (device globals) ----------------
__device__ float g_q[BB*HH*LL*HD];
__device__ float g_k[BB*HH*LL*HD];
__device__ float g_v[BB*HH*LL*HD];
__device__ float g_S[BB*HH*NC*HD*HD];
__device__ float g_z[BB*HH*NC*HD];
__device__ __nv_bfloat16 g_xh[BB*LL*DD];   // x split hi/lo
__device__ __nv_bfloat16 g_xl[BB*LL*DD];
__device__ __nv_bfloat16 g_wh[4*DD*DD];    // Wq,Wk,Wv,Wo split hi
__device__ __nv_bfloat16 g_wl[4*DD*DD];    // ... lo
__device__ __nv_bfloat16 g_oh[BB*LL*DD];   // attention out split hi/lo
__device__ __nv_bfloat16 g_ol[BB*LL*DD];

// ---------------- PTX helpers ----------------
__device__ __forceinline__ uint32_t s2u(const void* p) {
    uint32_t a;
    asm("{ .reg .u64 t; cvta.to.shared.u64 t, %1; cvt.u32.u64 %0, t; }" : "=r"(a) : "l"(p));
    return a;
}
__device__ __forceinline__ void cp16(uint32_t s, const void* g) {
    asm volatile("cp.async.cg.shared.global [%0], [%1], 16;" :: "r"(s), "l"(g) : "memory");
}
__device__ __forceinline__ void ldm_x4(uint32_t* r, uint32_t addr) {
    asm volatile("ldmatrix.sync.aligned.m8n8.x4.shared.b16 {%0,%1,%2,%3}, [%4];"
        : "=r"(r[0]), "=r"(r[1]), "=r"(r[2]), "=r"(r[3]) : "r"(addr));
}
__device__ __forceinline__ void ldm_x2(uint32_t* r, uint32_t addr) {
    asm volatile("ldmatrix.sync.aligned.m8n8.x2.shared.b16 {%0,%1}, [%2];"
        : "=r"(r[0]), "=r"(r[1]) : "r"(addr));
}
__device__ __forceinline__ void mma16816(float* d, const uint32_t* a, const uint32_t* b) {
    asm volatile("mma.sync.aligned.m16n8k16.row.col.f32.bf16.bf16.f32 "
        "{%0,%1,%2,%3}, {%4,%5,%6,%7}, {%8,%9}, {%0,%1,%2,%3};"
        : "+f"(d[0]), "+f"(d[1]), "+f"(d[2]), "+f"(d[3])
        : "r"(a[0]), "r"(a[1]), "r"(a[2]), "r"(a[3]), "r"(b[0]), "r"(b[1]));
}

// ---------------- split fp32 -> bf16 hi + bf16 lo ----------------
__global__ __launch_bounds__(256) void split_kernel(
    const float* __restrict__ src, __nv_bfloat16* __restrict__ dh,
    __nv_bfloat16* __restrict__ dl, int n)
{
    int i = (blockIdx.x * 256 + threadIdx.x) * 4;
    if (i >= n) return;
    float4 v = *reinterpret_cast<const float4*>(src + i);
    __nv_bfloat16 h0 = __float2bfloat16(v.x), h1 = __float2bfloat16(v.y);
    __nv_bfloat16 h2 = __float2bfloat16(v.z), h3 = __float2bfloat16(v.w);
    __nv_bfloat16 l0 = __float2bfloat16(v.x - __bfloat162float(h0));
    __nv_bfloat16 l1 = __float2bfloat16(v.y - __bfloat162float(h1));
    __nv_bfloat16 l2 = __float2bfloat16(v.z - __bfloat162float(h2));
    __nv_bfloat16 l3 = __float2bfloat16(v.w - __bfloat162float(h3));
    __nv_bfloat162 ph0; ph0.x = h0; ph0.y = h1;
    __nv_bfloat162 ph1; ph1.x = h2; ph1.y = h3;
    __nv_bfloat162 pl0; pl0.x = l0; pl0.y = l1;
    __nv_bfloat162 pl1; pl1.x = l2; pl1.y = l3;
    *reinterpret_cast<__nv_bfloat162*>(dh + i)     = ph0;
    *reinterpret_cast<__nv_bfloat162*>(dh + i + 2) = ph1;
    *reinterpret_cast<__nv_bfloat162*>(dl + i)     = pl0;
    *reinterpret_cast<__nv_bfloat162*>(dl + i + 2) = pl1;
}

// =======================================================================
// HMMA split-bf16 GEMM: D = A @ W^T (+bias, opt silu, opt scatter)
// CTA 128x128, 256 threads (8 warps, 2x4), warp tile 64x32.
// K in chunks of 32 (two k16 halves); per k16: 16 mma tiles x 3 splits.
// 4-stage cp.async pipeline. smem rows padded to 80B for conflict-free
// ldmatrix. Stage = [Ah|Al|Bh|Bl], each 128 rows x 32 bf16.
// =======================================================================
#define LDS_B   80                    // bytes per smem row (32 bf16 + 8 pad)
#define MAT_B   (128 * LDS_B)         // 10240
#define STAGE_B (4 * MAT_B)           // 40960
#define STAGES  4
#define GEMM_SMEM (STAGES * STAGE_B)  // 163840

__global__ __launch_bounds__(256, 1) void gemm_tc(
    const __nv_bfloat16* __restrict__ Ah0, const __nv_bfloat16* __restrict__ Al0,
    const float* __restrict__ bq, const float* __restrict__ bk, const float* __restrict__ bv,
    float* __restrict__ outp, int qkv_mode)
{
    extern __shared__ char smem[];
    const uint32_t sb = s2u(smem);
    const int tid = threadIdx.x;
    const int wid = tid >> 5, lane = tid & 31;
    const int wm = wid & 1, wn = wid >> 1;

    const __nv_bfloat16 *Ah, *Al, *Bh, *Bl;
    const float* bias;
    float* qkv_out = nullptr;
    int n0, do_silu;
    if (qkv_mode) {
        int w = blockIdx.x >> 3;
        Bh = g_wh + (size_t)w * (DD * DD);
        Bl = g_wl + (size_t)w * (DD * DD);
        bias = (w == 0) ? bq : (w == 1) ? bk : bv;
        qkv_out = (w == 0) ? g_q : (w == 1) ? g_k : g_v;
        do_silu = (w < 2);
        n0 = (blockIdx.x & 7) * 128;
        Ah = Ah0; Al = Al0;
    } else {
        Bh = g_wh + 3 * (size_t)(DD * DD);
        Bl = g_wl + 3 * (size_t)(DD * DD);
        bias = bq; do_silu = 0;
        n0 = blockIdx.x * 128;
        Ah = g_oh; Al = g_ol;
    }
    const int m0 = blockIdx.y * 128;

    float acc[4][4][4];
#pragma unroll
    for (int a = 0; a < 4; a++)
#pragma unroll
        for (int b = 0; b < 4; b++)
#pragma unroll
            for (int c = 0; c < 4; c++) acc[a][b][c] = 0.f;

    auto load_chunk = [&](int cc) {
        const int kc = cc * 32;
        const uint32_t st = sb + (uint32_t)(cc & (STAGES - 1)) * STAGE_B;
#pragma unroll
        for (int mat = 0; mat < 4; mat++) {
            const __nv_bfloat16* base =
                (mat == 0) ? Ah : (mat == 1) ? Al : (mat == 2) ? Bh : Bl;
            const int rowoff = (mat < 2) ? m0 : n0;
#pragma unroll
            for (int i = 0; i < 2; i++) {
                int idx = tid + i * 256;     // 0..511
                int r = idx >> 2, g = idx & 3;
                cp16(st + (uint32_t)(mat * MAT_B + r * LDS_B + g * 16),
                     base + (size_t)(rowoff + r) * DD + kc + g * 8);
            }
        }
        asm volatile("cp.async.commit_group;" ::: "memory");
    };

    load_chunk(0);
    load_chunk(1);

    // per-lane static smem offsets
    const int arow = wm * 64 + (lane & 15);
    const int acol = (lane >> 4) * 8;
    const int brow = wn * 32 + (lane & 7);
    const int bcol = ((lane >> 3) & 1) * 8;

    const int NK = 1024 / 32;   // 32 chunks
    for (int c = 0; c < NK; c++) {
        if (c + 2 < NK) load_chunk(c + 2);
        if (c < NK - 2)      asm volatile("cp.async.wait_group 2;" ::: "memory");
        else if (c == NK - 2) asm volatile("cp.async.wait_group 1;" ::: "memory");
        else                 asm volatile("cp.async.wait_group 0;" ::: "memory");
        __syncthreads();

        const uint32_t st  = sb + (uint32_t)(c & (STAGES - 1)) * STAGE_B;
        const uint32_t aAh = st, aAl = st + MAT_B, aBh = st + 2 * MAT_B, aBl = st + 3 * MAT_B;

#pragma unroll
        for (int h = 0; h < 2; h++) {
            uint32_t ah[4][4], al[4][4];
#pragma unroll
            for (int mt = 0; mt < 4; mt++) {
                uint32_t off = (uint32_t)((arow + mt * 16) * LDS_B + (acol + h * 16) * 2);
                ldm_x4(ah[mt], aAh + off);
                ldm_x4(al[mt], aAl + off);
            }
            uint32_t bhf[4][2], blf[4][2];
#pragma unroll
            for (int nt = 0; nt < 4; nt++) {
                uint32_t off = (uint32_t)((brow + nt * 8) * LDS_B + (bcol + h * 16) * 2);
                ldm_x2(bhf[nt], aBh + off);
                ldm_x2(blf[nt], aBl + off);
            }
#pragma unroll
            for (int mt = 0; mt < 4; mt++)
#pragma unroll
                for (int nt = 0; nt < 4; nt++) {
                    mma16816(acc[mt][nt], ah[mt], bhf[nt]);
                    mma16816(acc[mt][nt], ah[mt], blf[nt]);
                    mma16816(acc[mt][nt], al[mt], bhf[nt]);
                }
        }
    }

    // ---- epilogue: bias + opt silu + scatter ----
    float bv2[4][2];
#pragma unroll
    for (int nt = 0; nt < 4; nt++) {
        int col = n0 + wn * 32 + nt * 8 + 2 * (lane & 3);
        bv2[nt][0] = bias[col];
        bv2[nt][1] = bias[col + 1];
    }
#pragma unroll
    for (int mt = 0; mt < 4; mt++) {
#pragma unroll
        for (int half = 0; half < 2; half++) {
            int m = m0 + wm * 64 + mt * 16 + (lane >> 2) + half * 8;
            int b = m >> 11, lpos = m & 2047;
#pragma unroll
            for (int nt = 0; nt < 4; nt++) {
                int col = n0 + wn * 32 + nt * 8 + 2 * (lane & 3);
                float v0 = acc[mt][nt][half * 2 + 0] + bv2[nt][0];
                float v1 = acc[mt][nt][half * 2 + 1] + bv2[nt][1];
                if (do_silu) {
                    v0 = v0 / (1.f + expf(-v0));
                    v1 = v1 / (1.f + expf(-v1));
                }
                if (qkv_mode) {
                    int hidx = col >> 6, i2 = col & 63;
                    float* p = qkv_out + ((size_t)((b << 4) | hidx) * LL + lpos) * HD + i2;
                    *reinterpret_cast<float2*>(p) = make_float2(v0, v1);
                } else {
                    *reinterpret_cast<float2*>(outp + (size_t)m * DD + col) =
                        make_float2(v0, v1);
                }
            }
        }
    }
}

// =======================================================================
// Per-chunk state: kv[d][e] = sum_t k[t][d]*v[t][e], ksum[d] = sum_t k[t][d]
// =======================================================================
__global__ __launch_bounds__(256) void chunk_state_kernel()
{
    extern __shared__ float sm[];
    float* ks  = sm;
    float* vsm = sm + 8192;

    int cid = blockIdx.x;
    int bh = cid >> 4, nch = cid & 15;
    size_t base = ((size_t)bh * LL + (size_t)nch * CH) * HD;
    int tid = threadIdx.x;

    const float4* kg4 = reinterpret_cast<const float4*>(g_k + base);
    const float4* vg4 = reinterpret_cast<const float4*>(g_v + base);
    for (int i4 = tid; i4 < 2048; i4 += 256) {
        reinterpret_cast<float4*>(ks)[i4]  = kg4[i4];
        reinterpret_cast<float4*>(vsm)[i4] = vg4[i4];
    }
    __syncthreads();

    int tx = tid & 15, ty = tid >> 4;
    int i0 = ty * 4, j0 = tx * 4;
    float c[4][4] = {};
#pragma unroll 4
    for (int t = 0; t < 128; t++) {
        float4 a = *reinterpret_cast<const float4*>(&ks[t * 64 + i0]);
        float4 bvv = *reinterpret_cast<const float4*>(&vsm[t * 64 + j0]);
        float av[4] = {a.x, a.y, a.z, a.w};
        float bw[4] = {bvv.x, bvv.y, bvv.z, bvv.w};
#pragma unroll
        for (int ii = 0; ii < 4; ii++)
#pragma unroll
            for (int jj = 0; jj < 4; jj++) c[ii][jj] += av[ii] * bw[jj];
    }
    float* Sp = g_S + (size_t)cid * 4096;
#pragma unroll
    for (int ii = 0; ii < 4; ii++) {
        float4 o4 = make_float4(c[ii][0], c[ii][1], c[ii][2], c[ii][3]);
        *reinterpret_cast<float4*>(&Sp[(i0 + ii) * 64 + j0]) = o4;
    }
    if (tid < 64) {
        float s = 0.f;
#pragma unroll 4
        for (int t = 0; t < 128; t++) s += ks[t * 64 + tid];
        g_z[(size_t)cid * 64 + tid] = s;
    }
}

// =======================================================================
// Exclusive prefix over NC chunks of S and z.
// =======================================================================
__global__ __launch_bounds__(256) void prefix_kernel()
{
    int bh = blockIdx.x;
    int tid = threadIdx.x;
    for (int e = tid; e < 4096; e += 256) {
        float run = 0.f;
#pragma unroll
        for (int n = 0; n < NC; n++) {
            size_t idx = ((size_t)bh * NC + n) * 4096 + e;
            float t = g_S[idx];
            g_S[idx] = run;
            run += t;
        }
    }
    if (tid < 64) {
        float run = 0.f;
#pragma unroll
        for (int n = 0; n < NC; n++) {
            size_t idx = ((size_t)bh * NC + n) * 64 + tid;
            float t = g_z[idx];
            g_z[idx] = run;
            run += t;
        }
    }
}

// =======================================================================
// Intra-chunk attention; writes bf16 hi/lo split output for the O-proj GEMM.
// =======================================================================
__global__ __launch_bounds__(256) void intra_kernel()
{
    extern __shared__ float sm[];
    const int LDT  = 132;
    const int LDS2 = 129;
    float* qT  = sm;
    float* kT  = qT + 64 * LDT;
    float* vs  = kT + 64 * LDT;
    float* scT = vs + 128 * 64;
    float* Ss  = scT + 128 * LDS2;
    float* zs  = Ss + 64 * 64;
    float* den = zs + 64;

    int cid = blockIdx.x;
    int bh = cid >> 4, nch = cid & 15;
    size_t base = ((size_t)bh * LL + (size_t)nch * CH) * HD;
    const float* qg  = g_q + base;
    const float* kgp = g_k + base;
    const float* vgp = g_v + base;
    int tid = threadIdx.x;

    for (int idx = tid; idx < 8192; idx += 256) {
        int t = idx >> 6, i = idx & 63;
        qT[i * LDT + t] = qg[idx];
        kT[i * LDT + t] = kgp[idx];
        vs[idx] = vgp[idx];
    }
    for (int idx = tid; idx < 4096; idx += 256) Ss[idx] = g_S[(size_t)cid * 4096 + idx];
    if (tid < 64) zs[tid] = g_z[(size_t)cid * 64 + tid];
    __syncthreads();

    const int tx = tid & 15, ty = tid >> 4;

    // phase 1: masked scores -> scT[j][i]
    {
        float c[8][8];
#pragma unroll
        for (int ii = 0; ii < 8; ii++)
#pragma unroll
            for (int jj = 0; jj < 8; jj++) c[ii][jj] = 0.f;
        int i0 = ty * 8, j0 = tx * 8;
#pragma unroll 4
        for (int kk = 0; kk < 64; kk++) {
            float4 a0 = *reinterpret_cast<const float4*>(&qT[kk * LDT + i0]);
            float4 a1 = *reinterpret_cast<const float4*>(&qT[kk * LDT + i0 + 4]);
            float4 b0 = *reinterpret_cast<const float4*>(&kT[kk * LDT + j0]);
            float4 b1 = *reinterpret_cast<const float4*>(&kT[kk * LDT + j0 + 4]);
            float a[8] = {a0.x, a0.y, a0.z, a0.w, a1.x, a1.y, a1.z, a1.w};
            float bx[8] = {b0.x, b0.y, b0.z, b0.w, b1.x, b1.y, b1.z, b1.w};
#pragma unroll
            for (int ii = 0; ii < 8; ii++)
#pragma unroll
                for (int jj = 0; jj < 8; jj++) c[ii][jj] += a[ii] * bx[jj];
        }
#pragma unroll
        for (int jj = 0; jj < 8; jj++) {
            int j = j0 + jj;
#pragma unroll
            for (int ii = 0; ii < 8; ii++) {
                int i = i0 + ii;
                scT[j * LDS2 + i] = (j <= i) ? c[ii][jj] : 0.f;
            }
        }
    }
    __syncthreads();

    // phase 1.5: denominators
    if (tid < 128) {
        float s = 0.f;
        for (int j = 0; j < 128; j++) s += scT[j * LDS2 + tid];
        float s2 = 0.f;
        for (int dd = 0; dd < 64; dd++) s2 += qT[dd * LDT + tid] * zs[dd];
        den[tid] = fmaxf(s + s2, 1e-3f);
    }
    __syncthreads();

    // phase 2: num = scores@v + q@S ; out = num/den -> bf16 hi/lo split
    {
        int ex = tid & 15, iy = tid >> 4;
        int i0 = iy * 8, e0 = ex * 4;
        float c[8][4];
#pragma unroll
        for (int ii = 0; ii < 8; ii++)
#pragma unroll
            for (int jj = 0; jj < 4; jj++) c[ii][jj] = 0.f;

#pragma unroll 4
        for (int j = 0; j < 128; j++) {
            float4 bvv = *reinterpret_cast<const float4*>(&vs[j * 64 + e0]);
#pragma unroll
            for (int ii = 0; ii < 8; ii++) {
                float a = scT[j * LDS2 + i0 + ii];
                c[ii][0] += a * bvv.x; c[ii][1] += a * bvv.y;
                c[ii][2] += a * bvv.z; c[ii][3] += a * bvv.w;
            }
        }
#pragma unroll 4
        for (int dd = 0; dd < 64; dd++) {
            float4 bvv = *reinterpret_cast<const float4*>(&Ss[dd * 64 + e0]);
            float4 a0 = *reinterpret_cast<const float4*>(&qT[dd * LDT + i0]);
            float4 a1 = *reinterpret_cast<const float4*>(&qT[dd * LDT + i0 + 4]);
            float a[8] = {a0.x, a0.y, a0.z, a0.w, a1.x, a1.y, a1.z, a1.w};
#pragma unroll
            for (int ii = 0; ii < 8; ii++) {
                c[ii][0] += a[ii] * bvv.x; c[ii][1] += a[ii] * bvv.y;
                c[ii][2] += a[ii] * bvv.z; c[ii][3] += a[ii] * bvv.w;
            }
        }
        int bidx = bh >> 4, hd = bh & 15;
#pragma unroll
        for (int ii = 0; ii < 8; ii++) {
            int i = i0 + ii;
            float r = 1.f / den[i];
            int l = nch * CH + i;
            float o0 = c[ii][0] * r, o1 = c[ii][1] * r, o2 = c[ii][2] * r, o3 = c[ii][3] * r;
            __nv_bfloat16 h0 = __float2bfloat16(o0), h1 = __float2bfloat16(o1);
            __nv_bfloat16 h2 = __float2bfloat16(o2), h3 = __float2bfloat16(o3);
            __nv_bfloat16 l0 = __float2bfloat16(o0 - __bfloat162float(h0));
            __nv_bfloat16 l1 = __float2bfloat16(o1 - __bfloat162float(h1));
            __nv_bfloat16 l2 = __float2bfloat16(o2 - __bfloat162float(h2));
            __nv_bfloat16 l3 = __float2bfloat16(o3 - __bfloat162float(h3));
            size_t obase = ((size_t)bidx * LL + l) * DD + hd * 64 + e0;
            __nv_bfloat162 ph0; ph0.x = h0; ph0.y = h1;
            __nv_bfloat162 ph1; ph1.x = h2; ph1.y = h3;
            __nv_bfloat162 pl0; pl0.x = l0; pl0.y = l1;
            __nv_bfloat162 pl1; pl1.x = l2; pl1.y = l3;
            *reinterpret_cast<__nv_bfloat162*>(g_oh + obase)     = ph0;
            *reinterpret_cast<__nv_bfloat162*>(g_oh + obase + 2) = ph1;
            *reinterpret_cast<__nv_bfloat162*>(g_ol + obase)     = pl0;
            *reinterpret_cast<__nv_bfloat162*>(g_ol + obase + 2) = pl1;
        }
    }
}

// =======================================================================
extern "C" void kernel_launch(void* const* d_in, const int* in_sizes, int n_in,
                              void* d_out, int out_size)
{
    const float* x  = (const float*)d_in[0];
    const float* Wq = (const float*)d_in[1];
    const float* bq = (const float*)d_in[2];
    const float* Wk = (const float*)d_in[3];
    const float* bk = (const float*)d_in[4];
    const float* Wv = (const float*)d_in[5];
    const float* bv = (const float*)d_in[6];
    const float* Wo = (const float*)d_in[7];
    const float* bo = (const float*)d_in[8];
    float* out = (float*)d_out;

    static const int INTRA_SMEM = (64 * 132 * 2 + 128 * 64 + 128 * 129 + 64 * 64 + 64 + 128) * 4;
    cudaFuncSetAttribute(chunk_state_kernel, cudaFuncAttributeMaxDynamicSharedMemorySize, 65536);
    cudaFuncSetAttribute(intra_kernel, cudaFuncAttributeMaxDynamicSharedMemorySize, INTRA_SMEM);
    cudaFuncSetAttribute(gemm_tc, cudaFuncAttributeMaxDynamicSharedMemorySize, GEMM_SMEM);

    __nv_bfloat16 *xh, *xl, *wh, *wl;
    cudaGetSymbolAddress((void**)&xh, g_xh);
    cudaGetSymbolAddress((void**)&xl, g_xl);
    cudaGetSymbolAddress((void**)&wh, g_wh);
    cudaGetSymbolAddress((void**)&wl, g_wl);

    // 0) split fp32 inputs into bf16 hi/lo pairs
    split_kernel<<<8192, 256>>>(x, xh, xl, BB * LL * DD);
    split_kernel<<<1024, 256>>>(Wq, wh,               wl,               DD * DD);
    split_kernel<<<1024, 256>>>(Wk, wh + 1 * DD * DD, wl + 1 * DD * DD, DD * DD);
    split_kernel<<<1024, 256>>>(Wv, wh + 2 * DD * DD, wl + 2 * DD * DD, DD * DD);
    split_kernel<<<1024, 256>>>(Wo, wh + 3 * DD * DD, wl + 3 * DD * DD, DD * DD);

    // 1) fused QKV projection on tensor cores (3 weights x 8 n-tiles x 64 m-tiles)
    gemm_tc<<<dim3(24, 64), 256, GEMM_SMEM>>>(xh, xl, bq, bk, bv, nullptr, 1);

    // 2) per-chunk kv state + k sums
    chunk_state_kernel<<<BB * HH * NC, 256, 65536>>>();

    // 3) exclusive prefix over chunks
    prefix_kernel<<<BB * HH, 256>>>();

    // 4) intra-chunk attention (emits bf16 hi/lo split)
    intra_kernel<<<BB * HH * NC, 256, INTRA_SMEM>>>();

    // 5) output projection on tensor cores
    gemm_tc<<<dim3(8, 64), 256, GEMM_SMEM>>>(nullptr, nullptr, bo, bo, bo, out, 0);
}

// round 8
// speedup vs baseline: 2.5567x; 1.0871x over previous
#include <cuda_runtime.h>
#include <cuda_bf16.h>
#include <math.h>
#include <stdint.h>

// Problem constants
#define BB   4
#define HH   16
#define LL   2048
#define DD   1024
#define HD   64
#define CH   128
#define NC   16

// ---------------- scratch (device globals) ----------------
__device__ float g_q[BB*HH*LL*HD];
__device__ float g_k[BB*HH*LL*HD];
__device__ float g_v[BB*HH*LL*HD];
__device__ float g_S[BB*HH*NC*HD*HD];
__device__ float g_z[BB*HH*NC*HD];
__device__ __nv_bfloat16 g_xh[BB*LL*DD];   // x split hi/lo
__device__ __nv_bfloat16 g_xl[BB*LL*DD];
__device__ __nv_bfloat16 g_wh[4*DD*DD];    // Wq,Wk,Wv,Wo split hi
__device__ __nv_bfloat16 g_wl[4*DD*DD];    // ... lo
__device__ __nv_bfloat16 g_oh[BB*LL*DD];   // attention out split hi/lo
__device__ __nv_bfloat16 g_ol[BB*LL*DD];

// ---------------- PTX helpers ----------------
__device__ __forceinline__ uint32_t s2u(const void* p) {
    uint32_t a;
    asm("{ .reg .u64 t; cvta.to.shared.u64 t, %1; cvt.u32.u64 %0, t; }" : "=r"(a) : "l"(p));
    return a;
}
__device__ __forceinline__ void cp16(uint32_t s, const void* g) {
    asm volatile("cp.async.cg.shared.global [%0], [%1], 16;" :: "r"(s), "l"(g) : "memory");
}
__device__ __forceinline__ void ldm_x4(uint32_t* r, uint32_t addr) {
    asm volatile("ldmatrix.sync.aligned.m8n8.x4.shared.b16 {%0,%1,%2,%3}, [%4];"
        : "=r"(r[0]), "=r"(r[1]), "=r"(r[2]), "=r"(r[3]) : "r"(addr));
}
__device__ __forceinline__ void mma16816(float* d, const uint32_t* a, const uint32_t* b) {
    asm volatile("mma.sync.aligned.m16n8k16.row.col.f32.bf16.bf16.f32 "
        "{%0,%1,%2,%3}, {%4,%5,%6,%7}, {%8,%9}, {%0,%1,%2,%3};"
        : "+f"(d[0]), "+f"(d[1]), "+f"(d[2]), "+f"(d[3])
        : "r"(a[0]), "r"(a[1]), "r"(a[2]), "r"(a[3]), "r"(b[0]), "r"(b[1]));
}

// ---------------- split fp32 -> bf16 hi + bf16 lo (x + all 4 weights) ----
__global__ __launch_bounds__(256) void split_all_kernel(
    const float* __restrict__ x,
    const float* __restrict__ Wq, const float* __restrict__ Wk,
    const float* __restrict__ Wv, const float* __restrict__ Wo)
{
    const int XN = BB * LL * DD;          // 8M
    long long i = ((long long)blockIdx.x * 256 + threadIdx.x) * 4;
    const float* src;
    __nv_bfloat16 *dh, *dl;
    long long off;
    if (i < XN) {
        src = x; dh = g_xh; dl = g_xl; off = i;
    } else {
        long long j = i - XN;
        int w = (int)(j >> 20);           // DD*DD = 1M
        off = j & ((1 << 20) - 1);
        src = (w == 0) ? Wq : (w == 1) ? Wk : (w == 2) ? Wv : Wo;
        dh = g_wh + ((long long)w << 20);
        dl = g_wl + ((long long)w << 20);
    }
    float4 v = *reinterpret_cast<const float4*>(src + off);
    __nv_bfloat16 h0 = __float2bfloat16(v.x), h1 = __float2bfloat16(v.y);
    __nv_bfloat16 h2 = __float2bfloat16(v.z), h3 = __float2bfloat16(v.w);
    __nv_bfloat16 l0 = __float2bfloat16(v.x - __bfloat162float(h0));
    __nv_bfloat16 l1 = __float2bfloat16(v.y - __bfloat162float(h1));
    __nv_bfloat16 l2 = __float2bfloat16(v.z - __bfloat162float(h2));
    __nv_bfloat16 l3 = __float2bfloat16(v.w - __bfloat162float(h3));
    __nv_bfloat162 ph0; ph0.x = h0; ph0.y = h1;
    __nv_bfloat162 ph1; ph1.x = h2; ph1.y = h3;
    __nv_bfloat162 pl0; pl0.x = l0; pl0.y = l1;
    __nv_bfloat162 pl1; pl1.x = l2; pl1.y = l3;
    *reinterpret_cast<__nv_bfloat162*>(dh + off)     = ph0;
    *reinterpret_cast<__nv_bfloat162*>(dh + off + 2) = ph1;
    *reinterpret_cast<__nv_bfloat162*>(dl + off)     = pl0;
    *reinterpret_cast<__nv_bfloat162*>(dl + off + 2) = pl1;
}

// =======================================================================
// HMMA split-bf16 GEMM: D = A @ W^T (+bias, opt silu, opt scatter)
// CTA 128x128, 512 threads (16 warps, 4x4), warp tile 32x32.
// K chunks of 32; per k16: A 4 ldm_x4, B 4 ldm_x4, 24 MMAs per warp.
// 4-stage cp.async pipeline. Row stride 80B: 16B-aligned for cp.async
// and conflict-free for ldmatrix (r*80 mod 128 -> 8 distinct 16B slots).
// =======================================================================
#define LDS_B   80
#define MAT_B   (128 * LDS_B)         // 10240
#define STAGE_B (4 * MAT_B)           // 40960
#define STAGES  4
#define GEMM_SMEM (STAGES * STAGE_B)  // 163840

__global__ __launch_bounds__(512, 1) void gemm_tc(
    const __nv_bfloat16* __restrict__ Ah0, const __nv_bfloat16* __restrict__ Al0,
    const float* __restrict__ bq, const float* __restrict__ bk, const float* __restrict__ bv,
    float* __restrict__ outp, int qkv_mode)
{
    extern __shared__ char smem[];
    const uint32_t sb = s2u(smem);
    const int tid = threadIdx.x;
    const int wid = tid >> 5, lane = tid & 31;
    const int wm = wid & 3, wn = wid >> 2;

    const __nv_bfloat16 *Ah, *Al, *Bh, *Bl;
    const float* bias;
    float* qkv_out = nullptr;
    int n0, do_silu;
    if (qkv_mode) {
        int w = blockIdx.x >> 3;
        Bh = g_wh + (size_t)w * (DD * DD);
        Bl = g_wl + (size_t)w * (DD * DD);
        bias = (w == 0) ? bq : (w == 1) ? bk : bv;
        qkv_out = (w == 0) ? g_q : (w == 1) ? g_k : g_v;
        do_silu = (w < 2);
        n0 = (blockIdx.x & 7) * 128;
        Ah = Ah0; Al = Al0;
    } else {
        Bh = g_wh + 3 * (size_t)(DD * DD);
        Bl = g_wl + 3 * (size_t)(DD * DD);
        bias = bq; do_silu = 0;
        n0 = blockIdx.x * 128;
        Ah = g_oh; Al = g_ol;
    }
    const int m0 = blockIdx.y * 128;

    float acc[2][4][4];
#pragma unroll
    for (int a = 0; a < 2; a++)
#pragma unroll
        for (int b = 0; b < 4; b++)
#pragma unroll
            for (int c = 0; c < 4; c++) acc[a][b][c] = 0.f;

    const int lr = tid >> 2, lg = tid & 3;           // load row / 16B group
    const uint32_t lso = (uint32_t)(lr * LDS_B + lg * 16);
    const size_t goffA = (size_t)(m0 + lr) * DD + lg * 8;
    const size_t goffB = (size_t)(n0 + lr) * DD + lg * 8;

    auto load_chunk = [&](int cc) {
        const int kc = cc * 32;
        const uint32_t st = sb + (uint32_t)(cc & (STAGES - 1)) * STAGE_B;
        cp16(st + 0 * MAT_B + lso, Ah + goffA + kc);
        cp16(st + 1 * MAT_B + lso, Al + goffA + kc);
        cp16(st + 2 * MAT_B + lso, Bh + goffB + kc);
        cp16(st + 3 * MAT_B + lso, Bl + goffB + kc);
        asm volatile("cp.async.commit_group;" ::: "memory");
    };

    load_chunk(0);
    load_chunk(1);

    // per-lane static smem offsets
    const int arow = wm * 32 + (lane & 15);
    const int acol = (lane >> 4) * 8;
    const int brow = wn * 32 + ((lane >> 4) << 3) + (lane & 7);
    const int bcol = ((lane >> 3) & 1) * 8;

    const int NK = 1024 / 32;   // 32 chunks
    for (int c = 0; c < NK; c++) {
        if (c + 2 < NK) load_chunk(c + 2);
        if (c < NK - 2)       asm volatile("cp.async.wait_group 2;" ::: "memory");
        else if (c == NK - 2) asm volatile("cp.async.wait_group 1;" ::: "memory");
        else                  asm volatile("cp.async.wait_group 0;" ::: "memory");
        __syncthreads();

        const uint32_t st  = sb + (uint32_t)(c & (STAGES - 1)) * STAGE_B;
        const uint32_t aAh = st, aAl = st + MAT_B, aBh = st + 2 * MAT_B, aBl = st + 3 * MAT_B;

#pragma unroll
        for (int h = 0; h < 2; h++) {
            uint32_t ah[2][4], al[2][4];
#pragma unroll
            for (int mt = 0; mt < 2; mt++) {
                uint32_t off = (uint32_t)((arow + mt * 16) * LDS_B + (acol + h * 16) * 2);
                ldm_x4(ah[mt], aAh + off);
                ldm_x4(al[mt], aAl + off);
            }
            uint32_t bhf[2][4], blf[2][4];   // [p][4]: p covers n-tiles 2p,2p+1
#pragma unroll
            for (int p = 0; p < 2; p++) {
                uint32_t off = (uint32_t)((brow + p * 16) * LDS_B + (bcol + h * 16) * 2);
                ldm_x4(bhf[p], aBh + off);
                ldm_x4(blf[p], aBl + off);
            }
#pragma unroll
            for (int mt = 0; mt < 2; mt++)
#pragma unroll
                for (int nt = 0; nt < 4; nt++) {
                    const uint32_t* bh2 = &bhf[nt >> 1][(nt & 1) * 2];
                    const uint32_t* bl2 = &blf[nt >> 1][(nt & 1) * 2];
                    mma16816(acc[mt][nt], ah[mt], bh2);
                    mma16816(acc[mt][nt], ah[mt], bl2);
                    mma16816(acc[mt][nt], al[mt], bh2);
                }
        }
    }

    // ---- epilogue: bias + opt silu + scatter ----
    float bv2[4][2];
#pragma unroll
    for (int nt = 0; nt < 4; nt++) {
        int col = n0 + wn * 32 + nt * 8 + 2 * (lane & 3);
        bv2[nt][0] = bias[col];
        bv2[nt][1] = bias[col + 1];
    }
#pragma unroll
    for (int mt = 0; mt < 2; mt++) {
#pragma unroll
        for (int half = 0; half < 2; half++) {
            int m = m0 + wm * 32 + mt * 16 + (lane >> 2) + half * 8;
            int b = m >> 11, lpos = m & 2047;
#pragma unroll
            for (int nt = 0; nt < 4; nt++) {
                int col = n0 + wn * 32 + nt * 8 + 2 * (lane & 3);
                float v0 = acc[mt][nt][half * 2 + 0] + bv2[nt][0];
                float v1 = acc[mt][nt][half * 2 + 1] + bv2[nt][1];
                if (do_silu) {
                    v0 = v0 / (1.f + expf(-v0));
                    v1 = v1 / (1.f + expf(-v1));
                }
                if (qkv_mode) {
                    int hidx = col >> 6, i2 = col & 63;
                    float* p = qkv_out + ((size_t)((b << 4) | hidx) * LL + lpos) * HD + i2;
                    *reinterpret_cast<float2*>(p) = make_float2(v0, v1);
                } else {
                    *reinterpret_cast<float2*>(outp + (size_t)m * DD + col) =
                        make_float2(v0, v1);
                }
            }
        }
    }
}

// =======================================================================
// Per-chunk state: kv[d][e] = sum_t k[t][d]*v[t][e], ksum[d] = sum_t k[t][d]
// =======================================================================
__global__ __launch_bounds__(256) void chunk_state_kernel()
{
    extern __shared__ float sm[];
    float* ks  = sm;
    float* vsm = sm + 8192;

    int cid = blockIdx.x;
    int bh = cid >> 4, nch = cid & 15;
    size_t base = ((size_t)bh * LL + (size_t)nch * CH) * HD;
    int tid = threadIdx.x;

    const float4* kg4 = reinterpret_cast<const float4*>(g_k + base);
    const float4* vg4 = reinterpret_cast<const float4*>(g_v + base);
    for (int i4 = tid; i4 < 2048; i4 += 256) {
        reinterpret_cast<float4*>(ks)[i4]  = kg4[i4];
        reinterpret_cast<float4*>(vsm)[i4] = vg4[i4];
    }
    __syncthreads();

    int tx = tid & 15, ty = tid >> 4;
    int i0 = ty * 4, j0 = tx * 4;
    float c[4][4] = {};
#pragma unroll 4
    for (int t = 0; t < 128; t++) {
        float4 a = *reinterpret_cast<const float4*>(&ks[t * 64 + i0]);
        float4 bvv = *reinterpret_cast<const float4*>(&vsm[t * 64 + j0]);
        float av[4] = {a.x, a.y, a.z, a.w};
        float bw[4] = {bvv.x, bvv.y, bvv.z, bvv.w};
#pragma unroll
        for (int ii = 0; ii < 4; ii++)
#pragma unroll
            for (int jj = 0; jj < 4; jj++) c[ii][jj] += av[ii] * bw[jj];
    }
    float* Sp = g_S + (size_t)cid * 4096;
#pragma unroll
    for (int ii = 0; ii < 4; ii++) {
        float4 o4 = make_float4(c[ii][0], c[ii][1], c[ii][2], c[ii][3]);
        *reinterpret_cast<float4*>(&Sp[(i0 + ii) * 64 + j0]) = o4;
    }
    if (tid < 64) {
        float s = 0.f;
#pragma unroll 4
        for (int t = 0; t < 128; t++) s += ks[t * 64 + tid];
        g_z[(size_t)cid * 64 + tid] = s;
    }
}

// =======================================================================
// Exclusive prefix over NC chunks of S and z.
// =======================================================================
__global__ __launch_bounds__(256) void prefix_kernel()
{
    int bh = blockIdx.x;
    int tid = threadIdx.x;
    for (int e = tid; e < 4096; e += 256) {
        float run = 0.f;
#pragma unroll
        for (int n = 0; n < NC; n++) {
            size_t idx = ((size_t)bh * NC + n) * 4096 + e;
            float t = g_S[idx];
            g_S[idx] = run;
            run += t;
        }
    }
    if (tid < 64) {
        float run = 0.f;
#pragma unroll
        for (int n = 0; n < NC; n++) {
            size_t idx = ((size_t)bh * NC + n) * 64 + tid;
            float t = g_z[idx];
            g_z[idx] = run;
            run += t;
        }
    }
}

// =======================================================================
// Intra-chunk attention; writes bf16 hi/lo split output for the O-proj GEMM.
// =======================================================================
__global__ __launch_bounds__(256) void intra_kernel()
{
    extern __shared__ float sm[];
    const int LDT  = 132;
    const int LDS2 = 129;
    float* qT  = sm;
    float* kT  = qT + 64 * LDT;
    float* vs  = kT + 64 * LDT;
    float* scT = vs + 128 * 64;
    float* Ss  = scT + 128 * LDS2;
    float* zs  = Ss + 64 * 64;
    float* den = zs + 64;

    int cid = blockIdx.x;
    int bh = cid >> 4, nch = cid & 15;
    size_t base = ((size_t)bh * LL + (size_t)nch * CH) * HD;
    const float* qg  = g_q + base;
    const float* kgp = g_k + base;
    const float* vgp = g_v + base;
    int tid = threadIdx.x;

    for (int idx = tid; idx < 8192; idx += 256) {
        int t = idx >> 6, i = idx & 63;
        qT[i * LDT + t] = qg[idx];
        kT[i * LDT + t] = kgp[idx];
        vs[idx] = vgp[idx];
    }
    for (int idx = tid; idx < 4096; idx += 256) Ss[idx] = g_S[(size_t)cid * 4096 + idx];
    if (tid < 64) zs[tid] = g_z[(size_t)cid * 64 + tid];
    __syncthreads();

    const int tx = tid & 15, ty = tid >> 4;

    // phase 1: masked scores -> scT[j][i]
    {
        float c[8][8];
#pragma unroll
        for (int ii = 0; ii < 8; ii++)
#pragma unroll
            for (int jj = 0; jj < 8; jj++) c[ii][jj] = 0.f;
        int i0 = ty * 8, j0 = tx * 8;
#pragma unroll 4
        for (int kk = 0; kk < 64; kk++) {
            float4 a0 = *reinterpret_cast<const float4*>(&qT[kk * LDT + i0]);
            float4 a1 = *reinterpret_cast<const float4*>(&qT[kk * LDT + i0 + 4]);
            float4 b0 = *reinterpret_cast<const float4*>(&kT[kk * LDT + j0]);
            float4 b1 = *reinterpret_cast<const float4*>(&kT[kk * LDT + j0 + 4]);
            float a[8] = {a0.x, a0.y, a0.z, a0.w, a1.x, a1.y, a1.z, a1.w};
            float bx[8] = {b0.x, b0.y, b0.z, b0.w, b1.x, b1.y, b1.z, b1.w};
#pragma unroll
            for (int ii = 0; ii < 8; ii++)
#pragma unroll
                for (int jj = 0; jj < 8; jj++) c[ii][jj] += a[ii] * bx[jj];
        }
#pragma unroll
        for (int jj = 0; jj < 8; jj++) {
            int j = j0 + jj;
#pragma unroll
            for (int ii = 0; ii < 8; ii++) {
                int i = i0 + ii;
                scT[j * LDS2 + i] = (j <= i) ? c[ii][jj] : 0.f;
            }
        }
    }
    __syncthreads();

    // phase 1.5: denominators
    if (tid < 128) {
        float s = 0.f;
        for (int j = 0; j < 128; j++) s += scT[j * LDS2 + tid];
        float s2 = 0.f;
        for (int dd = 0; dd < 64; dd++) s2 += qT[dd * LDT + tid] * zs[dd];
        den[tid] = fmaxf(s + s2, 1e-3f);
    }
    __syncthreads();

    // phase 2: num = scores@v + q@S ; out = num/den -> bf16 hi/lo split
    {
        int ex = tid & 15, iy = tid >> 4;
        int i0 = iy * 8, e0 = ex * 4;
        float c[8][4];
#pragma unroll
        for (int ii = 0; ii < 8; ii++)
#pragma unroll
            for (int jj = 0; jj < 4; jj++) c[ii][jj] = 0.f;

#pragma unroll 4
        for (int j = 0; j < 128; j++) {
            float4 bvv = *reinterpret_cast<const float4*>(&vs[j * 64 + e0]);
#pragma unroll
            for (int ii = 0; ii < 8; ii++) {
                float a = scT[j * LDS2 + i0 + ii];
                c[ii][0] += a * bvv.x; c[ii][1] += a * bvv.y;
                c[ii][2] += a * bvv.z; c[ii][3] += a * bvv.w;
            }
        }
#pragma unroll 4
        for (int dd = 0; dd < 64; dd++) {
            float4 bvv = *reinterpret_cast<const float4*>(&Ss[dd * 64 + e0]);
            float4 a0 = *reinterpret_cast<const float4*>(&qT[dd * LDT + i0]);
            float4 a1 = *reinterpret_cast<const float4*>(&qT[dd * LDT + i0 + 4]);
            float a[8] = {a0.x, a0.y, a0.z, a0.w, a1.x, a1.y, a1.z, a1.w};
#pragma unroll
            for (int ii = 0; ii < 8; ii++) {
                c[ii][0] += a[ii] * bvv.x; c[ii][1] += a[ii] * bvv.y;
                c[ii][2] += a[ii] * bvv.z; c[ii][3] += a[ii] * bvv.w;
            }
        }
        int bidx = bh >> 4, hd = bh & 15;
#pragma unroll
        for (int ii = 0; ii < 8; ii++) {
            int i = i0 + ii;
            float r = 1.f / den[i];
            int l = nch * CH + i;
            float o0 = c[ii][0] * r, o1 = c[ii][1] * r, o2 = c[ii][2] * r, o3 = c[ii][3] * r;
            __nv_bfloat16 h0 = __float2bfloat16(o0), h1 = __float2bfloat16(o1);
            __nv_bfloat16 h2 = __float2bfloat16(o2), h3 = __float2bfloat16(o3);
            __nv_bfloat16 l0 = __float2bfloat16(o0 - __bfloat162float(h0));
            __nv_bfloat16 l1 = __float2bfloat16(o1 - __bfloat162float(h1));
            __nv_bfloat16 l2 = __float2bfloat16(o2 - __bfloat162float(h2));
            __nv_bfloat16 l3 = __float2bfloat16(o3 - __bfloat162float(h3));
            size_t obase = ((size_t)bidx * LL + l) * DD + hd * 64 + e0;
            __nv_bfloat162 ph0; ph0.x = h0; ph0.y = h1;
            __nv_bfloat162 ph1; ph1.x = h2; ph1.y = h3;
            __nv_bfloat162 pl0; pl0.x = l0; pl0.y = l1;
            __nv_bfloat162 pl1; pl1.x = l2; pl1.y = l3;
            *reinterpret_cast<__nv_bfloat162*>(g_oh + obase)     = ph0;
            *reinterpret_cast<__nv_bfloat162*>(g_oh + obase + 2) = ph1;
            *reinterpret_cast<__nv_bfloat162*>(g_ol + obase)     = pl0;
            *reinterpret_cast<__nv_bfloat162*>(g_ol + obase + 2) = pl1;
        }
    }
}

// =======================================================================
extern "C" void kernel_launch(void* const* d_in, const int* in_sizes, int n_in,
                              void* d_out, int out_size)
{
    const float* x  = (const float*)d_in[0];
    const float* Wq = (const float*)d_in[1];
    const float* bq = (const float*)d_in[2];
    const float* Wk = (const float*)d_in[3];
    const float* bk = (const float*)d_in[4];
    const float* Wv = (const float*)d_in[5];
    const float* bv = (const float*)d_in[6];
    const float* Wo = (const float*)d_in[7];
    const float* bo = (const float*)d_in[8];
    float* out = (float*)d_out;

    static const int INTRA_SMEM = (64 * 132 * 2 + 128 * 64 + 128 * 129 + 64 * 64 + 64 + 128) * 4;
    cudaFuncSetAttribute(chunk_state_kernel, cudaFuncAttributeMaxDynamicSharedMemorySize, 65536);
    cudaFuncSetAttribute(intra_kernel, cudaFuncAttributeMaxDynamicSharedMemorySize, INTRA_SMEM);
    cudaFuncSetAttribute(gemm_tc, cudaFuncAttributeMaxDynamicSharedMemorySize, GEMM_SMEM);

    __nv_bfloat16 *xh, *xl;
    cudaGetSymbolAddress((void**)&xh, g_xh);
    cudaGetSymbolAddress((void**)&xl, g_xl);

    // 0) split fp32 inputs (x + 4 weights) into bf16 hi/lo pairs, one launch
    split_all_kernel<<<(BB*LL*DD + 4*DD*DD) / 1024, 256>>>(x, Wq, Wk, Wv, Wo);

    // 1) fused QKV projection on tensor cores (3 weights x 8 n-tiles x 64 m-tiles)
    gemm_tc<<<dim3(24, 64), 512, GEMM_SMEM>>>(xh, xl, bq, bk, bv, nullptr, 1);

    // 2) per-chunk kv state + k sums
    chunk_state_kernel<<<BB * HH * NC, 256, 65536>>>();

    // 3) exclusive prefix over chunks
    prefix_kernel<<<BB * HH, 256>>>();

    // 4) intra-chunk attention (emits bf16 hi/lo split)
    intra_kernel<<<BB * HH * NC, 256, INTRA_SMEM>>>();

    // 5) output projection on tensor cores
    gemm_tc<<<dim3(8, 64), 512, GEMM_SMEM>>>(nullptr, nullptr, bo, bo, bo, out, 0);
}

// round 9
// speedup vs baseline: 2.7996x; 1.0950x over previous
#include <cuda_runtime.h>
#include <cuda_bf16.h>
#include <math.h>
#include <stdint.h>

// Problem constants
#define BB   4
#define HH   16
#define LL   2048
#define DD   1024
#define HD   64
#define CH   128
#define NC   16

// ---------------- scratch (device globals) ----------------
__device__ float g_q[BB*HH*LL*HD];
__device__ float g_k[BB*HH*LL*HD];
__device__ float g_v[BB*HH*LL*HD];
__device__ float g_S[BB*HH*NC*HD*HD];
__device__ float g_z[BB*HH*NC*HD];
__device__ __nv_bfloat16 g_xh[BB*LL*DD];   // x split hi/lo
__device__ __nv_bfloat16 g_xl[BB*LL*DD];
__device__ __nv_bfloat16 g_wh[4*DD*DD];    // Wq,Wk,Wv,Wo split hi
__device__ __nv_bfloat16 g_wl[4*DD*DD];    // ... lo
__device__ __nv_bfloat16 g_oh[BB*LL*DD];   // attention out split hi/lo
__device__ __nv_bfloat16 g_ol[BB*LL*DD];

// ---------------- PTX helpers ----------------
__device__ __forceinline__ uint32_t s2u(const void* p) {
    uint32_t a;
    asm("{ .reg .u64 t; cvta.to.shared.u64 t, %1; cvt.u32.u64 %0, t; }" : "=r"(a) : "l"(p));
    return a;
}
__device__ __forceinline__ void cp16(uint32_t s, const void* g) {
    asm volatile("cp.async.cg.shared.global [%0], [%1], 16;" :: "r"(s), "l"(g) : "memory");
}
__device__ __forceinline__ void ldm_x4(uint32_t* r, uint32_t addr) {
    asm volatile("ldmatrix.sync.aligned.m8n8.x4.shared.b16 {%0,%1,%2,%3}, [%4];"
        : "=r"(r[0]), "=r"(r[1]), "=r"(r[2]), "=r"(r[3]) : "r"(addr));
}
__device__ __forceinline__ void mma16816(float* d, const uint32_t* a, const uint32_t* b) {
    asm volatile("mma.sync.aligned.m16n8k16.row.col.f32.bf16.bf16.f32 "
        "{%0,%1,%2,%3}, {%4,%5,%6,%7}, {%8,%9}, {%0,%1,%2,%3};"
        : "+f"(d[0]), "+f"(d[1]), "+f"(d[2]), "+f"(d[3])
        : "r"(a[0]), "r"(a[1]), "r"(a[2]), "r"(a[3]), "r"(b[0]), "r"(b[1]));
}
// pack two fp32 into bf16x2 (lo -> lower 16 bits)
__device__ __forceinline__ uint32_t pk2(float lo, float hi) {
    uint32_t r;
    asm("cvt.rn.bf16x2.f32 %0, %1, %2;" : "=r"(r) : "f"(hi), "f"(lo));
    return r;
}
__device__ __forceinline__ float bfh(float x) {
    return __bfloat162float(__float2bfloat16(x));
}

// ---------------- split fp32 -> bf16 hi + bf16 lo (x + all 4 weights) ----
__global__ __launch_bounds__(256) void split_all_kernel(
    const float* __restrict__ x,
    const float* __restrict__ Wq, const float* __restrict__ Wk,
    const float* __restrict__ Wv, const float* __restrict__ Wo)
{
    const int XN = BB * LL * DD;          // 8M
    long long i = ((long long)blockIdx.x * 256 + threadIdx.x) * 4;
    const float* src;
    __nv_bfloat16 *dh, *dl;
    long long off;
    if (i < XN) {
        src = x; dh = g_xh; dl = g_xl; off = i;
    } else {
        long long j = i - XN;
        int w = (int)(j >> 20);           // DD*DD = 1M
        off = j & ((1 << 20) - 1);
        src = (w == 0) ? Wq : (w == 1) ? Wk : (w == 2) ? Wv : Wo;
        dh = g_wh + ((long long)w << 20);
        dl = g_wl + ((long long)w << 20);
    }
    float4 v = *reinterpret_cast<const float4*>(src + off);
    __nv_bfloat16 h0 = __float2bfloat16(v.x), h1 = __float2bfloat16(v.y);
    __nv_bfloat16 h2 = __float2bfloat16(v.z), h3 = __float2bfloat16(v.w);
    __nv_bfloat16 l0 = __float2bfloat16(v.x - __bfloat162float(h0));
    __nv_bfloat16 l1 = __float2bfloat16(v.y - __bfloat162float(h1));
    __nv_bfloat16 l2 = __float2bfloat16(v.z - __bfloat162float(h2));
    __nv_bfloat16 l3 = __float2bfloat16(v.w - __bfloat162float(h3));
    __nv_bfloat162 ph0; ph0.x = h0; ph0.y = h1;
    __nv_bfloat162 ph1; ph1.x = h2; ph1.y = h3;
    __nv_bfloat162 pl0; pl0.x = l0; pl0.y = l1;
    __nv_bfloat162 pl1; pl1.x = l2; pl1.y = l3;
    *reinterpret_cast<__nv_bfloat162*>(dh + off)     = ph0;
    *reinterpret_cast<__nv_bfloat162*>(dh + off + 2) = ph1;
    *reinterpret_cast<__nv_bfloat162*>(dl + off)     = pl0;
    *reinterpret_cast<__nv_bfloat162*>(dl + off + 2) = pl1;
}

// =======================================================================
// HMMA split-bf16 GEMM (unchanged from passing R8)
// =======================================================================
#define LDS_B   80
#define MAT_B   (128 * LDS_B)
#define STAGE_B (4 * MAT_B)
#define STAGES  4
#define GEMM_SMEM (STAGES * STAGE_B)  // 163840

__global__ __launch_bounds__(512, 1) void gemm_tc(
    const __nv_bfloat16* __restrict__ Ah0, const __nv_bfloat16* __restrict__ Al0,
    const float* __restrict__ bq, const float* __restrict__ bk, const float* __restrict__ bv,
    float* __restrict__ outp, int qkv_mode)
{
    extern __shared__ char smem[];
    const uint32_t sb = s2u(smem);
    const int tid = threadIdx.x;
    const int wid = tid >> 5, lane = tid & 31;
    const int wm = wid & 3, wn = wid >> 2;

    const __nv_bfloat16 *Ah, *Al, *Bh, *Bl;
    const float* bias;
    float* qkv_out = nullptr;
    int n0, do_silu;
    if (qkv_mode) {
        int w = blockIdx.x >> 3;
        Bh = g_wh + (size_t)w * (DD * DD);
        Bl = g_wl + (size_t)w * (DD * DD);
        bias = (w == 0) ? bq : (w == 1) ? bk : bv;
        qkv_out = (w == 0) ? g_q : (w == 1) ? g_k : g_v;
        do_silu = (w < 2);
        n0 = (blockIdx.x & 7) * 128;
        Ah = Ah0; Al = Al0;
    } else {
        Bh = g_wh + 3 * (size_t)(DD * DD);
        Bl = g_wl + 3 * (size_t)(DD * DD);
        bias = bq; do_silu = 0;
        n0 = blockIdx.x * 128;
        Ah = g_oh; Al = g_ol;
    }
    const int m0 = blockIdx.y * 128;

    float acc[2][4][4];
#pragma unroll
    for (int a = 0; a < 2; a++)
#pragma unroll
        for (int b = 0; b < 4; b++)
#pragma unroll
            for (int c = 0; c < 4; c++) acc[a][b][c] = 0.f;

    const int lr = tid >> 2, lg = tid & 3;
    const uint32_t lso = (uint32_t)(lr * LDS_B + lg * 16);
    const size_t goffA = (size_t)(m0 + lr) * DD + lg * 8;
    const size_t goffB = (size_t)(n0 + lr) * DD + lg * 8;

    auto load_chunk = [&](int cc) {
        const int kc = cc * 32;
        const uint32_t st = sb + (uint32_t)(cc & (STAGES - 1)) * STAGE_B;
        cp16(st + 0 * MAT_B + lso, Ah + goffA + kc);
        cp16(st + 1 * MAT_B + lso, Al + goffA + kc);
        cp16(st + 2 * MAT_B + lso, Bh + goffB + kc);
        cp16(st + 3 * MAT_B + lso, Bl + goffB + kc);
        asm volatile("cp.async.commit_group;" ::: "memory");
    };

    load_chunk(0);
    load_chunk(1);

    const int arow = wm * 32 + (lane & 15);
    const int acol = (lane >> 4) * 8;
    const int brow = wn * 32 + ((lane >> 4) << 3) + (lane & 7);
    const int bcol = ((lane >> 3) & 1) * 8;

    const int NK = 1024 / 32;
    for (int c = 0; c < NK; c++) {
        if (c + 2 < NK) load_chunk(c + 2);
        if (c < NK - 2)       asm volatile("cp.async.wait_group 2;" ::: "memory");
        else if (c == NK - 2) asm volatile("cp.async.wait_group 1;" ::: "memory");
        else                  asm volatile("cp.async.wait_group 0;" ::: "memory");
        __syncthreads();

        const uint32_t st  = sb + (uint32_t)(c & (STAGES - 1)) * STAGE_B;
        const uint32_t aAh = st, aAl = st + MAT_B, aBh = st + 2 * MAT_B, aBl = st + 3 * MAT_B;

#pragma unroll
        for (int h = 0; h < 2; h++) {
            uint32_t ah[2][4], al[2][4];
#pragma unroll
            for (int mt = 0; mt < 2; mt++) {
                uint32_t off = (uint32_t)((arow + mt * 16) * LDS_B + (acol + h * 16) * 2);
                ldm_x4(ah[mt], aAh + off);
                ldm_x4(al[mt], aAl + off);
            }
            uint32_t bhf[2][4], blf[2][4];
#pragma unroll
            for (int p = 0; p < 2; p++) {
                uint32_t off = (uint32_t)((brow + p * 16) * LDS_B + (bcol + h * 16) * 2);
                ldm_x4(bhf[p], aBh + off);
                ldm_x4(blf[p], aBl + off);
            }
#pragma unroll
            for (int mt = 0; mt < 2; mt++)
#pragma unroll
                for (int nt = 0; nt < 4; nt++) {
                    const uint32_t* bh2 = &bhf[nt >> 1][(nt & 1) * 2];
                    const uint32_t* bl2 = &blf[nt >> 1][(nt & 1) * 2];
                    mma16816(acc[mt][nt], ah[mt], bh2);
                    mma16816(acc[mt][nt], ah[mt], bl2);
                    mma16816(acc[mt][nt], al[mt], bh2);
                }
        }
    }

    float bv2[4][2];
#pragma unroll
    for (int nt = 0; nt < 4; nt++) {
        int col = n0 + wn * 32 + nt * 8 + 2 * (lane & 3);
        bv2[nt][0] = bias[col];
        bv2[nt][1] = bias[col + 1];
    }
#pragma unroll
    for (int mt = 0; mt < 2; mt++) {
#pragma unroll
        for (int half = 0; half < 2; half++) {
            int m = m0 + wm * 32 + mt * 16 + (lane >> 2) + half * 8;
            int b = m >> 11, lpos = m & 2047;
#pragma unroll
            for (int nt = 0; nt < 4; nt++) {
                int col = n0 + wn * 32 + nt * 8 + 2 * (lane & 3);
                float v0 = acc[mt][nt][half * 2 + 0] + bv2[nt][0];
                float v1 = acc[mt][nt][half * 2 + 1] + bv2[nt][1];
                if (do_silu) {
                    v0 = v0 / (1.f + expf(-v0));
                    v1 = v1 / (1.f + expf(-v1));
                }
                if (qkv_mode) {
                    int hidx = col >> 6, i2 = col & 63;
                    float* p = qkv_out + ((size_t)((b << 4) | hidx) * LL + lpos) * HD + i2;
                    *reinterpret_cast<float2*>(p) = make_float2(v0, v1);
                } else {
                    *reinterpret_cast<float2*>(outp + (size_t)m * DD + col) =
                        make_float2(v0, v1);
                }
            }
        }
    }
}

// =======================================================================
// Per-chunk state (unchanged)
// =======================================================================
__global__ __launch_bounds__(256) void chunk_state_kernel()
{
    extern __shared__ float sm[];
    float* ks  = sm;
    float* vsm = sm + 8192;

    int cid = blockIdx.x;
    int bh = cid >> 4, nch = cid & 15;
    size_t base = ((size_t)bh * LL + (size_t)nch * CH) * HD;
    int tid = threadIdx.x;

    const float4* kg4 = reinterpret_cast<const float4*>(g_k + base);
    const float4* vg4 = reinterpret_cast<const float4*>(g_v + base);
    for (int i4 = tid; i4 < 2048; i4 += 256) {
        reinterpret_cast<float4*>(ks)[i4]  = kg4[i4];
        reinterpret_cast<float4*>(vsm)[i4] = vg4[i4];
    }
    __syncthreads();

    int tx = tid & 15, ty = tid >> 4;
    int i0 = ty * 4, j0 = tx * 4;
    float c[4][4] = {};
#pragma unroll 4
    for (int t = 0; t < 128; t++) {
        float4 a = *reinterpret_cast<const float4*>(&ks[t * 64 + i0]);
        float4 bvv = *reinterpret_cast<const float4*>(&vsm[t * 64 + j0]);
        float av[4] = {a.x, a.y, a.z, a.w};
        float bw[4] = {bvv.x, bvv.y, bvv.z, bvv.w};
#pragma unroll
        for (int ii = 0; ii < 4; ii++)
#pragma unroll
            for (int jj = 0; jj < 4; jj++) c[ii][jj] += av[ii] * bw[jj];
    }
    float* Sp = g_S + (size_t)cid * 4096;
#pragma unroll
    for (int ii = 0; ii < 4; ii++) {
        float4 o4 = make_float4(c[ii][0], c[ii][1], c[ii][2], c[ii][3]);
        *reinterpret_cast<float4*>(&Sp[(i0 + ii) * 64 + j0]) = o4;
    }
    if (tid < 64) {
        float s = 0.f;
#pragma unroll 4
        for (int t = 0; t < 128; t++) s += ks[t * 64 + tid];
        g_z[(size_t)cid * 64 + tid] = s;
    }
}

// =======================================================================
// Parallel exclusive prefix over NC chunks: one thread per element.
// =======================================================================
__global__ __launch_bounds__(256) void prefix2_kernel()
{
    const int PER = 4096 + 64;
    int idx = blockIdx.x * 256 + threadIdx.x;
    if (idx >= 64 * PER) return;
    int bh = idx / PER, rme = idx - bh * PER;
    if (rme < 4096) {
        float run = 0.f;
        size_t p = (size_t)bh * NC * 4096 + rme;
#pragma unroll
        for (int n = 0; n < NC; n++) {
            float t = g_S[p]; g_S[p] = run; run += t; p += 4096;
        }
    } else {
        int e = rme - 4096;
        float run = 0.f;
        size_t p = (size_t)bh * NC * 64 + e;
#pragma unroll
        for (int n = 0; n < NC; n++) {
            float t = g_z[p]; g_z[p] = run; run += t; p += 64;
        }
    }
}

// =======================================================================
// Intra-chunk attention on tensor cores (split-bf16, flash P-reuse).
// 256 threads = 8 warps: wm 0..3 (rows of 32), wn 0..1 (K split).
// phase1: scores = q k^T (M128 N128 K64, 3-term split), mask, rowsum->den,
//         split scores to bf16 A-fragments in registers.
// phase2: num = scores@v (K split by wn) + q@S (d split by wn);
//         wn partials combined via smem; out = num/max(den+q.z, eps)
//         written as bf16 hi/lo for the O projection.
// =======================================================================
#define LQE 72      // elts per row for q/k/S^T (64 data + 8 pad -> 144B)
#define LQB 144
#define LVE 136     // elts per row for v^T (128 data + 8 pad -> 272B)
#define LVB 272

#define OFF_QH 0
#define OFF_QL 18432
#define OFF_KH 36864
#define OFF_KL 55296
#define OFF_VH 73728
#define OFF_VL 91136
#define OFF_SH 108544
#define OFF_SL 117760
#define OFF_NUM 126976
#define OFF_Z 159744
#define OFF_DEN 160000
#define INTRA2_SMEM 160512

__global__ __launch_bounds__(256, 1) void intra2_kernel()
{
    extern __shared__ char smc[];
    __nv_bfloat16* qhp = (__nv_bfloat16*)(smc + OFF_QH);
    __nv_bfloat16* qlp = (__nv_bfloat16*)(smc + OFF_QL);
    __nv_bfloat16* khp = (__nv_bfloat16*)(smc + OFF_KH);
    __nv_bfloat16* klp = (__nv_bfloat16*)(smc + OFF_KL);
    __nv_bfloat16* vhp = (__nv_bfloat16*)(smc + OFF_VH);
    __nv_bfloat16* vlp = (__nv_bfloat16*)(smc + OFF_VL);
    __nv_bfloat16* Shp = (__nv_bfloat16*)(smc + OFF_SH);
    __nv_bfloat16* Slp = (__nv_bfloat16*)(smc + OFF_SL);
    float* numb = (float*)(smc + OFF_NUM);
    float* zs   = (float*)(smc + OFF_Z);
    float* den  = (float*)(smc + OFF_DEN);
    const uint32_t sb = s2u(smc);

    const int cid = blockIdx.x;
    const int bh = cid >> 4, nch = cid & 15;
    const size_t base = ((size_t)bh * LL + (size_t)nch * CH) * HD;
    const int tid = threadIdx.x, wid = tid >> 5, lane = tid & 31;
    const int wm = wid & 3, wn = wid >> 2;

    // ---- load & convert to split-bf16 smem ----
    for (int idx = tid; idx < 8192; idx += 256) {
        int t = idx >> 6, d = idx & 63;
        float qv = g_q[base + idx];
        float kv = g_k[base + idx];
        float vv = g_v[base + idx];
        float qhh = bfh(qv), khh = bfh(kv), vhh = bfh(vv);
        qhp[t * LQE + d] = __float2bfloat16(qv);
        qlp[t * LQE + d] = __float2bfloat16(qv - qhh);
        khp[t * LQE + d] = __float2bfloat16(kv);
        klp[t * LQE + d] = __float2bfloat16(kv - khh);
        vhp[d * LVE + t] = __float2bfloat16(vv);
        vlp[d * LVE + t] = __float2bfloat16(vv - vhh);
    }
    for (int idx = tid; idx < 4096; idx += 256) {
        int d = idx >> 6, e = idx & 63;
        float sv = g_S[(size_t)cid * 4096 + idx];
        float shh = bfh(sv);
        Shp[e * LQE + d] = __float2bfloat16(sv);
        Slp[e * LQE + d] = __float2bfloat16(sv - shh);
    }
    if (tid < 64) zs[tid] = g_z[(size_t)cid * 64 + tid];
    if (tid < 128) den[tid] = 0.f;
    __syncthreads();

    const int r = lane >> 2, c2 = 2 * (lane & 3);
    const int arow = wm * 32 + (lane & 15);
    const int acol = (lane >> 4) * 8;
    const int brow = ((lane >> 4) << 3) + (lane & 7);
    const int bcol = ((lane >> 3) & 1) * 8;
    const uint32_t sQH = sb + OFF_QH, sQL = sb + OFF_QL;
    const uint32_t sKH = sb + OFF_KH, sKL = sb + OFF_KL;
    const uint32_t sVH = sb + OFF_VH, sVL = sb + OFF_VL;
    const uint32_t sSH = sb + OFF_SH, sSL = sb + OFF_SL;

    // ---- phase 1: scores = q k^T (warp covers rows wm*32, cols wn*64) ----
    float acc[2][8][4];
#pragma unroll
    for (int a = 0; a < 2; a++)
#pragma unroll
        for (int b = 0; b < 8; b++)
#pragma unroll
            for (int c = 0; c < 4; c++) acc[a][b][c] = 0.f;

#pragma unroll
    for (int g = 0; g < 4; g++) {
        uint32_t qaf[2][4], qbf[2][4];
#pragma unroll
        for (int mt = 0; mt < 2; mt++) {
            uint32_t off = (uint32_t)((arow + mt * 16) * LQB + (acol + g * 16) * 2);
            ldm_x4(qaf[mt], sQH + off);
            ldm_x4(qbf[mt], sQL + off);
        }
        uint32_t kaf[4][4], kbf2[4][4];
#pragma unroll
        for (int p = 0; p < 4; p++) {
            uint32_t off = (uint32_t)((wn * 64 + brow + p * 16) * LQB + (bcol + g * 16) * 2);
            ldm_x4(kaf[p], sKH + off);
            ldm_x4(kbf2[p], sKL + off);
        }
#pragma unroll
        for (int mt = 0; mt < 2; mt++)
#pragma unroll
            for (int nt = 0; nt < 8; nt++) {
                const uint32_t* b1 = &kaf[nt >> 1][(nt & 1) * 2];
                const uint32_t* b2 = &kbf2[nt >> 1][(nt & 1) * 2];
                mma16816(acc[mt][nt], qaf[mt], b1);
                mma16816(acc[mt][nt], qaf[mt], b2);
                mma16816(acc[mt][nt], qbf[mt], b1);
            }
    }

    // ---- mask + rowsum (den) + split scores to A-fragments ----
    uint32_t shf[2][4][4], slf[2][4][4];
#pragma unroll
    for (int mt = 0; mt < 2; mt++) {
        float rs0 = 0.f, rs1 = 0.f;
        int i0 = wm * 32 + mt * 16 + r, i1 = i0 + 8;
#pragma unroll
        for (int nt = 0; nt < 8; nt++) {
            int j0 = wn * 64 + nt * 8 + c2;
            float s00 = (j0     <= i0) ? acc[mt][nt][0] : 0.f;
            float s01 = (j0 + 1 <= i0) ? acc[mt][nt][1] : 0.f;
            float s10 = (j0     <= i1) ? acc[mt][nt][2] : 0.f;
            float s11 = (j0 + 1 <= i1) ? acc[mt][nt][3] : 0.f;
            rs0 += s00 + s01;
            rs1 += s10 + s11;
            int g = nt >> 1, hh = (nt & 1) * 2;
            shf[mt][g][hh]     = pk2(s00, s01);
            shf[mt][g][hh + 1] = pk2(s10, s11);
            slf[mt][g][hh]     = pk2(s00 - bfh(s00), s01 - bfh(s01));
            slf[mt][g][hh + 1] = pk2(s10 - bfh(s10), s11 - bfh(s11));
        }
        rs0 += __shfl_xor_sync(0xffffffffu, rs0, 1);
        rs0 += __shfl_xor_sync(0xffffffffu, rs0, 2);
        rs1 += __shfl_xor_sync(0xffffffffu, rs1, 1);
        rs1 += __shfl_xor_sync(0xffffffffu, rs1, 2);
        if ((lane & 3) == 0) {
            atomicAdd(&den[i0], rs0);
            atomicAdd(&den[i1], rs1);
        }
    }

    // ---- den += q . z ----
    if (tid < 128) {
        float s = 0.f;
#pragma unroll 8
        for (int d = 0; d < 64; d++) {
            float qv = __bfloat162float(qhp[tid * LQE + d]) +
                       __bfloat162float(qlp[tid * LQE + d]);
            s += qv * zs[d];
        }
        atomicAdd(&den[tid], s);
    }

    // ---- phase 2: num = scores @ v  +  q @ S ----
    float acc2[2][8][4];
#pragma unroll
    for (int a = 0; a < 2; a++)
#pragma unroll
        for (int b = 0; b < 8; b++)
#pragma unroll
            for (int c = 0; c < 4; c++) acc2[a][b][c] = 0.f;

#pragma unroll
    for (int g = 0; g < 4; g++) {
        uint32_t vaf[4][4], vbf2[4][4];
#pragma unroll
        for (int p = 0; p < 4; p++) {
            uint32_t off = (uint32_t)((brow + p * 16) * LVB + (bcol + wn * 64 + g * 16) * 2);
            ldm_x4(vaf[p], sVH + off);
            ldm_x4(vbf2[p], sVL + off);
        }
#pragma unroll
        for (int mt = 0; mt < 2; mt++)
#pragma unroll
            for (int nt = 0; nt < 8; nt++) {
                const uint32_t* b1 = &vaf[nt >> 1][(nt & 1) * 2];
                const uint32_t* b2 = &vbf2[nt >> 1][(nt & 1) * 2];
                mma16816(acc2[mt][nt], shf[mt][g], b1);
                mma16816(acc2[mt][nt], shf[mt][g], b2);
                mma16816(acc2[mt][nt], slf[mt][g], b1);
            }
    }
#pragma unroll
    for (int g2 = 0; g2 < 2; g2++) {
        int gd = wn * 2 + g2;
        uint32_t qaf[2][4], qbf[2][4];
#pragma unroll
        for (int mt = 0; mt < 2; mt++) {
            uint32_t off = (uint32_t)((arow + mt * 16) * LQB + (acol + gd * 16) * 2);
            ldm_x4(qaf[mt], sQH + off);
            ldm_x4(qbf[mt], sQL + off);
        }
        uint32_t Saf[4][4], Sbf2[4][4];
#pragma unroll
        for (int p = 0; p < 4; p++) {
            uint32_t off = (uint32_t)((brow + p * 16) * LQB + (bcol + gd * 16) * 2);
            ldm_x4(Saf[p], sSH + off);
            ldm_x4(Sbf2[p], sSL + off);
        }
#pragma unroll
        for (int mt = 0; mt < 2; mt++)
#pragma unroll
            for (int nt = 0; nt < 8; nt++) {
                const uint32_t* b1 = &Saf[nt >> 1][(nt & 1) * 2];
                const uint32_t* b2 = &Sbf2[nt >> 1][(nt & 1) * 2];
                mma16816(acc2[mt][nt], qaf[mt], b1);
                mma16816(acc2[mt][nt], qaf[mt], b2);
                mma16816(acc2[mt][nt], qbf[mt], b1);
            }
    }

    // ---- combine K-split partials, divide by den, store bf16 hi/lo ----
    __syncthreads();   // den atomics complete; numbuf region free
    if (wn == 0) {
#pragma unroll
        for (int mt = 0; mt < 2; mt++) {
            int i0 = wm * 32 + mt * 16 + r;
#pragma unroll
            for (int nt = 0; nt < 8; nt++) {
                int col = nt * 8 + c2;
                numb[i0 * 64 + col]           = acc2[mt][nt][0];
                numb[i0 * 64 + col + 1]       = acc2[mt][nt][1];
                numb[(i0 + 8) * 64 + col]     = acc2[mt][nt][2];
                numb[(i0 + 8) * 64 + col + 1] = acc2[mt][nt][3];
            }
        }
    }
    __syncthreads();
    if (wn == 1) {
        const int bidx = bh >> 4, hd = bh & 15;
#pragma unroll
        for (int mt = 0; mt < 2; mt++) {
            int i0 = wm * 32 + mt * 16 + r;
            float dr0 = 1.f / fmaxf(den[i0], 1e-3f);
            float dr1 = 1.f / fmaxf(den[i0 + 8], 1e-3f);
            int l0 = nch * CH + i0;
            size_t ob0 = ((size_t)bidx * LL + l0) * DD + hd * 64;
            size_t ob1 = ((size_t)bidx * LL + l0 + 8) * DD + hd * 64;
#pragma unroll
            for (int nt = 0; nt < 8; nt++) {
                int col = nt * 8 + c2;
                float o00 = (acc2[mt][nt][0] + numb[i0 * 64 + col])           * dr0;
                float o01 = (acc2[mt][nt][1] + numb[i0 * 64 + col + 1])       * dr0;
                float o10 = (acc2[mt][nt][2] + numb[(i0 + 8) * 64 + col])     * dr1;
                float o11 = (acc2[mt][nt][3] + numb[(i0 + 8) * 64 + col + 1]) * dr1;
                uint32_t h0 = pk2(o00, o01), h1 = pk2(o10, o11);
                uint32_t z0 = pk2(o00 - bfh(o00), o01 - bfh(o01));
                uint32_t z1 = pk2(o10 - bfh(o10), o11 - bfh(o11));
                *reinterpret_cast<uint32_t*>(g_oh + ob0 + col) = h0;
                *reinterpret_cast<uint32_t*>(g_oh + ob1 + col) = h1;
                *reinterpret_cast<uint32_t*>(g_ol + ob0 + col) = z0;
                *reinterpret_cast<uint32_t*>(g_ol + ob1 + col) = z1;
            }
        }
    }
}

// =======================================================================
extern "C" void kernel_launch(void* const* d_in, const int* in_sizes, int n_in,
                              void* d_out, int out_size)
{
    const float* x  = (const float*)d_in[0];
    const float* Wq = (const float*)d_in[1];
    const float* bq = (const float*)d_in[2];
    const float* Wk = (const float*)d_in[3];
    const float* bk = (const float*)d_in[4];
    const float* Wv = (const float*)d_in[5];
    const float* bv = (const float*)d_in[6];
    const float* Wo = (const float*)d_in[7];
    const float* bo = (const float*)d_in[8];
    float* out = (float*)d_out;

    cudaFuncSetAttribute(chunk_state_kernel, cudaFuncAttributeMaxDynamicSharedMemorySize, 65536);
    cudaFuncSetAttribute(intra2_kernel, cudaFuncAttributeMaxDynamicSharedMemorySize, INTRA2_SMEM);
    cudaFuncSetAttribute(gemm_tc, cudaFuncAttributeMaxDynamicSharedMemorySize, GEMM_SMEM);

    __nv_bfloat16 *xh, *xl;
    cudaGetSymbolAddress((void**)&xh, g_xh);
    cudaGetSymbolAddress((void**)&xl, g_xl);

    // 0) split fp32 inputs (x + 4 weights) into bf16 hi/lo pairs
    split_all_kernel<<<(BB*LL*DD + 4*DD*DD) / 1024, 256>>>(x, Wq, Wk, Wv, Wo);

    // 1) fused QKV projection on tensor cores
    gemm_tc<<<dim3(24, 64), 512, GEMM_SMEM>>>(xh, xl, bq, bk, bv, nullptr, 1);

    // 2) per-chunk kv state + k sums
    chunk_state_kernel<<<BB * HH * NC, 256, 65536>>>();

    // 3) exclusive prefix over chunks (parallel, one thread per element)
    prefix2_kernel<<<(64 * (4096 + 64) + 255) / 256, 256>>>();

    // 4) intra-chunk attention on tensor cores (emits bf16 hi/lo split)
    intra2_kernel<<<BB * HH * NC, 256, INTRA2_SMEM>>>();

    // 5) output projection on tensor cores
    gemm_tc<<<dim3(8, 64), 512, GEMM_SMEM>>>(nullptr, nullptr, bo, bo, bo, out, 0);
}

// round 10
// speedup vs baseline: 2.8145x; 1.0053x over previous
#include <cuda_runtime.h>
#include <cuda_bf16.h>
#include <math.h>
#include <stdint.h>

// Problem constants
#define BB   4
#define HH   16
#define LL   2048
#define DD   1024
#define HD   64
#define CH   128
#define NC   16

// ---------------- scratch (device globals) ----------------
__device__ float g_S[BB*HH*NC*HD*HD];
__device__ float g_z[BB*HH*NC*HD];
__device__ __nv_bfloat16 g_xh[BB*LL*DD];   // x split hi/lo
__device__ __nv_bfloat16 g_xl[BB*LL*DD];
__device__ __nv_bfloat16 g_wh[4*DD*DD];    // Wq,Wk,Wv,Wo split hi
__device__ __nv_bfloat16 g_wl[4*DD*DD];    // ... lo
__device__ __nv_bfloat16 g_qh[BB*HH*LL*HD];  // q/k/v split bf16 (B,H,L,d)
__device__ __nv_bfloat16 g_ql[BB*HH*LL*HD];
__device__ __nv_bfloat16 g_kh[BB*HH*LL*HD];
__device__ __nv_bfloat16 g_kl[BB*HH*LL*HD];
__device__ __nv_bfloat16 g_vh[BB*HH*LL*HD];
__device__ __nv_bfloat16 g_vl[BB*HH*LL*HD];
__device__ __nv_bfloat16 g_oh[BB*LL*DD];   // attention out split hi/lo
__device__ __nv_bfloat16 g_ol[BB*LL*DD];

// ---------------- PTX helpers ----------------
__device__ __forceinline__ uint32_t s2u(const void* p) {
    uint32_t a;
    asm("{ .reg .u64 t; cvta.to.shared.u64 t, %1; cvt.u32.u64 %0, t; }" : "=r"(a) : "l"(p));
    return a;
}
__device__ __forceinline__ void cp16(uint32_t s, const void* g) {
    asm volatile("cp.async.cg.shared.global [%0], [%1], 16;" :: "r"(s), "l"(g) : "memory");
}
__device__ __forceinline__ void ldm_x4(uint32_t* r, uint32_t addr) {
    asm volatile("ldmatrix.sync.aligned.m8n8.x4.shared.b16 {%0,%1,%2,%3}, [%4];"
        : "=r"(r[0]), "=r"(r[1]), "=r"(r[2]), "=r"(r[3]) : "r"(addr));
}
__device__ __forceinline__ void ldm_x4_t(uint32_t* r, uint32_t addr) {
    asm volatile("ldmatrix.sync.aligned.m8n8.x4.trans.shared.b16 {%0,%1,%2,%3}, [%4];"
        : "=r"(r[0]), "=r"(r[1]), "=r"(r[2]), "=r"(r[3]) : "r"(addr));
}
__device__ __forceinline__ void mma16816(float* d, const uint32_t* a, const uint32_t* b) {
    asm volatile("mma.sync.aligned.m16n8k16.row.col.f32.bf16.bf16.f32 "
        "{%0,%1,%2,%3}, {%4,%5,%6,%7}, {%8,%9}, {%0,%1,%2,%3};"
        : "+f"(d[0]), "+f"(d[1]), "+f"(d[2]), "+f"(d[3])
        : "r"(a[0]), "r"(a[1]), "r"(a[2]), "r"(a[3]), "r"(b[0]), "r"(b[1]));
}
__device__ __forceinline__ uint32_t pk2(float lo, float hi) {
    uint32_t r;
    asm("cvt.rn.bf16x2.f32 %0, %1, %2;" : "=r"(r) : "f"(hi), "f"(lo));
    return r;
}
__device__ __forceinline__ float bfh(float x) {
    return __bfloat162float(__float2bfloat16(x));
}

// ---------------- split fp32 -> bf16 hi + bf16 lo (x + all 4 weights) ----
__global__ __launch_bounds__(256) void split_all_kernel(
    const float* __restrict__ x,
    const float* __restrict__ Wq, const float* __restrict__ Wk,
    const float* __restrict__ Wv, const float* __restrict__ Wo)
{
    const int XN = BB * LL * DD;          // 8M
    long long i = ((long long)blockIdx.x * 256 + threadIdx.x) * 4;
    const float* src;
    __nv_bfloat16 *dh, *dl;
    long long off;
    if (i < XN) {
        src = x; dh = g_xh; dl = g_xl; off = i;
    } else {
        long long j = i - XN;
        int w = (int)(j >> 20);           // DD*DD = 1M
        off = j & ((1 << 20) - 1);
        src = (w == 0) ? Wq : (w == 1) ? Wk : (w == 2) ? Wv : Wo;
        dh = g_wh + ((long long)w << 20);
        dl = g_wl + ((long long)w << 20);
    }
    float4 v = *reinterpret_cast<const float4*>(src + off);
    __nv_bfloat16 h0 = __float2bfloat16(v.x), h1 = __float2bfloat16(v.y);
    __nv_bfloat16 h2 = __float2bfloat16(v.z), h3 = __float2bfloat16(v.w);
    __nv_bfloat16 l0 = __float2bfloat16(v.x - __bfloat162float(h0));
    __nv_bfloat16 l1 = __float2bfloat16(v.y - __bfloat162float(h1));
    __nv_bfloat16 l2 = __float2bfloat16(v.z - __bfloat162float(h2));
    __nv_bfloat16 l3 = __float2bfloat16(v.w - __bfloat162float(h3));
    __nv_bfloat162 ph0; ph0.x = h0; ph0.y = h1;
    __nv_bfloat162 ph1; ph1.x = h2; ph1.y = h3;
    __nv_bfloat162 pl0; pl0.x = l0; pl0.y = l1;
    __nv_bfloat162 pl1; pl1.x = l2; pl1.y = l3;
    *reinterpret_cast<__nv_bfloat162*>(dh + off)     = ph0;
    *reinterpret_cast<__nv_bfloat162*>(dh + off + 2) = ph1;
    *reinterpret_cast<__nv_bfloat162*>(dl + off)     = pl0;
    *reinterpret_cast<__nv_bfloat162*>(dl + off + 2) = pl1;
}

// =======================================================================
// HMMA split-bf16 GEMM. CTA 128x128, 512 threads (16 warps 4x4),
// warp tile 32x32. K chunks of 64, 3 stages, distance-1 cp.async prefetch
// (write (c+1)%3 vs laggard read (c-1)%3 -> safe). Rows 144B (128B data
// + 16 pad): 16B-aligned, ldmatrix conflict-free (r*144 mod 128 distinct).
// qkv_mode epilogue writes q/k/v directly as split bf16 hi/lo.
// =======================================================================
#define LDS_B   144
#define MAT_B   (128 * LDS_B)         // 18432
#define STAGE_B (4 * MAT_B)           // 73728
#define STAGES  3
#define GEMM_SMEM (STAGES * STAGE_B)  // 221184

__global__ __launch_bounds__(512, 1) void gemm_tc(
    const __nv_bfloat16* __restrict__ Ah0, const __nv_bfloat16* __restrict__ Al0,
    const float* __restrict__ bq, const float* __restrict__ bk, const float* __restrict__ bv,
    float* __restrict__ outp, int qkv_mode)
{
    extern __shared__ char smem[];
    const uint32_t sb = s2u(smem);
    const int tid = threadIdx.x;
    const int wid = tid >> 5, lane = tid & 31;
    const int wm = wid & 3, wn = wid >> 2;

    const __nv_bfloat16 *Ah, *Al, *Bh, *Bl;
    const float* bias;
    __nv_bfloat16 *ohp = nullptr, *olp = nullptr;
    int n0, do_silu;
    if (qkv_mode) {
        int w = blockIdx.x >> 3;
        Bh = g_wh + (size_t)w * (DD * DD);
        Bl = g_wl + (size_t)w * (DD * DD);
        bias = (w == 0) ? bq : (w == 1) ? bk : bv;
        ohp = (w == 0) ? g_qh : (w == 1) ? g_kh : g_vh;
        olp = (w == 0) ? g_ql : (w == 1) ? g_kl : g_vl;
        do_silu = (w < 2);
        n0 = (blockIdx.x & 7) * 128;
        Ah = Ah0; Al = Al0;
    } else {
        Bh = g_wh + 3 * (size_t)(DD * DD);
        Bl = g_wl + 3 * (size_t)(DD * DD);
        bias = bq; do_silu = 0;
        n0 = blockIdx.x * 128;
        Ah = g_oh; Al = g_ol;
    }
    const int m0 = blockIdx.y * 128;

    float acc[2][4][4];
#pragma unroll
    for (int a = 0; a < 2; a++)
#pragma unroll
        for (int b = 0; b < 4; b++)
#pragma unroll
            for (int c = 0; c < 4; c++) acc[a][b][c] = 0.f;

    auto load_chunk = [&](int cc) {
        const int kc = cc * 64;
        const uint32_t st = sb + (uint32_t)(cc % 3) * STAGE_B;
#pragma unroll
        for (int i = 0; i < 2; i++) {
            int idx = tid + i * 512;
            int r = idx >> 3, g = idx & 7;
            uint32_t so = (uint32_t)(r * LDS_B + g * 16);
            size_t ea = (size_t)(m0 + r) * DD + kc + g * 8;
            size_t eb = (size_t)(n0 + r) * DD + kc + g * 8;
            cp16(st + 0 * MAT_B + so, Ah + ea);
            cp16(st + 1 * MAT_B + so, Al + ea);
            cp16(st + 2 * MAT_B + so, Bh + eb);
            cp16(st + 3 * MAT_B + so, Bl + eb);
        }
        asm volatile("cp.async.commit_group;" ::: "memory");
    };

    load_chunk(0);

    const int arow = wm * 32 + (lane & 15);
    const int acol = (lane >> 4) * 8;
    const int brow = wn * 32 + ((lane >> 4) << 3) + (lane & 7);
    const int bcol = ((lane >> 3) & 1) * 8;

    const int NK = 1024 / 64;   // 16 chunks
    for (int c = 0; c < NK; c++) {
        if (c + 1 < NK) {
            load_chunk(c + 1);
            asm volatile("cp.async.wait_group 1;" ::: "memory");
        } else {
            asm volatile("cp.async.wait_group 0;" ::: "memory");
        }
        __syncthreads();

        const uint32_t st  = sb + (uint32_t)(c % 3) * STAGE_B;
        const uint32_t aAh = st, aAl = st + MAT_B, aBh = st + 2 * MAT_B, aBl = st + 3 * MAT_B;

#pragma unroll
        for (int h = 0; h < 4; h++) {
            uint32_t ah[2][4], al[2][4];
#pragma unroll
            for (int mt = 0; mt < 2; mt++) {
                uint32_t off = (uint32_t)((arow + mt * 16) * LDS_B + (acol + h * 16) * 2);
                ldm_x4(ah[mt], aAh + off);
                ldm_x4(al[mt], aAl + off);
            }
            uint32_t bhf[2][4], blf[2][4];
#pragma unroll
            for (int p = 0; p < 2; p++) {
                uint32_t off = (uint32_t)((brow + p * 16) * LDS_B + (bcol + h * 16) * 2);
                ldm_x4(bhf[p], aBh + off);
                ldm_x4(blf[p], aBl + off);
            }
#pragma unroll
            for (int mt = 0; mt < 2; mt++)
#pragma unroll
                for (int nt = 0; nt < 4; nt++) {
                    const uint32_t* bh2 = &bhf[nt >> 1][(nt & 1) * 2];
                    const uint32_t* bl2 = &blf[nt >> 1][(nt & 1) * 2];
                    mma16816(acc[mt][nt], ah[mt], bh2);
                    mma16816(acc[mt][nt], ah[mt], bl2);
                    mma16816(acc[mt][nt], al[mt], bh2);
                }
        }
    }

    // ---- epilogue ----
    float bv2[4][2];
#pragma unroll
    for (int nt = 0; nt < 4; nt++) {
        int col = n0 + wn * 32 + nt * 8 + 2 * (lane & 3);
        bv2[nt][0] = bias[col];
        bv2[nt][1] = bias[col + 1];
    }
#pragma unroll
    for (int mt = 0; mt < 2; mt++) {
#pragma unroll
        for (int half = 0; half < 2; half++) {
            int m = m0 + wm * 32 + mt * 16 + (lane >> 2) + half * 8;
            int b = m >> 11, lpos = m & 2047;
#pragma unroll
            for (int nt = 0; nt < 4; nt++) {
                int col = n0 + wn * 32 + nt * 8 + 2 * (lane & 3);
                float v0 = acc[mt][nt][half * 2 + 0] + bv2[nt][0];
                float v1 = acc[mt][nt][half * 2 + 1] + bv2[nt][1];
                if (do_silu) {
                    v0 = v0 / (1.f + expf(-v0));
                    v1 = v1 / (1.f + expf(-v1));
                }
                if (qkv_mode) {
                    int hidx = col >> 6, i2 = col & 63;
                    size_t po = ((size_t)((b << 4) | hidx) * LL + lpos) * HD + i2;
                    *reinterpret_cast<uint32_t*>(ohp + po) = pk2(v0, v1);
                    *reinterpret_cast<uint32_t*>(olp + po) =
                        pk2(v0 - bfh(v0), v1 - bfh(v1));
                } else {
                    *reinterpret_cast<float2*>(outp + (size_t)m * DD + col) =
                        make_float2(v0, v1);
                }
            }
        }
    }
}

// =======================================================================
// Per-chunk state from split-bf16 k/v: kv[d][e], ksum[d]
// =======================================================================
__global__ __launch_bounds__(256) void chunk_state_kernel()
{
    extern __shared__ float sm[];
    float* ks  = sm;         // [t][d] 128x64 fp32
    float* vsm = sm + 8192;

    int cid = blockIdx.x;
    size_t base = (size_t)(cid >> 4) * LL * HD + (size_t)(cid & 15) * CH * HD;
    int tid = threadIdx.x;

    const uint4* kh4 = reinterpret_cast<const uint4*>(g_kh + base);
    const uint4* kl4 = reinterpret_cast<const uint4*>(g_kl + base);
    const uint4* vh4 = reinterpret_cast<const uint4*>(g_vh + base);
    const uint4* vl4 = reinterpret_cast<const uint4*>(g_vl + base);
    for (int i4 = tid; i4 < 1024; i4 += 256) {
        uint4 h = kh4[i4], l = kl4[i4];
        uint4 hv = vh4[i4], lv = vl4[i4];
#pragma unroll
        for (int j = 0; j < 4; j++) {
            __nv_bfloat162 hh = reinterpret_cast<const __nv_bfloat162*>(&h)[j];
            __nv_bfloat162 ll = reinterpret_cast<const __nv_bfloat162*>(&l)[j];
            ks[i4 * 8 + j * 2]     = __bfloat162float(hh.x) + __bfloat162float(ll.x);
            ks[i4 * 8 + j * 2 + 1] = __bfloat162float(hh.y) + __bfloat162float(ll.y);
            __nv_bfloat162 hh2 = reinterpret_cast<const __nv_bfloat162*>(&hv)[j];
            __nv_bfloat162 ll2 = reinterpret_cast<const __nv_bfloat162*>(&lv)[j];
            vsm[i4 * 8 + j * 2]     = __bfloat162float(hh2.x) + __bfloat162float(ll2.x);
            vsm[i4 * 8 + j * 2 + 1] = __bfloat162float(hh2.y) + __bfloat162float(ll2.y);
        }
    }
    __syncthreads();

    int tx = tid & 15, ty = tid >> 4;
    int i0 = ty * 4, j0 = tx * 4;
    float c[4][4] = {};
#pragma unroll 4
    for (int t = 0; t < 128; t++) {
        float4 a = *reinterpret_cast<const float4*>(&ks[t * 64 + i0]);
        float4 bvv = *reinterpret_cast<const float4*>(&vsm[t * 64 + j0]);
        float av[4] = {a.x, a.y, a.z, a.w};
        float bw[4] = {bvv.x, bvv.y, bvv.z, bvv.w};
#pragma unroll
        for (int ii = 0; ii < 4; ii++)
#pragma unroll
            for (int jj = 0; jj < 4; jj++) c[ii][jj] += av[ii] * bw[jj];
    }
    float* Sp = g_S + (size_t)cid * 4096;
#pragma unroll
    for (int ii = 0; ii < 4; ii++) {
        float4 o4 = make_float4(c[ii][0], c[ii][1], c[ii][2], c[ii][3]);
        *reinterpret_cast<float4*>(&Sp[(i0 + ii) * 64 + j0]) = o4;
    }
    if (tid < 64) {
        float s = 0.f;
#pragma unroll 4
        for (int t = 0; t < 128; t++) s += ks[t * 64 + tid];
        g_z[(size_t)cid * 64 + tid] = s;
    }
}

// =======================================================================
// Parallel exclusive prefix over NC chunks
// =======================================================================
__global__ __launch_bounds__(256) void prefix2_kernel()
{
    const int PER = 4096 + 64;
    int idx = blockIdx.x * 256 + threadIdx.x;
    if (idx >= 64 * PER) return;
    int bh = idx / PER, rme = idx - bh * PER;
    if (rme < 4096) {
        float run = 0.f;
        size_t p = (size_t)bh * NC * 4096 + rme;
#pragma unroll
        for (int n = 0; n < NC; n++) {
            float t = g_S[p]; g_S[p] = run; run += t; p += 4096;
        }
    } else {
        int e = rme - 4096;
        float run = 0.f;
        size_t p = (size_t)bh * NC * 64 + e;
#pragma unroll
        for (int n = 0; n < NC; n++) {
            float t = g_z[p]; g_z[p] = run; run += t; p += 64;
        }
    }
}

// =======================================================================
// Intra-chunk attention on tensor cores. Inputs arrive pre-split (bf16
// hi/lo) via cp.async; v and S consumed through ldmatrix.trans B-frags.
// =======================================================================
#define LQE 72
#define LQB 144

#define OFF_QH 0
#define OFF_QL 18432
#define OFF_KH 36864
#define OFF_KL 55296
#define OFF_VH 73728
#define OFF_VL 92160
#define OFF_SH 110592
#define OFF_SL 119808
#define OFF_NUM 129024
#define OFF_Z 161792
#define OFF_DEN 162048
#define INTRA2_SMEM 162560

__global__ __launch_bounds__(256, 1) void intra2_kernel()
{
    extern __shared__ char smc[];
    __nv_bfloat16* qhp = (__nv_bfloat16*)(smc + OFF_QH);
    __nv_bfloat16* qlp = (__nv_bfloat16*)(smc + OFF_QL);
    __nv_bfloat16* Shp = (__nv_bfloat16*)(smc + OFF_SH);
    __nv_bfloat16* Slp = (__nv_bfloat16*)(smc + OFF_SL);
    float* numb = (float*)(smc + OFF_NUM);
    float* zs   = (float*)(smc + OFF_Z);
    float* den  = (float*)(smc + OFF_DEN);
    const uint32_t sb = s2u(smc);

    const int cid = blockIdx.x;
    const int bh = cid >> 4, nch = cid & 15;
    const size_t base = ((size_t)bh * LL + (size_t)nch * CH) * HD;
    const int tid = threadIdx.x, wid = tid >> 5, lane = tid & 31;
    const int wm = wid & 3, wn = wid >> 2;

    const uint32_t sQH = sb + OFF_QH, sQL = sb + OFF_QL;
    const uint32_t sKH = sb + OFF_KH, sKL = sb + OFF_KL;
    const uint32_t sVH = sb + OFF_VH, sVL = sb + OFF_VL;
    const uint32_t sSH = sb + OFF_SH, sSL = sb + OFF_SL;

    // ---- cp.async loads of pre-split q/k/v ([t][d], 144B rows) ----
#pragma unroll
    for (int i = 0; i < 4; i++) {
        int idx = tid + i * 256;           // 0..1023
        int r = idx >> 3, g = idx & 7;
        uint32_t so = (uint32_t)(r * LQB + g * 16);
        size_t src = base + (size_t)r * HD + g * 8;
        cp16(sQH + so, g_qh + src);
        cp16(sQL + so, g_ql + src);
        cp16(sKH + so, g_kh + src);
        cp16(sKL + so, g_kl + src);
        cp16(sVH + so, g_vh + src);
        cp16(sVL + so, g_vl + src);
    }
    asm volatile("cp.async.commit_group;" ::: "memory");

    // ---- S convert+split (natural [d][e]); z; den init ----
    for (int idx = tid; idx < 4096; idx += 256) {
        float sv = g_S[(size_t)cid * 4096 + idx];
        float sh = bfh(sv);
        int d = idx >> 6, e = idx & 63;
        Shp[d * LQE + e] = __float2bfloat16(sv);
        Slp[d * LQE + e] = __float2bfloat16(sv - sh);
    }
    if (tid < 64) zs[tid] = g_z[(size_t)cid * 64 + tid];
    if (tid < 128) den[tid] = 0.f;
    asm volatile("cp.async.wait_group 0;" ::: "memory");
    __syncthreads();

    const int r = lane >> 2, c2 = 2 * (lane & 3);
    const int arow = wm * 32 + (lane & 15);
    const int acol = (lane >> 4) * 8;
    const int brow = ((lane >> 4) << 3) + (lane & 7);
    const int bcol = ((lane >> 3) & 1) * 8;
    const int tkr = (lane & 7) | (((lane >> 3) & 1) << 3);   // trans: k-row in 16
    const int tnc = (lane >> 4) << 3;                        // trans: n-col group

    // ---- phase 1: scores = q k^T ----
    float acc[2][8][4];
#pragma unroll
    for (int a = 0; a < 2; a++)
#pragma unroll
        for (int b = 0; b < 8; b++)
#pragma unroll
            for (int c = 0; c < 4; c++) acc[a][b][c] = 0.f;

#pragma unroll
    for (int g = 0; g < 4; g++) {
        uint32_t qaf[2][4], qbf[2][4];
#pragma unroll
        for (int mt = 0; mt < 2; mt++) {
            uint32_t off = (uint32_t)((arow + mt * 16) * LQB + (acol + g * 16) * 2);
            ldm_x4(qaf[mt], sQH + off);
            ldm_x4(qbf[mt], sQL + off);
        }
        uint32_t kaf[4][4], kbf2[4][4];
#pragma unroll
        for (int p = 0; p < 4; p++) {
            uint32_t off = (uint32_t)((wn * 64 + brow + p * 16) * LQB + (bcol + g * 16) * 2);
            ldm_x4(kaf[p], sKH + off);
            ldm_x4(kbf2[p], sKL + off);
        }
#pragma unroll
        for (int mt = 0; mt < 2; mt++)
#pragma unroll
            for (int nt = 0; nt < 8; nt++) {
                const uint32_t* b1 = &kaf[nt >> 1][(nt & 1) * 2];
                const uint32_t* b2 = &kbf2[nt >> 1][(nt & 1) * 2];
                mma16816(acc[mt][nt], qaf[mt], b1);
                mma16816(acc[mt][nt], qaf[mt], b2);
                mma16816(acc[mt][nt], qbf[mt], b1);
            }
    }

    // ---- mask + rowsum (den) + split scores to A-fragments ----
    uint32_t shf[2][4][4], slf[2][4][4];
#pragma unroll
    for (int mt = 0; mt < 2; mt++) {
        float rs0 = 0.f, rs1 = 0.f;
        int i0 = wm * 32 + mt * 16 + r, i1 = i0 + 8;
#pragma unroll
        for (int nt = 0; nt < 8; nt++) {
            int j0 = wn * 64 + nt * 8 + c2;
            float s00 = (j0     <= i0) ? acc[mt][nt][0] : 0.f;
            float s01 = (j0 + 1 <= i0) ? acc[mt][nt][1] : 0.f;
            float s10 = (j0     <= i1) ? acc[mt][nt][2] : 0.f;
            float s11 = (j0 + 1 <= i1) ? acc[mt][nt][3] : 0.f;
            rs0 += s00 + s01;
            rs1 += s10 + s11;
            int g = nt >> 1, hh = (nt & 1) * 2;
            shf[mt][g][hh]     = pk2(s00, s01);
            shf[mt][g][hh + 1] = pk2(s10, s11);
            slf[mt][g][hh]     = pk2(s00 - bfh(s00), s01 - bfh(s01));
            slf[mt][g][hh + 1] = pk2(s10 - bfh(s10), s11 - bfh(s11));
        }
        rs0 += __shfl_xor_sync(0xffffffffu, rs0, 1);
        rs0 += __shfl_xor_sync(0xffffffffu, rs0, 2);
        rs1 += __shfl_xor_sync(0xffffffffu, rs1, 1);
        rs1 += __shfl_xor_sync(0xffffffffu, rs1, 2);
        if ((lane & 3) == 0) {
            atomicAdd(&den[i0], rs0);
            atomicAdd(&den[i1], rs1);
        }
    }

    // ---- den += q . z ----
    if (tid < 128) {
        float s = 0.f;
#pragma unroll 8
        for (int d = 0; d < 64; d++) {
            float qv = __bfloat162float(qhp[tid * LQE + d]) +
                       __bfloat162float(qlp[tid * LQE + d]);
            s += qv * zs[d];
        }
        atomicAdd(&den[tid], s);
    }

    // ---- phase 2: num = scores @ v (trans B)  +  q @ S (trans B) ----
    float acc2[2][8][4];
#pragma unroll
    for (int a = 0; a < 2; a++)
#pragma unroll
        for (int b = 0; b < 8; b++)
#pragma unroll
            for (int c = 0; c < 4; c++) acc2[a][b][c] = 0.f;

#pragma unroll
    for (int g = 0; g < 4; g++) {
        uint32_t vaf[4][4], vbf2[4][4];
#pragma unroll
        for (int p = 0; p < 4; p++) {
            uint32_t off = (uint32_t)((wn * 64 + g * 16 + tkr) * LQB + (p * 16 + tnc) * 2);
            ldm_x4_t(vaf[p], sVH + off);
            ldm_x4_t(vbf2[p], sVL + off);
        }
#pragma unroll
        for (int mt = 0; mt < 2; mt++)
#pragma unroll
            for (int nt = 0; nt < 8; nt++) {
                const uint32_t* b1 = &vaf[nt >> 1][(nt & 1) * 2];
                const uint32_t* b2 = &vbf2[nt >> 1][(nt & 1) * 2];
                mma16816(acc2[mt][nt], shf[mt][g], b1);
                mma16816(acc2[mt][nt], shf[mt][g], b2);
                mma16816(acc2[mt][nt], slf[mt][g], b1);
            }
    }
#pragma unroll
    for (int g2 = 0; g2 < 2; g2++) {
        int gd = wn * 2 + g2;
        uint32_t qaf[2][4], qbf[2][4];
#pragma unroll
        for (int mt = 0; mt < 2; mt++) {
            uint32_t off = (uint32_t)((arow + mt * 16) * LQB + (acol + gd * 16) * 2);
            ldm_x4(qaf[mt], sQH + off);
            ldm_x4(qbf[mt], sQL + off);
        }
        uint32_t Saf[4][4], Sbf2[4][4];
#pragma unroll
        for (int p = 0; p < 4; p++) {
            uint32_t off = (uint32_t)((gd * 16 + tkr) * LQB + (p * 16 + tnc) * 2);
            ldm_x4_t(Saf[p], sSH + off);
            ldm_x4_t(Sbf2[p], sSL + off);
        }
#pragma unroll
        for (int mt = 0; mt < 2; mt++)
#pragma unroll
            for (int nt = 0; nt < 8; nt++) {
                const uint32_t* b1 = &Saf[nt >> 1][(nt & 1) * 2];
                const uint32_t* b2 = &Sbf2[nt >> 1][(nt & 1) * 2];
                mma16816(acc2[mt][nt], qaf[mt], b1);
                mma16816(acc2[mt][nt], qaf[mt], b2);
                mma16816(acc2[mt][nt], qbf[mt], b1);
            }
    }

    // ---- combine K-split partials, divide by den, store bf16 hi/lo ----
    __syncthreads();
    if (wn == 0) {
#pragma unroll
        for (int mt = 0; mt < 2; mt++) {
            int i0 = wm * 32 + mt * 16 + r;
#pragma unroll
            for (int nt = 0; nt < 8; nt++) {
                int col = nt * 8 + c2;
                numb[i0 * 64 + col]           = acc2[mt][nt][0];
                numb[i0 * 64 + col + 1]       = acc2[mt][nt][1];
                numb[(i0 + 8) * 64 + col]     = acc2[mt][nt][2];
                numb[(i0 + 8) * 64 + col + 1] = acc2[mt][nt][3];
            }
        }
    }
    __syncthreads();
    if (wn == 1) {
        const int bidx = bh >> 4, hd = bh & 15;
#pragma unroll
        for (int mt = 0; mt < 2; mt++) {
            int i0 = wm * 32 + mt * 16 + r;
            float dr0 = 1.f / fmaxf(den[i0], 1e-3f);
            float dr1 = 1.f / fmaxf(den[i0 + 8], 1e-3f);
            int l0 = nch * CH + i0;
            size_t ob0 = ((size_t)bidx * LL + l0) * DD + hd * 64;
            size_t ob1 = ((size_t)bidx * LL + l0 + 8) * DD + hd * 64;
#pragma unroll
            for (int nt = 0; nt < 8; nt++) {
                int col = nt * 8 + c2;
                float o00 = (acc2[mt][nt][0] + numb[i0 * 64 + col])           * dr0;
                float o01 = (acc2[mt][nt][1] + numb[i0 * 64 + col + 1])       * dr0;
                float o10 = (acc2[mt][nt][2] + numb[(i0 + 8) * 64 + col])     * dr1;
                float o11 = (acc2[mt][nt][3] + numb[(i0 + 8) * 64 + col + 1]) * dr1;
                uint32_t h0 = pk2(o00, o01), h1 = pk2(o10, o11);
                uint32_t z0 = pk2(o00 - bfh(o00), o01 - bfh(o01));
                uint32_t z1 = pk2(o10 - bfh(o10), o11 - bfh(o11));
                *reinterpret_cast<uint32_t*>(g_oh + ob0 + col) = h0;
                *reinterpret_cast<uint32_t*>(g_oh + ob1 + col) = h1;
                *reinterpret_cast<uint32_t*>(g_ol + ob0 + col) = z0;
                *reinterpret_cast<uint32_t*>(g_ol + ob1 + col) = z1;
            }
        }
    }
}

// =======================================================================
extern "C" void kernel_launch(void* const* d_in, const int* in_sizes, int n_in,
                              void* d_out, int out_size)
{
    const float* x  = (const float*)d_in[0];
    const float* Wq = (const float*)d_in[1];
    const float* bq = (const float*)d_in[2];
    const float* Wk = (const float*)d_in[3];
    const float* bk = (const float*)d_in[4];
    const float* Wv = (const float*)d_in[5];
    const float* bv = (const float*)d_in[6];
    const float* Wo = (const float*)d_in[7];
    const float* bo = (const float*)d_in[8];
    float* out = (float*)d_out;

    cudaFuncSetAttribute(chunk_state_kernel, cudaFuncAttributeMaxDynamicSharedMemorySize, 65536);
    cudaFuncSetAttribute(intra2_kernel, cudaFuncAttributeMaxDynamicSharedMemorySize, INTRA2_SMEM);
    cudaFuncSetAttribute(gemm_tc, cudaFuncAttributeMaxDynamicSharedMemorySize, GEMM_SMEM);

    __nv_bfloat16 *xh, *xl;
    cudaGetSymbolAddress((void**)&xh, g_xh);
    cudaGetSymbolAddress((void**)&xl, g_xl);

    // 0) split fp32 inputs (x + 4 weights) into bf16 hi/lo pairs
    split_all_kernel<<<(BB*LL*DD + 4*DD*DD) / 1024, 256>>>(x, Wq, Wk, Wv, Wo);

    // 1) fused QKV projection (writes q/k/v pre-split bf16)
    gemm_tc<<<dim3(24, 64), 512, GEMM_SMEM>>>(xh, xl, bq, bk, bv, nullptr, 1);

    // 2) per-chunk kv state + k sums
    chunk_state_kernel<<<BB * HH * NC, 256, 65536>>>();

    // 3) exclusive prefix over chunks
    prefix2_kernel<<<(64 * (4096 + 64) + 255) / 256, 256>>>();

    // 4) intra-chunk attention on tensor cores
    intra2_kernel<<<BB * HH * NC, 256, INTRA2_SMEM>>>();

    // 5) output projection
    gemm_tc<<<dim3(8, 64), 512, GEMM_SMEM>>>(nullptr, nullptr, bo, bo, bo, out, 0);
}

// round 12
// speedup vs baseline: 2.8995x; 1.0302x over previous
#include <cuda_runtime.h>
#include <cuda_bf16.h>
#include <math.h>
#include <stdint.h>

// Problem constants
#define BB   4
#define HH   16
#define LL   2048
#define DD   1024
#define HD   64
#define CH   128
#define NC   16

// ---------------- scratch (device globals) ----------------
__device__ float g_S[BB*HH*NC*HD*HD];
__device__ float g_z[BB*HH*NC*HD];
__device__ __nv_bfloat16 g_xh[BB*LL*DD];   // x split hi/lo
__device__ __nv_bfloat16 g_xl[BB*LL*DD];
__device__ __nv_bfloat16 g_wh[4*DD*DD];    // Wq,Wk,Wv,Wo split hi
__device__ __nv_bfloat16 g_wl[4*DD*DD];    // ... lo
__device__ __nv_bfloat16 g_qh[BB*HH*LL*HD];  // q/k/v split bf16 (B,H,L,d)
__device__ __nv_bfloat16 g_ql[BB*HH*LL*HD];
__device__ __nv_bfloat16 g_kh[BB*HH*LL*HD];
__device__ __nv_bfloat16 g_kl[BB*HH*LL*HD];
__device__ __nv_bfloat16 g_vh[BB*HH*LL*HD];
__device__ __nv_bfloat16 g_vl[BB*HH*LL*HD];
__device__ __nv_bfloat16 g_oh[BB*LL*DD];   // attention out split hi/lo
__device__ __nv_bfloat16 g_ol[BB*LL*DD];

// ---------------- PTX helpers ----------------
__device__ __forceinline__ uint32_t s2u(const void* p) {
    uint32_t a;
    asm("{ .reg .u64 t; cvta.to.shared.u64 t, %1; cvt.u32.u64 %0, t; }" : "=r"(a) : "l"(p));
    return a;
}
__device__ __forceinline__ void cp16(uint32_t s, const void* g) {
    asm volatile("cp.async.cg.shared.global [%0], [%1], 16;" :: "r"(s), "l"(g) : "memory");
}
__device__ __forceinline__ void ldm_x4(uint32_t* r, uint32_t addr) {
    asm volatile("ldmatrix.sync.aligned.m8n8.x4.shared.b16 {%0,%1,%2,%3}, [%4];"
        : "=r"(r[0]), "=r"(r[1]), "=r"(r[2]), "=r"(r[3]) : "r"(addr));
}
__device__ __forceinline__ void ldm_x4_t(uint32_t* r, uint32_t addr) {
    asm volatile("ldmatrix.sync.aligned.m8n8.x4.trans.shared.b16 {%0,%1,%2,%3}, [%4];"
        : "=r"(r[0]), "=r"(r[1]), "=r"(r[2]), "=r"(r[3]) : "r"(addr));
}
__device__ __forceinline__ void mma16816(float* d, const uint32_t* a, const uint32_t* b) {
    asm volatile("mma.sync.aligned.m16n8k16.row.col.f32.bf16.bf16.f32 "
        "{%0,%1,%2,%3}, {%4,%5,%6,%7}, {%8,%9}, {%0,%1,%2,%3};"
        : "+f"(d[0]), "+f"(d[1]), "+f"(d[2]), "+f"(d[3])
        : "r"(a[0]), "r"(a[1]), "r"(a[2]), "r"(a[3]), "r"(b[0]), "r"(b[1]));
}
__device__ __forceinline__ uint32_t pk2(float lo, float hi) {
    uint32_t r;
    asm("cvt.rn.bf16x2.f32 %0, %1, %2;" : "=r"(r) : "f"(hi), "f"(lo));
    return r;
}
__device__ __forceinline__ float bfh(float x) {
    return __bfloat162float(__float2bfloat16(x));
}
// 128B-row XOR swizzle: row, colbyte (colbyte any, 16B-group swizzled)
__device__ __forceinline__ uint32_t isw(int row, int colb) {
    return (uint32_t)(row * 128 + ((((colb >> 4) ^ (row & 7)) << 4) | (colb & 15)));
}

// ---------------- split fp32 -> bf16 hi + bf16 lo (x + all 4 weights) ----
__global__ __launch_bounds__(256) void split_all_kernel(
    const float* __restrict__ x,
    const float* __restrict__ Wq, const float* __restrict__ Wk,
    const float* __restrict__ Wv, const float* __restrict__ Wo)
{
    const int XN = BB * LL * DD;          // 8M
    long long i = ((long long)blockIdx.x * 256 + threadIdx.x) * 4;
    const float* src;
    __nv_bfloat16 *dh, *dl;
    long long off;
    if (i < XN) {
        src = x; dh = g_xh; dl = g_xl; off = i;
    } else {
        long long j = i - XN;
        int w = (int)(j >> 20);           // DD*DD = 1M
        off = j & ((1 << 20) - 1);
        src = (w == 0) ? Wq : (w == 1) ? Wk : (w == 2) ? Wv : Wo;
        dh = g_wh + ((long long)w << 20);
        dl = g_wl + ((long long)w << 20);
    }
    float4 v = *reinterpret_cast<const float4*>(src + off);
    __nv_bfloat16 h0 = __float2bfloat16(v.x), h1 = __float2bfloat16(v.y);
    __nv_bfloat16 h2 = __float2bfloat16(v.z), h3 = __float2bfloat16(v.w);
    __nv_bfloat16 l0 = __float2bfloat16(v.x - __bfloat162float(h0));
    __nv_bfloat16 l1 = __float2bfloat16(v.y - __bfloat162float(h1));
    __nv_bfloat16 l2 = __float2bfloat16(v.z - __bfloat162float(h2));
    __nv_bfloat16 l3 = __float2bfloat16(v.w - __bfloat162float(h3));
    __nv_bfloat162 ph0; ph0.x = h0; ph0.y = h1;
    __nv_bfloat162 ph1; ph1.x = h2; ph1.y = h3;
    __nv_bfloat162 pl0; pl0.x = l0; pl0.y = l1;
    __nv_bfloat162 pl1; pl1.x = l2; pl1.y = l3;
    *reinterpret_cast<__nv_bfloat162*>(dh + off)     = ph0;
    *reinterpret_cast<__nv_bfloat162*>(dh + off + 2) = ph1;
    *reinterpret_cast<__nv_bfloat162*>(dl + off)     = pl0;
    *reinterpret_cast<__nv_bfloat162*>(dl + off + 2) = pl1;
}

// =======================================================================
// HMMA split-bf16 GEMM (unchanged from passing R10)
// =======================================================================
#define LDS_B   144
#define MAT_B   (128 * LDS_B)
#define STAGE_B (4 * MAT_B)
#define STAGES  3
#define GEMM_SMEM (STAGES * STAGE_B)  // 221184

__global__ __launch_bounds__(512, 1) void gemm_tc(
    const __nv_bfloat16* __restrict__ Ah0, const __nv_bfloat16* __restrict__ Al0,
    const float* __restrict__ bq, const float* __restrict__ bk, const float* __restrict__ bv,
    float* __restrict__ outp, int qkv_mode)
{
    extern __shared__ char smem[];
    const uint32_t sb = s2u(smem);
    const int tid = threadIdx.x;
    const int wid = tid >> 5, lane = tid & 31;
    const int wm = wid & 3, wn = wid >> 2;

    const __nv_bfloat16 *Ah, *Al, *Bh, *Bl;
    const float* bias;
    __nv_bfloat16 *ohp = nullptr, *olp = nullptr;
    int n0, do_silu;
    if (qkv_mode) {
        int w = blockIdx.x >> 3;
        Bh = g_wh + (size_t)w * (DD * DD);
        Bl = g_wl + (size_t)w * (DD * DD);
        bias = (w == 0) ? bq : (w == 1) ? bk : bv;
        ohp = (w == 0) ? g_qh : (w == 1) ? g_kh : g_vh;
        olp = (w == 0) ? g_ql : (w == 1) ? g_kl : g_vl;
        do_silu = (w < 2);
        n0 = (blockIdx.x & 7) * 128;
        Ah = Ah0; Al = Al0;
    } else {
        Bh = g_wh + 3 * (size_t)(DD * DD);
        Bl = g_wl + 3 * (size_t)(DD * DD);
        bias = bq; do_silu = 0;
        n0 = blockIdx.x * 128;
        Ah = g_oh; Al = g_ol;
    }
    const int m0 = blockIdx.y * 128;

    float acc[2][4][4];
#pragma unroll
    for (int a = 0; a < 2; a++)
#pragma unroll
        for (int b = 0; b < 4; b++)
#pragma unroll
            for (int c = 0; c < 4; c++) acc[a][b][c] = 0.f;

    auto load_chunk = [&](int cc) {
        const int kc = cc * 64;
        const uint32_t st = sb + (uint32_t)(cc % 3) * STAGE_B;
#pragma unroll
        for (int i = 0; i < 2; i++) {
            int idx = tid + i * 512;
            int r = idx >> 3, g = idx & 7;
            uint32_t so = (uint32_t)(r * LDS_B + g * 16);
            size_t ea = (size_t)(m0 + r) * DD + kc + g * 8;
            size_t eb = (size_t)(n0 + r) * DD + kc + g * 8;
            cp16(st + 0 * MAT_B + so, Ah + ea);
            cp16(st + 1 * MAT_B + so, Al + ea);
            cp16(st + 2 * MAT_B + so, Bh + eb);
            cp16(st + 3 * MAT_B + so, Bl + eb);
        }
        asm volatile("cp.async.commit_group;" ::: "memory");
    };

    load_chunk(0);

    const int arow = wm * 32 + (lane & 15);
    const int acol = (lane >> 4) * 8;
    const int brow = wn * 32 + ((lane >> 4) << 3) + (lane & 7);
    const int bcol = ((lane >> 3) & 1) * 8;

    const int NK = 1024 / 64;   // 16 chunks
    for (int c = 0; c < NK; c++) {
        if (c + 1 < NK) {
            load_chunk(c + 1);
            asm volatile("cp.async.wait_group 1;" ::: "memory");
        } else {
            asm volatile("cp.async.wait_group 0;" ::: "memory");
        }
        __syncthreads();

        const uint32_t st  = sb + (uint32_t)(c % 3) * STAGE_B;
        const uint32_t aAh = st, aAl = st + MAT_B, aBh = st + 2 * MAT_B, aBl = st + 3 * MAT_B;

#pragma unroll
        for (int h = 0; h < 4; h++) {
            uint32_t ah[2][4], al[2][4];
#pragma unroll
            for (int mt = 0; mt < 2; mt++) {
                uint32_t off = (uint32_t)((arow + mt * 16) * LDS_B + (acol + h * 16) * 2);
                ldm_x4(ah[mt], aAh + off);
                ldm_x4(al[mt], aAl + off);
            }
            uint32_t bhf[2][4], blf[2][4];
#pragma unroll
            for (int p = 0; p < 2; p++) {
                uint32_t off = (uint32_t)((brow + p * 16) * LDS_B + (bcol + h * 16) * 2);
                ldm_x4(bhf[p], aBh + off);
                ldm_x4(blf[p], aBl + off);
            }
#pragma unroll
            for (int mt = 0; mt < 2; mt++)
#pragma unroll
                for (int nt = 0; nt < 4; nt++) {
                    const uint32_t* bh2 = &bhf[nt >> 1][(nt & 1) * 2];
                    const uint32_t* bl2 = &blf[nt >> 1][(nt & 1) * 2];
                    mma16816(acc[mt][nt], ah[mt], bh2);
                    mma16816(acc[mt][nt], ah[mt], bl2);
                    mma16816(acc[mt][nt], al[mt], bh2);
                }
        }
    }

    // ---- epilogue ----
    float bv2[4][2];
#pragma unroll
    for (int nt = 0; nt < 4; nt++) {
        int col = n0 + wn * 32 + nt * 8 + 2 * (lane & 3);
        bv2[nt][0] = bias[col];
        bv2[nt][1] = bias[col + 1];
    }
#pragma unroll
    for (int mt = 0; mt < 2; mt++) {
#pragma unroll
        for (int half = 0; half < 2; half++) {
            int m = m0 + wm * 32 + mt * 16 + (lane >> 2) + half * 8;
            int b = m >> 11, lpos = m & 2047;
#pragma unroll
            for (int nt = 0; nt < 4; nt++) {
                int col = n0 + wn * 32 + nt * 8 + 2 * (lane & 3);
                float v0 = acc[mt][nt][half * 2 + 0] + bv2[nt][0];
                float v1 = acc[mt][nt][half * 2 + 1] + bv2[nt][1];
                if (do_silu) {
                    v0 = v0 / (1.f + expf(-v0));
                    v1 = v1 / (1.f + expf(-v1));
                }
                if (qkv_mode) {
                    int hidx = col >> 6, i2 = col & 63;
                    size_t po = ((size_t)((b << 4) | hidx) * LL + lpos) * HD + i2;
                    *reinterpret_cast<uint32_t*>(ohp + po) = pk2(v0, v1);
                    *reinterpret_cast<uint32_t*>(olp + po) =
                        pk2(v0 - bfh(v0), v1 - bfh(v1));
                } else {
                    *reinterpret_cast<float2*>(outp + (size_t)m * DD + col) =
                        make_float2(v0, v1);
                }
            }
        }
    }
}

// =======================================================================
// Per-chunk state from split-bf16 k/v: kv[d][e], ksum[d]
// =======================================================================
__global__ __launch_bounds__(256) void chunk_state_kernel()
{
    extern __shared__ float sm[];
    float* ks  = sm;
    float* vsm = sm + 8192;

    int cid = blockIdx.x;
    size_t base = (size_t)(cid >> 4) * LL * HD + (size_t)(cid & 15) * CH * HD;
    int tid = threadIdx.x;

    const uint4* kh4 = reinterpret_cast<const uint4*>(g_kh + base);
    const uint4* kl4 = reinterpret_cast<const uint4*>(g_kl + base);
    const uint4* vh4 = reinterpret_cast<const uint4*>(g_vh + base);
    const uint4* vl4 = reinterpret_cast<const uint4*>(g_vl + base);
    for (int i4 = tid; i4 < 1024; i4 += 256) {
        uint4 h = kh4[i4], l = kl4[i4];
        uint4 hv = vh4[i4], lv = vl4[i4];
#pragma unroll
        for (int j = 0; j < 4; j++) {
            __nv_bfloat162 hh = reinterpret_cast<const __nv_bfloat162*>(&h)[j];
            __nv_bfloat162 ll = reinterpret_cast<const __nv_bfloat162*>(&l)[j];
            ks[i4 * 8 + j * 2]     = __bfloat162float(hh.x) + __bfloat162float(ll.x);
            ks[i4 * 8 + j * 2 + 1] = __bfloat162float(hh.y) + __bfloat162float(ll.y);
            __nv_bfloat162 hh2 = reinterpret_cast<const __nv_bfloat162*>(&hv)[j];
            __nv_bfloat162 ll2 = reinterpret_cast<const __nv_bfloat162*>(&lv)[j];
            vsm[i4 * 8 + j * 2]     = __bfloat162float(hh2.x) + __bfloat162float(ll2.x);
            vsm[i4 * 8 + j * 2 + 1] = __bfloat162float(hh2.y) + __bfloat162float(ll2.y);
        }
    }
    __syncthreads();

    int tx = tid & 15, ty = tid >> 4;
    int i0 = ty * 4, j0 = tx * 4;
    float c[4][4] = {};
#pragma unroll 4
    for (int t = 0; t < 128; t++) {
        float4 a = *reinterpret_cast<const float4*>(&ks[t * 64 + i0]);
        float4 bvv = *reinterpret_cast<const float4*>(&vsm[t * 64 + j0]);
        float av[4] = {a.x, a.y, a.z, a.w};
        float bw[4] = {bvv.x, bvv.y, bvv.z, bvv.w};
#pragma unroll
        for (int ii = 0; ii < 4; ii++)
#pragma unroll
            for (int jj = 0; jj < 4; jj++) c[ii][jj] += av[ii] * bw[jj];
    }
    float* Sp = g_S + (size_t)cid * 4096;
#pragma unroll
    for (int ii = 0; ii < 4; ii++) {
        float4 o4 = make_float4(c[ii][0], c[ii][1], c[ii][2], c[ii][3]);
        *reinterpret_cast<float4*>(&Sp[(i0 + ii) * 64 + j0]) = o4;
    }
    if (tid < 64) {
        float s = 0.f;
#pragma unroll 4
        for (int t = 0; t < 128; t++) s += ks[t * 64 + tid];
        g_z[(size_t)cid * 64 + tid] = s;
    }
}

// =======================================================================
// Parallel exclusive prefix over NC chunks
// =======================================================================
__global__ __launch_bounds__(256) void prefix2_kernel()
{
    const int PER = 4096 + 64;
    int idx = blockIdx.x * 256 + threadIdx.x;
    if (idx >= 64 * PER) return;
    int bh = idx / PER, rme = idx - bh * PER;
    if (rme < 4096) {
        float run = 0.f;
        size_t p = (size_t)bh * NC * 4096 + rme;
#pragma unroll
        for (int n = 0; n < NC; n++) {
            float t = g_S[p]; g_S[p] = run; run += t; p += 4096;
        }
    } else {
        int e = rme - 4096;
        float run = 0.f;
        size_t p = (size_t)bh * NC * 64 + e;
#pragma unroll
        for (int n = 0; n < NC; n++) {
            float t = g_z[p]; g_z[p] = run; run += t; p += 64;
        }
    }
}

// =======================================================================
// Intra-chunk attention, tensor cores, 112.8KB smem (swizzled 128B rows)
// + <=128 regs (phase-2 split in two column halves) -> 2 CTAs/SM.
// numb overlays the K region (dead after phase 1).
// =======================================================================
#define OFF_QH 0
#define OFF_QL 16384
#define OFF_KH 32768
#define OFF_KL 49152
#define OFF_VH 65536
#define OFF_VL 81920
#define OFF_SH 98304
#define OFF_SL 106496
#define OFF_Z  114688
#define OFF_DEN 114944
#define OFF_NUM OFF_KH
#define INTRA2_SMEM 115456

__global__ __launch_bounds__(256, 2) void intra2_kernel()
{
    extern __shared__ char smc[];
    float* numb = (float*)(smc + OFF_NUM);
    float* zs   = (float*)(smc + OFF_Z);
    float* den  = (float*)(smc + OFF_DEN);
    const uint32_t sb = s2u(smc);

    const int cid = blockIdx.x;
    const int bh = cid >> 4, nch = cid & 15;
    const size_t base = ((size_t)bh * LL + (size_t)nch * CH) * HD;
    const int tid = threadIdx.x, wid = tid >> 5, lane = tid & 31;
    const int wm = wid & 3, wn = wid >> 2;

    const uint32_t sQH = sb + OFF_QH, sQL = sb + OFF_QL;
    const uint32_t sKH = sb + OFF_KH, sKL = sb + OFF_KL;
    const uint32_t sVH = sb + OFF_VH, sVL = sb + OFF_VL;
    const uint32_t sSH = sb + OFF_SH, sSL = sb + OFF_SL;

    // ---- cp.async loads of pre-split q/k/v (swizzled 128B rows) ----
#pragma unroll
    for (int i = 0; i < 4; i++) {
        int idx = tid + i * 256;           // 0..1023
        int r = idx >> 3, g = idx & 7;
        uint32_t so = (uint32_t)(r * 128 + ((g ^ (r & 7)) << 4));
        size_t src = base + (size_t)r * HD + g * 8;
        cp16(sQH + so, g_qh + src);
        cp16(sQL + so, g_ql + src);
        cp16(sKH + so, g_kh + src);
        cp16(sKL + so, g_kl + src);
        cp16(sVH + so, g_vh + src);
        cp16(sVL + so, g_vl + src);
    }
    asm volatile("cp.async.commit_group;" ::: "memory");

    // ---- S convert+split into swizzled [d][e]; z; den init ----
    for (int idx = tid; idx < 4096; idx += 256) {
        float sv = g_S[(size_t)cid * 4096 + idx];
        float sh = bfh(sv);
        int d = idx >> 6, e = idx & 63;
        uint32_t off = isw(d, e * 2);
        *(__nv_bfloat16*)(smc + OFF_SH + off) = __float2bfloat16(sv);
        *(__nv_bfloat16*)(smc + OFF_SL + off) = __float2bfloat16(sv - sh);
    }
    if (tid < 64) zs[tid] = g_z[(size_t)cid * 64 + tid];
    if (tid < 128) den[tid] = 0.f;
    asm volatile("cp.async.wait_group 0;" ::: "memory");
    __syncthreads();

    const int r = lane >> 2, c2 = 2 * (lane & 3);
    const int arow = wm * 32 + (lane & 15);
    const int acol = (lane >> 4) * 8;
    const int brow = ((lane >> 4) << 3) + (lane & 7);
    const int bcol = ((lane >> 3) & 1) * 8;
    const int tkr = (lane & 7) | (((lane >> 3) & 1) << 3);
    const int tnc = (lane >> 4) << 3;

    // ---- phase 1: scores = q k^T ----
    float acc[2][8][4];
#pragma unroll
    for (int a = 0; a < 2; a++)
#pragma unroll
        for (int b = 0; b < 8; b++)
#pragma unroll
            for (int c = 0; c < 4; c++) acc[a][b][c] = 0.f;

#pragma unroll
    for (int g = 0; g < 4; g++) {
        uint32_t qaf[2][4], qbf[2][4];
#pragma unroll
        for (int mt = 0; mt < 2; mt++) {
            uint32_t off = isw(arow + mt * 16, (acol + g * 16) * 2);
            ldm_x4(qaf[mt], sQH + off);
            ldm_x4(qbf[mt], sQL + off);
        }
        uint32_t kaf[4][4], kbf2[4][4];
#pragma unroll
        for (int p = 0; p < 4; p++) {
            uint32_t off = isw(wn * 64 + brow + p * 16, (bcol + g * 16) * 2);
            ldm_x4(kaf[p], sKH + off);
            ldm_x4(kbf2[p], sKL + off);
        }
#pragma unroll
        for (int mt = 0; mt < 2; mt++)
#pragma unroll
            for (int nt = 0; nt < 8; nt++) {
                const uint32_t* b1 = &kaf[nt >> 1][(nt & 1) * 2];
                const uint32_t* b2 = &kbf2[nt >> 1][(nt & 1) * 2];
                mma16816(acc[mt][nt], qaf[mt], b1);
                mma16816(acc[mt][nt], qaf[mt], b2);
                mma16816(acc[mt][nt], qbf[mt], b1);
            }
    }

    // ---- mask + rowsum (den) + split scores to A-fragments ----
    uint32_t shf[2][4][4], slf[2][4][4];
#pragma unroll
    for (int mt = 0; mt < 2; mt++) {
        float rs0 = 0.f, rs1 = 0.f;
        int i0 = wm * 32 + mt * 16 + r, i1 = i0 + 8;
#pragma unroll
        for (int nt = 0; nt < 8; nt++) {
            int j0 = wn * 64 + nt * 8 + c2;
            float s00 = (j0     <= i0) ? acc[mt][nt][0] : 0.f;
            float s01 = (j0 + 1 <= i0) ? acc[mt][nt][1] : 0.f;
            float s10 = (j0     <= i1) ? acc[mt][nt][2] : 0.f;
            float s11 = (j0 + 1 <= i1) ? acc[mt][nt][3] : 0.f;
            rs0 += s00 + s01;
            rs1 += s10 + s11;
            int g = nt >> 1, hh = (nt & 1) * 2;
            shf[mt][g][hh]     = pk2(s00, s01);
            shf[mt][g][hh + 1] = pk2(s10, s11);
            slf[mt][g][hh]     = pk2(s00 - bfh(s00), s01 - bfh(s01));
            slf[mt][g][hh + 1] = pk2(s10 - bfh(s10), s11 - bfh(s11));
        }
        rs0 += __shfl_xor_sync(0xffffffffu, rs0, 1);
        rs0 += __shfl_xor_sync(0xffffffffu, rs0, 2);
        rs1 += __shfl_xor_sync(0xffffffffu, rs1, 1);
        rs1 += __shfl_xor_sync(0xffffffffu, rs1, 2);
        if ((lane & 3) == 0) {
            atomicAdd(&den[i0], rs0);
            atomicAdd(&den[i1], rs1);
        }
    }

    // ---- den += q . z ----
    if (tid < 128) {
        float s = 0.f;
        int tmask = tid & 7;
#pragma unroll 8
        for (int d = 0; d < 64; d++) {
            uint32_t off = (uint32_t)(tid * 128 + ((((d >> 3) ^ tmask) << 4) | ((d & 7) * 2)));
            float qv = __bfloat162float(*(__nv_bfloat16*)(smc + OFF_QH + off)) +
                       __bfloat162float(*(__nv_bfloat16*)(smc + OFF_QL + off));
            s += qv * zs[d];
        }
        atomicAdd(&den[tid], s);
    }

    // ---- phase 2 in two output-column halves (regs <= 128) ----
    const int bidx = bh >> 4, hd = bh & 15;
#pragma unroll 1
    for (int eh = 0; eh < 2; eh++) {
        float acc2[2][4][4];
#pragma unroll
        for (int a = 0; a < 2; a++)
#pragma unroll
            for (int b = 0; b < 4; b++)
#pragma unroll
                for (int c = 0; c < 4; c++) acc2[a][b][c] = 0.f;

        // scores @ v (transposed B loads), this warp's wn K-half
#pragma unroll
        for (int g = 0; g < 4; g++) {
            uint32_t vaf[2][4], vbf2[2][4];
#pragma unroll
            for (int p2 = 0; p2 < 2; p2++) {
                int pg = eh * 2 + p2;
                uint32_t off = isw(wn * 64 + g * 16 + tkr, (pg * 16 + tnc) * 2);
                ldm_x4_t(vaf[p2], sVH + off);
                ldm_x4_t(vbf2[p2], sVL + off);
            }
#pragma unroll
            for (int mt = 0; mt < 2; mt++)
#pragma unroll
                for (int nt = 0; nt < 4; nt++) {
                    const uint32_t* b1 = &vaf[nt >> 1][(nt & 1) * 2];
                    const uint32_t* b2 = &vbf2[nt >> 1][(nt & 1) * 2];
                    mma16816(acc2[mt][nt], shf[mt][g], b1);
                    mma16816(acc2[mt][nt], shf[mt][g], b2);
                    mma16816(acc2[mt][nt], slf[mt][g], b1);
                }
        }
        // q @ S (transposed B loads), this warp's wn d-half
#pragma unroll
        for (int g2 = 0; g2 < 2; g2++) {
            int gd = wn * 2 + g2;
            uint32_t qaf[2][4], qbf[2][4];
#pragma unroll
            for (int mt = 0; mt < 2; mt++) {
                uint32_t off = isw(arow + mt * 16, (acol + gd * 16) * 2);
                ldm_x4(qaf[mt], sQH + off);
                ldm_x4(qbf[mt], sQL + off);
            }
            uint32_t Saf[2][4], Sbf2[2][4];
#pragma unroll
            for (int p2 = 0; p2 < 2; p2++) {
                int pg = eh * 2 + p2;
                uint32_t off = isw(gd * 16 + tkr, (pg * 16 + tnc) * 2);
                ldm_x4_t(Saf[p2], sSH + off);
                ldm_x4_t(Sbf2[p2], sSL + off);
            }
#pragma unroll
            for (int mt = 0; mt < 2; mt++)
#pragma unroll
                for (int nt = 0; nt < 4; nt++) {
                    const uint32_t* b1 = &Saf[nt >> 1][(nt & 1) * 2];
                    const uint32_t* b2 = &Sbf2[nt >> 1][(nt & 1) * 2];
                    mma16816(acc2[mt][nt], qaf[mt], b1);
                    mma16816(acc2[mt][nt], qaf[mt], b2);
                    mma16816(acc2[mt][nt], qbf[mt], b1);
                }
        }

        // combine wn partials via numb (overlays dead K region), store
        __syncthreads();
        if (wn == 0) {
#pragma unroll
            for (int mt = 0; mt < 2; mt++) {
                int i0 = wm * 32 + mt * 16 + r;
#pragma unroll
                for (int nt = 0; nt < 4; nt++) {
                    int cl = nt * 8 + c2;
                    numb[i0 * 32 + cl]           = acc2[mt][nt][0];
                    numb[i0 * 32 + cl + 1]       = acc2[mt][nt][1];
                    numb[(i0 + 8) * 32 + cl]     = acc2[mt][nt][2];
                    numb[(i0 + 8) * 32 + cl + 1] = acc2[mt][nt][3];
                }
            }
        }
        __syncthreads();
        if (wn == 1) {
#pragma unroll
            for (int mt = 0; mt < 2; mt++) {
                int i0 = wm * 32 + mt * 16 + r;
                float dr0 = 1.f / fmaxf(den[i0], 1e-3f);
                float dr1 = 1.f / fmaxf(den[i0 + 8], 1e-3f);
                int l0 = nch * CH + i0;
                size_t ob0 = ((size_t)bidx * LL + l0) * DD + hd * 64 + eh * 32;
                size_t ob1 = ((size_t)bidx * LL + l0 + 8) * DD + hd * 64 + eh * 32;
#pragma unroll
                for (int nt = 0; nt < 4; nt++) {
                    int cl = nt * 8 + c2;
                    float o00 = (acc2[mt][nt][0] + numb[i0 * 32 + cl])           * dr0;
                    float o01 = (acc2[mt][nt][1] + numb[i0 * 32 + cl + 1])       * dr0;
                    float o10 = (acc2[mt][nt][2] + numb[(i0 + 8) * 32 + cl])     * dr1;
                    float o11 = (acc2[mt][nt][3] + numb[(i0 + 8) * 32 + cl + 1]) * dr1;
                    *reinterpret_cast<uint32_t*>(g_oh + ob0 + cl) = pk2(o00, o01);
                    *reinterpret_cast<uint32_t*>(g_oh + ob1 + cl) = pk2(o10, o11);
                    *reinterpret_cast<uint32_t*>(g_ol + ob0 + cl) =
                        pk2(o00 - bfh(o00), o01 - bfh(o01));
                    *reinterpret_cast<uint32_t*>(g_ol + ob1 + cl) =
                        pk2(o10 - bfh(o10), o11 - bfh(o11));
                }
            }
        }
        __syncthreads();
    }
}

// =======================================================================
extern "C" void kernel_launch(void* const* d_in, const int* in_sizes, int n_in,
                              void* d_out, int out_size)
{
    const float* x  = (const float*)d_in[0];
    const float* Wq = (const float*)d_in[1];
    const float* bq = (const float*)d_in[2];
    const float* Wk = (const float*)d_in[3];
    const float* bk = (const float*)d_in[4];
    const float* Wv = (const float*)d_in[5];
    const float* bv = (const float*)d_in[6];
    const float* Wo = (const float*)d_in[7];
    const float* bo = (const float*)d_in[8];
    float* out = (float*)d_out;

    cudaFuncSetAttribute(chunk_state_kernel, cudaFuncAttributeMaxDynamicSharedMemorySize, 65536);
    cudaFuncSetAttribute(intra2_kernel, cudaFuncAttributeMaxDynamicSharedMemorySize, INTRA2_SMEM);
    cudaFuncSetAttribute(gemm_tc, cudaFuncAttributeMaxDynamicSharedMemorySize, GEMM_SMEM);

    __nv_bfloat16 *xh, *xl;
    cudaGetSymbolAddress((void**)&xh, g_xh);
    cudaGetSymbolAddress((void**)&xl, g_xl);

    // 0) split fp32 inputs (x + 4 weights) into bf16 hi/lo pairs
    split_all_kernel<<<(BB*LL*DD + 4*DD*DD) / 1024, 256>>>(x, Wq, Wk, Wv, Wo);

    // 1) fused QKV projection (writes q/k/v pre-split bf16)
    gemm_tc<<<dim3(24, 64), 512, GEMM_SMEM>>>(xh, xl, bq, bk, bv, nullptr, 1);

    // 2) per-chunk kv state + k sums
    chunk_state_kernel<<<BB * HH * NC, 256, 65536>>>();

    // 3) exclusive prefix over chunks
    prefix2_kernel<<<(64 * (4096 + 64) + 255) / 256, 256>>>();

    // 4) intra-chunk attention on tensor cores (2 CTAs/SM)
    intra2_kernel<<<BB * HH * NC, 256, INTRA2_SMEM>>>();

    // 5) output projection
    gemm_tc<<<dim3(8, 64), 512, GEMM_SMEM>>>(nullptr, nullptr, bo, bo, bo, out, 0);
}

// round 13
// speedup vs baseline: 3.0287x; 1.0445x over previous
#include <cuda_runtime.h>
#include <cuda_bf16.h>
#include <math.h>
#include <stdint.h>

// Problem constants
#define BB   4
#define HH   16
#define LL   2048
#define DD   1024
#define HD   64
#define CH   128
#define NC   16

// ---------------- scratch (device globals) ----------------
__device__ float g_S[BB*HH*NC*HD*HD];
__device__ float g_z[BB*HH*NC*HD];
__device__ __nv_bfloat16 g_xh[BB*LL*DD];   // x split hi/lo
__device__ __nv_bfloat16 g_xl[BB*LL*DD];
__device__ __nv_bfloat16 g_wh[4*DD*DD];    // Wq,Wk,Wv,Wo split hi
__device__ __nv_bfloat16 g_wl[4*DD*DD];    // ... lo
__device__ __nv_bfloat16 g_qh[BB*HH*LL*HD];  // q/k/v split bf16 (B,H,L,d)
__device__ __nv_bfloat16 g_ql[BB*HH*LL*HD];
__device__ __nv_bfloat16 g_kh[BB*HH*LL*HD];
__device__ __nv_bfloat16 g_kl[BB*HH*LL*HD];
__device__ __nv_bfloat16 g_vh[BB*HH*LL*HD];
__device__ __nv_bfloat16 g_vl[BB*HH*LL*HD];
__device__ __nv_bfloat16 g_oh[BB*LL*DD];   // attention out split hi/lo
__device__ __nv_bfloat16 g_ol[BB*LL*DD];

// ---------------- PTX helpers ----------------
__device__ __forceinline__ uint32_t s2u(const void* p) {
    uint32_t a;
    asm("{ .reg .u64 t; cvta.to.shared.u64 t, %1; cvt.u32.u64 %0, t; }" : "=r"(a) : "l"(p));
    return a;
}
__device__ __forceinline__ void cp16(uint32_t s, const void* g) {
    asm volatile("cp.async.cg.shared.global [%0], [%1], 16;" :: "r"(s), "l"(g) : "memory");
}
__device__ __forceinline__ void ldm_x4(uint32_t* r, uint32_t addr) {
    asm volatile("ldmatrix.sync.aligned.m8n8.x4.shared.b16 {%0,%1,%2,%3}, [%4];"
        : "=r"(r[0]), "=r"(r[1]), "=r"(r[2]), "=r"(r[3]) : "r"(addr));
}
__device__ __forceinline__ void ldm_x4_t(uint32_t* r, uint32_t addr) {
    asm volatile("ldmatrix.sync.aligned.m8n8.x4.trans.shared.b16 {%0,%1,%2,%3}, [%4];"
        : "=r"(r[0]), "=r"(r[1]), "=r"(r[2]), "=r"(r[3]) : "r"(addr));
}
__device__ __forceinline__ void mma16816(float* d, const uint32_t* a, const uint32_t* b) {
    asm volatile("mma.sync.aligned.m16n8k16.row.col.f32.bf16.bf16.f32 "
        "{%0,%1,%2,%3}, {%4,%5,%6,%7}, {%8,%9}, {%0,%1,%2,%3};"
        : "+f"(d[0]), "+f"(d[1]), "+f"(d[2]), "+f"(d[3])
        : "r"(a[0]), "r"(a[1]), "r"(a[2]), "r"(a[3]), "r"(b[0]), "r"(b[1]));
}
__device__ __forceinline__ uint32_t pk2(float lo, float hi) {
    uint32_t r;
    asm("cvt.rn.bf16x2.f32 %0, %1, %2;" : "=r"(r) : "f"(hi), "f"(lo));
    return r;
}
__device__ __forceinline__ float bfh(float x) {
    return __bfloat162float(__float2bfloat16(x));
}
// 128B-row XOR swizzle: row, colbyte
__device__ __forceinline__ uint32_t isw(int row, int colb) {
    return (uint32_t)(row * 128 + ((((colb >> 4) ^ (row & 7)) << 4) | (colb & 15)));
}

// ---------------- split fp32 -> bf16 hi + bf16 lo (x + all 4 weights) ----
__global__ __launch_bounds__(256) void split_all_kernel(
    const float* __restrict__ x,
    const float* __restrict__ Wq, const float* __restrict__ Wk,
    const float* __restrict__ Wv, const float* __restrict__ Wo)
{
    const int XN = BB * LL * DD;
    long long i = ((long long)blockIdx.x * 256 + threadIdx.x) * 4;
    const float* src;
    __nv_bfloat16 *dh, *dl;
    long long off;
    if (i < XN) {
        src = x; dh = g_xh; dl = g_xl; off = i;
    } else {
        long long j = i - XN;
        int w = (int)(j >> 20);
        off = j & ((1 << 20) - 1);
        src = (w == 0) ? Wq : (w == 1) ? Wk : (w == 2) ? Wv : Wo;
        dh = g_wh + ((long long)w << 20);
        dl = g_wl + ((long long)w << 20);
    }
    float4 v = *reinterpret_cast<const float4*>(src + off);
    __nv_bfloat16 h0 = __float2bfloat16(v.x), h1 = __float2bfloat16(v.y);
    __nv_bfloat16 h2 = __float2bfloat16(v.z), h3 = __float2bfloat16(v.w);
    __nv_bfloat16 l0 = __float2bfloat16(v.x - __bfloat162float(h0));
    __nv_bfloat16 l1 = __float2bfloat16(v.y - __bfloat162float(h1));
    __nv_bfloat16 l2 = __float2bfloat16(v.z - __bfloat162float(h2));
    __nv_bfloat16 l3 = __float2bfloat16(v.w - __bfloat162float(h3));
    __nv_bfloat162 ph0; ph0.x = h0; ph0.y = h1;
    __nv_bfloat162 ph1; ph1.x = h2; ph1.y = h3;
    __nv_bfloat162 pl0; pl0.x = l0; pl0.y = l1;
    __nv_bfloat162 pl1; pl1.x = l2; pl1.y = l3;
    *reinterpret_cast<__nv_bfloat162*>(dh + off)     = ph0;
    *reinterpret_cast<__nv_bfloat162*>(dh + off + 2) = ph1;
    *reinterpret_cast<__nv_bfloat162*>(dl + off)     = pl0;
    *reinterpret_cast<__nv_bfloat162*>(dl + off + 2) = pl1;
}

// =======================================================================
// HMMA split-bf16 GEMM. CTA 128x128, 256 threads (8 warps 2x4),
// warp tile 64x32. K chunks of 32, 2 stages (80KB smem), <=128 regs
// -> 2 CTAs/SM to hide wave-transition prologue/epilogue bubbles.
// Rows 80B (proven conflict-free in R8).
// =======================================================================
#define G_LDS 80
#define G_MAT (128 * G_LDS)        // 10240
#define G_STG (4 * G_MAT)          // 40960
#define GEMM_SMEM (2 * G_STG)      // 81920

__global__ __launch_bounds__(256, 2) void gemm_tc(
    const __nv_bfloat16* __restrict__ Ah0, const __nv_bfloat16* __restrict__ Al0,
    const float* __restrict__ bq, const float* __restrict__ bk, const float* __restrict__ bv,
    float* __restrict__ outp, int qkv_mode)
{
    extern __shared__ char smem[];
    const uint32_t sb = s2u(smem);
    const int tid = threadIdx.x;
    const int wid = tid >> 5, lane = tid & 31;
    const int wm = wid & 1, wn = wid >> 1;

    const __nv_bfloat16 *Ah, *Al, *Bh, *Bl;
    const float* bias;
    __nv_bfloat16 *ohp = nullptr, *olp = nullptr;
    int n0, do_silu;
    if (qkv_mode) {
        int w = blockIdx.x >> 3;
        Bh = g_wh + (size_t)w * (DD * DD);
        Bl = g_wl + (size_t)w * (DD * DD);
        bias = (w == 0) ? bq : (w == 1) ? bk : bv;
        ohp = (w == 0) ? g_qh : (w == 1) ? g_kh : g_vh;
        olp = (w == 0) ? g_ql : (w == 1) ? g_kl : g_vl;
        do_silu = (w < 2);
        n0 = (blockIdx.x & 7) * 128;
        Ah = Ah0; Al = Al0;
    } else {
        Bh = g_wh + 3 * (size_t)(DD * DD);
        Bl = g_wl + 3 * (size_t)(DD * DD);
        bias = bq; do_silu = 0;
        n0 = blockIdx.x * 128;
        Ah = g_oh; Al = g_ol;
    }
    const int m0 = blockIdx.y * 128;

    float acc[4][4][4];
#pragma unroll
    for (int a = 0; a < 4; a++)
#pragma unroll
        for (int b = 0; b < 4; b++)
#pragma unroll
            for (int c = 0; c < 4; c++) acc[a][b][c] = 0.f;

    auto load_chunk = [&](int cc) {
        const int kc = cc * 32;
        const uint32_t st = sb + (uint32_t)(cc & 1) * G_STG;
#pragma unroll
        for (int i = 0; i < 2; i++) {
            int idx = tid + i * 256;      // 0..511
            int r = idx >> 2, g = idx & 3;
            uint32_t so = (uint32_t)(r * G_LDS + g * 16);
            size_t ea = (size_t)(m0 + r) * DD + kc + g * 8;
            size_t eb = (size_t)(n0 + r) * DD + kc + g * 8;
            cp16(st + 0 * G_MAT + so, Ah + ea);
            cp16(st + 1 * G_MAT + so, Al + ea);
            cp16(st + 2 * G_MAT + so, Bh + eb);
            cp16(st + 3 * G_MAT + so, Bl + eb);
        }
        asm volatile("cp.async.commit_group;" ::: "memory");
    };

    load_chunk(0);

    const int arow = wm * 64 + (lane & 15);
    const int acol = (lane >> 4) * 8;
    const int brow = wn * 32 + ((lane >> 4) << 3) + (lane & 7);
    const int bcol = ((lane >> 3) & 1) * 8;

    const int NK = 1024 / 32;   // 32 chunks
    for (int c = 0; c < NK; c++) {
        asm volatile("cp.async.wait_group 0;" ::: "memory");
        __syncthreads();
        if (c + 1 < NK) load_chunk(c + 1);   // overlaps compute(c), other buffer

        const uint32_t st  = sb + (uint32_t)(c & 1) * G_STG;
        const uint32_t aAh = st, aAl = st + G_MAT, aBh = st + 2 * G_MAT, aBl = st + 3 * G_MAT;

#pragma unroll
        for (int h = 0; h < 2; h++) {
            uint32_t bhf[2][4], blf[2][4];
#pragma unroll
            for (int p = 0; p < 2; p++) {
                uint32_t off = (uint32_t)((brow + p * 16) * G_LDS + (bcol + h * 16) * 2);
                ldm_x4(bhf[p], aBh + off);
                ldm_x4(blf[p], aBl + off);
            }
#pragma unroll
            for (int mt = 0; mt < 4; mt++) {
                uint32_t ah[4], al[4];
                uint32_t off = (uint32_t)((arow + mt * 16) * G_LDS + (acol + h * 16) * 2);
                ldm_x4(ah, aAh + off);
                ldm_x4(al, aAl + off);
#pragma unroll
                for (int nt = 0; nt < 4; nt++) {
                    const uint32_t* bh2 = &bhf[nt >> 1][(nt & 1) * 2];
                    const uint32_t* bl2 = &blf[nt >> 1][(nt & 1) * 2];
                    mma16816(acc[mt][nt], ah, bh2);
                    mma16816(acc[mt][nt], ah, bl2);
                    mma16816(acc[mt][nt], al, bh2);
                }
            }
        }
    }

    // ---- epilogue ----
    float bv2[4][2];
#pragma unroll
    for (int nt = 0; nt < 4; nt++) {
        int col = n0 + wn * 32 + nt * 8 + 2 * (lane & 3);
        bv2[nt][0] = bias[col];
        bv2[nt][1] = bias[col + 1];
    }
#pragma unroll
    for (int mt = 0; mt < 4; mt++) {
#pragma unroll
        for (int half = 0; half < 2; half++) {
            int m = m0 + wm * 64 + mt * 16 + (lane >> 2) + half * 8;
            int b = m >> 11, lpos = m & 2047;
#pragma unroll
            for (int nt = 0; nt < 4; nt++) {
                int col = n0 + wn * 32 + nt * 8 + 2 * (lane & 3);
                float v0 = acc[mt][nt][half * 2 + 0] + bv2[nt][0];
                float v1 = acc[mt][nt][half * 2 + 1] + bv2[nt][1];
                if (do_silu) {
                    v0 = v0 / (1.f + expf(-v0));
                    v1 = v1 / (1.f + expf(-v1));
                }
                if (qkv_mode) {
                    int hidx = col >> 6, i2 = col & 63;
                    size_t po = ((size_t)((b << 4) | hidx) * LL + lpos) * HD + i2;
                    *reinterpret_cast<uint32_t*>(ohp + po) = pk2(v0, v1);
                    *reinterpret_cast<uint32_t*>(olp + po) =
                        pk2(v0 - bfh(v0), v1 - bfh(v1));
                } else {
                    *reinterpret_cast<float2*>(outp + (size_t)m * DD + col) =
                        make_float2(v0, v1);
                }
            }
        }
    }
}

// =======================================================================
// Per-chunk state from split-bf16 k/v: kv[d][e], ksum[d]
// =======================================================================
__global__ __launch_bounds__(256) void chunk_state_kernel()
{
    extern __shared__ float sm[];
    float* ks  = sm;
    float* vsm = sm + 8192;

    int cid = blockIdx.x;
    size_t base = (size_t)(cid >> 4) * LL * HD + (size_t)(cid & 15) * CH * HD;
    int tid = threadIdx.x;

    const uint4* kh4 = reinterpret_cast<const uint4*>(g_kh + base);
    const uint4* kl4 = reinterpret_cast<const uint4*>(g_kl + base);
    const uint4* vh4 = reinterpret_cast<const uint4*>(g_vh + base);
    const uint4* vl4 = reinterpret_cast<const uint4*>(g_vl + base);
    for (int i4 = tid; i4 < 1024; i4 += 256) {
        uint4 h = kh4[i4], l = kl4[i4];
        uint4 hv = vh4[i4], lv = vl4[i4];
#pragma unroll
        for (int j = 0; j < 4; j++) {
            __nv_bfloat162 hh = reinterpret_cast<const __nv_bfloat162*>(&h)[j];
            __nv_bfloat162 ll = reinterpret_cast<const __nv_bfloat162*>(&l)[j];
            ks[i4 * 8 + j * 2]     = __bfloat162float(hh.x) + __bfloat162float(ll.x);
            ks[i4 * 8 + j * 2 + 1] = __bfloat162float(hh.y) + __bfloat162float(ll.y);
            __nv_bfloat162 hh2 = reinterpret_cast<const __nv_bfloat162*>(&hv)[j];
            __nv_bfloat162 ll2 = reinterpret_cast<const __nv_bfloat162*>(&lv)[j];
            vsm[i4 * 8 + j * 2]     = __bfloat162float(hh2.x) + __bfloat162float(ll2.x);
            vsm[i4 * 8 + j * 2 + 1] = __bfloat162float(hh2.y) + __bfloat162float(ll2.y);
        }
    }
    __syncthreads();

    int tx = tid & 15, ty = tid >> 4;
    int i0 = ty * 4, j0 = tx * 4;
    float c[4][4] = {};
#pragma unroll 4
    for (int t = 0; t < 128; t++) {
        float4 a = *reinterpret_cast<const float4*>(&ks[t * 64 + i0]);
        float4 bvv = *reinterpret_cast<const float4*>(&vsm[t * 64 + j0]);
        float av[4] = {a.x, a.y, a.z, a.w};
        float bw[4] = {bvv.x, bvv.y, bvv.z, bvv.w};
#pragma unroll
        for (int ii = 0; ii < 4; ii++)
#pragma unroll
            for (int jj = 0; jj < 4; jj++) c[ii][jj] += av[ii] * bw[jj];
    }
    float* Sp = g_S + (size_t)cid * 4096;
#pragma unroll
    for (int ii = 0; ii < 4; ii++) {
        float4 o4 = make_float4(c[ii][0], c[ii][1], c[ii][2], c[ii][3]);
        *reinterpret_cast<float4*>(&Sp[(i0 + ii) * 64 + j0]) = o4;
    }
    if (tid < 64) {
        float s = 0.f;
#pragma unroll 4
        for (int t = 0; t < 128; t++) s += ks[t * 64 + tid];
        g_z[(size_t)cid * 64 + tid] = s;
    }
}

// =======================================================================
// Parallel exclusive prefix over NC chunks
// =======================================================================
__global__ __launch_bounds__(256) void prefix2_kernel()
{
    const int PER = 4096 + 64;
    int idx = blockIdx.x * 256 + threadIdx.x;
    if (idx >= 64 * PER) return;
    int bh = idx / PER, rme = idx - bh * PER;
    if (rme < 4096) {
        float run = 0.f;
        size_t p = (size_t)bh * NC * 4096 + rme;
#pragma unroll
        for (int n = 0; n < NC; n++) {
            float t = g_S[p]; g_S[p] = run; run += t; p += 4096;
        }
    } else {
        int e = rme - 4096;
        float run = 0.f;
        size_t p = (size_t)bh * NC * 64 + e;
#pragma unroll
        for (int n = 0; n < NC; n++) {
            float t = g_z[p]; g_z[p] = run; run += t; p += 64;
        }
    }
}

// =======================================================================
// Intra-chunk attention, tensor cores, 2 CTAs/SM, causal-block skipping:
// fully-masked score tiles (j_min > row_max) never issue MMAs (acc stays
// zero -> downstream masking/split code unchanged and exact).
// =======================================================================
#define OFF_QH 0
#define OFF_QL 16384
#define OFF_KH 32768
#define OFF_KL 49152
#define OFF_VH 65536
#define OFF_VL 81920
#define OFF_SH 98304
#define OFF_SL 106496
#define OFF_Z  114688
#define OFF_DEN 114944
#define OFF_NUM OFF_KH
#define INTRA2_SMEM 115456

__global__ __launch_bounds__(256, 2) void intra2_kernel()
{
    extern __shared__ char smc[];
    float* numb = (float*)(smc + OFF_NUM);
    float* zs   = (float*)(smc + OFF_Z);
    float* den  = (float*)(smc + OFF_DEN);
    const uint32_t sb = s2u(smc);

    const int cid = blockIdx.x;
    const int bh = cid >> 4, nch = cid & 15;
    const size_t base = ((size_t)bh * LL + (size_t)nch * CH) * HD;
    const int tid = threadIdx.x, wid = tid >> 5, lane = tid & 31;
    const int wm = wid & 3, wn = wid >> 2;

    const uint32_t sQH = sb + OFF_QH, sQL = sb + OFF_QL;
    const uint32_t sKH = sb + OFF_KH, sKL = sb + OFF_KL;
    const uint32_t sVH = sb + OFF_VH, sVL = sb + OFF_VL;
    const uint32_t sSH = sb + OFF_SH, sSL = sb + OFF_SL;

    // ---- cp.async loads of pre-split q/k/v (swizzled 128B rows) ----
#pragma unroll
    for (int i = 0; i < 4; i++) {
        int idx = tid + i * 256;
        int r = idx >> 3, g = idx & 7;
        uint32_t so = (uint32_t)(r * 128 + ((g ^ (r & 7)) << 4));
        size_t src = base + (size_t)r * HD + g * 8;
        cp16(sQH + so, g_qh + src);
        cp16(sQL + so, g_ql + src);
        cp16(sKH + so, g_kh + src);
        cp16(sKL + so, g_kl + src);
        cp16(sVH + so, g_vh + src);
        cp16(sVL + so, g_vl + src);
    }
    asm volatile("cp.async.commit_group;" ::: "memory");

    // ---- S convert+split; z; den init ----
    for (int idx = tid; idx < 4096; idx += 256) {
        float sv = g_S[(size_t)cid * 4096 + idx];
        float sh = bfh(sv);
        int d = idx >> 6, e = idx & 63;
        uint32_t off = isw(d, e * 2);
        *(__nv_bfloat16*)(smc + OFF_SH + off) = __float2bfloat16(sv);
        *(__nv_bfloat16*)(smc + OFF_SL + off) = __float2bfloat16(sv - sh);
    }
    if (tid < 64) zs[tid] = g_z[(size_t)cid * 64 + tid];
    if (tid < 128) den[tid] = 0.f;
    asm volatile("cp.async.wait_group 0;" ::: "memory");
    __syncthreads();

    const int r = lane >> 2, c2 = 2 * (lane & 3);
    const int arow = wm * 32 + (lane & 15);
    const int acol = (lane >> 4) * 8;
    const int brow = ((lane >> 4) << 3) + (lane & 7);
    const int bcol = ((lane >> 3) & 1) * 8;
    const int tkr = (lane & 7) | (((lane >> 3) & 1) << 3);
    const int tnc = (lane >> 4) << 3;
    const int rmax = wm * 32 + 31;   // max row index this warp covers

    // ---- phase 1: scores = q k^T  (skip fully-masked tiles) ----
    float acc[2][8][4];
#pragma unroll
    for (int a = 0; a < 2; a++)
#pragma unroll
        for (int b = 0; b < 8; b++)
#pragma unroll
            for (int c = 0; c < 4; c++) acc[a][b][c] = 0.f;

    if (wn * 64 <= rmax) {   // warp has at least one live score tile
#pragma unroll
        for (int g = 0; g < 4; g++) {
            uint32_t qaf[2][4], qbf[2][4];
#pragma unroll
            for (int mt = 0; mt < 2; mt++) {
                uint32_t off = isw(arow + mt * 16, (acol + g * 16) * 2);
                ldm_x4(qaf[mt], sQH + off);
                ldm_x4(qbf[mt], sQL + off);
            }
            uint32_t kaf[4][4], kbf2[4][4];
#pragma unroll
            for (int p = 0; p < 4; p++) {
                if (wn * 64 + p * 16 <= rmax) {
                    uint32_t off = isw(wn * 64 + brow + p * 16, (bcol + g * 16) * 2);
                    ldm_x4(kaf[p], sKH + off);
                    ldm_x4(kbf2[p], sKL + off);
                }
            }
#pragma unroll
            for (int mt = 0; mt < 2; mt++)
#pragma unroll
                for (int nt = 0; nt < 8; nt++) {
                    if (wn * 64 + nt * 8 <= wm * 32 + mt * 16 + 15) {
                        const uint32_t* b1 = &kaf[nt >> 1][(nt & 1) * 2];
                        const uint32_t* b2 = &kbf2[nt >> 1][(nt & 1) * 2];
                        mma16816(acc[mt][nt], qaf[mt], b1);
                        mma16816(acc[mt][nt], qaf[mt], b2);
                        mma16816(acc[mt][nt], qbf[mt], b1);
                    }
                }
        }
    }

    // ---- mask + rowsum (den) + split scores to A-fragments ----
    uint32_t shf[2][4][4], slf[2][4][4];
#pragma unroll
    for (int mt = 0; mt < 2; mt++) {
        float rs0 = 0.f, rs1 = 0.f;
        int i0 = wm * 32 + mt * 16 + r, i1 = i0 + 8;
#pragma unroll
        for (int nt = 0; nt < 8; nt++) {
            int j0 = wn * 64 + nt * 8 + c2;
            float s00 = (j0     <= i0) ? acc[mt][nt][0] : 0.f;
            float s01 = (j0 + 1 <= i0) ? acc[mt][nt][1] : 0.f;
            float s10 = (j0     <= i1) ? acc[mt][nt][2] : 0.f;
            float s11 = (j0 + 1 <= i1) ? acc[mt][nt][3] : 0.f;
            rs0 += s00 + s01;
            rs1 += s10 + s11;
            int g = nt >> 1, hh = (nt & 1) * 2;
            shf[mt][g][hh]     = pk2(s00, s01);
            shf[mt][g][hh + 1] = pk2(s10, s11);
            slf[mt][g][hh]     = pk2(s00 - bfh(s00), s01 - bfh(s01));
            slf[mt][g][hh + 1] = pk2(s10 - bfh(s10), s11 - bfh(s11));
        }
        rs0 += __shfl_xor_sync(0xffffffffu, rs0, 1);
        rs0 += __shfl_xor_sync(0xffffffffu, rs0, 2);
        rs1 += __shfl_xor_sync(0xffffffffu, rs1, 1);
        rs1 += __shfl_xor_sync(0xffffffffu, rs1, 2);
        if ((lane & 3) == 0 && wn * 64 <= rmax) {
            atomicAdd(&den[i0], rs0);
            atomicAdd(&den[i1], rs1);
        }
    }

    // ---- den += q . z ----
    if (tid < 128) {
        float s = 0.f;
        int tmask = tid & 7;
#pragma unroll 8
        for (int d = 0; d < 64; d++) {
            uint32_t off = (uint32_t)(tid * 128 + ((((d >> 3) ^ tmask) << 4) | ((d & 7) * 2)));
            float qv = __bfloat162float(*(__nv_bfloat16*)(smc + OFF_QH + off)) +
                       __bfloat162float(*(__nv_bfloat16*)(smc + OFF_QL + off));
            s += qv * zs[d];
        }
        atomicAdd(&den[tid], s);
    }

    // ---- phase 2 in two output-column halves ----
    const int bidx = bh >> 4, hd = bh & 15;
#pragma unroll 1
    for (int eh = 0; eh < 2; eh++) {
        float acc2[2][4][4];
#pragma unroll
        for (int a = 0; a < 2; a++)
#pragma unroll
            for (int b = 0; b < 4; b++)
#pragma unroll
                for (int c = 0; c < 4; c++) acc2[a][b][c] = 0.f;

        // scores @ v (transposed B), skip zero-score K groups
#pragma unroll
        for (int g = 0; g < 4; g++) {
            if (wn * 64 + g * 16 <= rmax) {
                uint32_t vaf[2][4], vbf2[2][4];
#pragma unroll
                for (int p2 = 0; p2 < 2; p2++) {
                    int pg = eh * 2 + p2;
                    uint32_t off = isw(wn * 64 + g * 16 + tkr, (pg * 16 + tnc) * 2);
                    ldm_x4_t(vaf[p2], sVH + off);
                    ldm_x4_t(vbf2[p2], sVL + off);
                }
#pragma unroll
                for (int mt = 0; mt < 2; mt++) {
                    if (wn * 64 + g * 16 <= wm * 32 + mt * 16 + 15) {
#pragma unroll
                        for (int nt = 0; nt < 4; nt++) {
                            const uint32_t* b1 = &vaf[nt >> 1][(nt & 1) * 2];
                            const uint32_t* b2 = &vbf2[nt >> 1][(nt & 1) * 2];
                            mma16816(acc2[mt][nt], shf[mt][g], b1);
                            mma16816(acc2[mt][nt], shf[mt][g], b2);
                            mma16816(acc2[mt][nt], slf[mt][g], b1);
                        }
                    }
                }
            }
        }
        // q @ S (transposed B), this warp's wn d-half
#pragma unroll
        for (int g2 = 0; g2 < 2; g2++) {
            int gd = wn * 2 + g2;
            uint32_t qaf[2][4], qbf[2][4];
#pragma unroll
            for (int mt = 0; mt < 2; mt++) {
                uint32_t off = isw(arow + mt * 16, (acol + gd * 16) * 2);
                ldm_x4(qaf[mt], sQH + off);
                ldm_x4(qbf[mt], sQL + off);
            }
            uint32_t Saf[2][4], Sbf2[2][4];
#pragma unroll
            for (int p2 = 0; p2 < 2; p2++) {
                int pg = eh * 2 + p2;
                uint32_t off = isw(gd * 16 + tkr, (pg * 16 + tnc) * 2);
                ldm_x4_t(Saf[p2], sSH + off);
                ldm_x4_t(Sbf2[p2], sSL + off);
            }
#pragma unroll
            for (int mt = 0; mt < 2; mt++)
#pragma unroll
                for (int nt = 0; nt < 4; nt++) {
                    const uint32_t* b1 = &Saf[nt >> 1][(nt & 1) * 2];
                    const uint32_t* b2 = &Sbf2[nt >> 1][(nt & 1) * 2];
                    mma16816(acc2[mt][nt], qaf[mt], b1);
                    mma16816(acc2[mt][nt], qaf[mt], b2);
                    mma16816(acc2[mt][nt], qbf[mt], b1);
                }
        }

        // combine wn partials via numb (overlays dead K region), store
        __syncthreads();
        if (wn == 0) {
#pragma unroll
            for (int mt = 0; mt < 2; mt++) {
                int i0 = wm * 32 + mt * 16 + r;
#pragma unroll
                for (int nt = 0; nt < 4; nt++) {
                    int cl = nt * 8 + c2;
                    numb[i0 * 32 + cl]           = acc2[mt][nt][0];
                    numb[i0 * 32 + cl + 1]       = acc2[mt][nt][1];
                    numb[(i0 + 8) * 32 + cl]     = acc2[mt][nt][2];
                    numb[(i0 + 8) * 32 + cl + 1] = acc2[mt][nt][3];
                }
            }
        }
        __syncthreads();
        if (wn == 1) {
#pragma unroll
            for (int mt = 0; mt < 2; mt++) {
                int i0 = wm * 32 + mt * 16 + r;
                float dr0 = 1.f / fmaxf(den[i0], 1e-3f);
                float dr1 = 1.f / fmaxf(den[i0 + 8], 1e-3f);
                int l0 = nch * CH + i0;
                size_t ob0 = ((size_t)bidx * LL + l0) * DD + hd * 64 + eh * 32;
                size_t ob1 = ((size_t)bidx * LL + l0 + 8) * DD + hd * 64 + eh * 32;
#pragma unroll
                for (int nt = 0; nt < 4; nt++) {
                    int cl = nt * 8 + c2;
                    float o00 = (acc2[mt][nt][0] + numb[i0 * 32 + cl])           * dr0;
                    float o01 = (acc2[mt][nt][1] + numb[i0 * 32 + cl + 1])       * dr0;
                    float o10 = (acc2[mt][nt][2] + numb[(i0 + 8) * 32 + cl])     * dr1;
                    float o11 = (acc2[mt][nt][3] + numb[(i0 + 8) * 32 + cl + 1]) * dr1;
                    *reinterpret_cast<uint32_t*>(g_oh + ob0 + cl) = pk2(o00, o01);
                    *reinterpret_cast<uint32_t*>(g_oh + ob1 + cl) = pk2(o10, o11);
                    *reinterpret_cast<uint32_t*>(g_ol + ob0 + cl) =
                        pk2(o00 - bfh(o00), o01 - bfh(o01));
                    *reinterpret_cast<uint32_t*>(g_ol + ob1 + cl) =
                        pk2(o10 - bfh(o10), o11 - bfh(o11));
                }
            }
        }
        __syncthreads();
    }
}

// =======================================================================
extern "C" void kernel_launch(void* const* d_in, const int* in_sizes, int n_in,
                              void* d_out, int out_size)
{
    const float* x  = (const float*)d_in[0];
    const float* Wq = (const float*)d_in[1];
    const float* bq = (const float*)d_in[2];
    const float* Wk = (const float*)d_in[3];
    const float* bk = (const float*)d_in[4];
    const float* Wv = (const float*)d_in[5];
    const float* bv = (const float*)d_in[6];
    const float* Wo = (const float*)d_in[7];
    const float* bo = (const float*)d_in[8];
    float* out = (float*)d_out;

    cudaFuncSetAttribute(chunk_state_kernel, cudaFuncAttributeMaxDynamicSharedMemorySize, 65536);
    cudaFuncSetAttribute(intra2_kernel, cudaFuncAttributeMaxDynamicSharedMemorySize, INTRA2_SMEM);
    cudaFuncSetAttribute(gemm_tc, cudaFuncAttributeMaxDynamicSharedMemorySize, GEMM_SMEM);

    __nv_bfloat16 *xh, *xl;
    cudaGetSymbolAddress((void**)&xh, g_xh);
    cudaGetSymbolAddress((void**)&xl, g_xl);

    // 0) split fp32 inputs (x + 4 weights) into bf16 hi/lo pairs
    split_all_kernel<<<(BB*LL*DD + 4*DD*DD) / 1024, 256>>>(x, Wq, Wk, Wv, Wo);

    // 1) fused QKV projection (2 CTAs/SM)
    gemm_tc<<<dim3(24, 64), 256, GEMM_SMEM>>>(xh, xl, bq, bk, bv, nullptr, 1);

    // 2) per-chunk kv state + k sums
    chunk_state_kernel<<<BB * HH * NC, 256, 65536>>>();

    // 3) exclusive prefix over chunks
    prefix2_kernel<<<(64 * (4096 + 64) + 255) / 256, 256>>>();

    // 4) intra-chunk attention (2 CTAs/SM, causal-skip)
    intra2_kernel<<<BB * HH * NC, 256, INTRA2_SMEM>>>();

    // 5) output projection
    gemm_tc<<<dim3(8, 64), 256, GEMM_SMEM>>>(nullptr, nullptr, bo, bo, bo, out, 0);
}

// round 14
// speedup vs baseline: 3.2166x; 1.0621x over previous
#include <cuda_runtime.h>
#include <cuda_bf16.h>
#include <math.h>
#include <stdint.h>

// Problem constants
#define BB   4
#define HH   16
#define LL   2048
#define DD   1024
#define HD   64
#define CH   128
#define NC   16

// ---------------- scratch (device globals) ----------------
__device__ float g_S[BB*HH*NC*HD*HD];        // raw per-chunk states (fp32)
__device__ float g_z[BB*HH*NC*HD];
__device__ __nv_bfloat16 g_Sph[BB*HH*NC*HD*HD];  // exclusive-prefix S, split
__device__ __nv_bfloat16 g_Spl[BB*HH*NC*HD*HD];
__device__ __nv_bfloat16 g_xh[BB*LL*DD];
__device__ __nv_bfloat16 g_xl[BB*LL*DD];
__device__ __nv_bfloat16 g_wh[4*DD*DD];
__device__ __nv_bfloat16 g_wl[4*DD*DD];
__device__ __nv_bfloat16 g_qh[BB*HH*LL*HD];
__device__ __nv_bfloat16 g_ql[BB*HH*LL*HD];
__device__ __nv_bfloat16 g_kh[BB*HH*LL*HD];
__device__ __nv_bfloat16 g_kl[BB*HH*LL*HD];
__device__ __nv_bfloat16 g_vh[BB*HH*LL*HD];
__device__ __nv_bfloat16 g_vl[BB*HH*LL*HD];
__device__ __nv_bfloat16 g_oh[BB*LL*DD];
__device__ __nv_bfloat16 g_ol[BB*LL*DD];

// ---------------- PTX helpers ----------------
__device__ __forceinline__ uint32_t s2u(const void* p) {
    uint32_t a;
    asm("{ .reg .u64 t; cvta.to.shared.u64 t, %1; cvt.u32.u64 %0, t; }" : "=r"(a) : "l"(p));
    return a;
}
__device__ __forceinline__ void cp16(uint32_t s, const void* g) {
    asm volatile("cp.async.cg.shared.global [%0], [%1], 16;" :: "r"(s), "l"(g) : "memory");
}
__device__ __forceinline__ void ldm_x4(uint32_t* r, uint32_t addr) {
    asm volatile("ldmatrix.sync.aligned.m8n8.x4.shared.b16 {%0,%1,%2,%3}, [%4];"
        : "=r"(r[0]), "=r"(r[1]), "=r"(r[2]), "=r"(r[3]) : "r"(addr));
}
__device__ __forceinline__ void ldm_x4_t(uint32_t* r, uint32_t addr) {
    asm volatile("ldmatrix.sync.aligned.m8n8.x4.trans.shared.b16 {%0,%1,%2,%3}, [%4];"
        : "=r"(r[0]), "=r"(r[1]), "=r"(r[2]), "=r"(r[3]) : "r"(addr));
}
__device__ __forceinline__ void mma16816(float* d, const uint32_t* a, const uint32_t* b) {
    asm volatile("mma.sync.aligned.m16n8k16.row.col.f32.bf16.bf16.f32 "
        "{%0,%1,%2,%3}, {%4,%5,%6,%7}, {%8,%9}, {%0,%1,%2,%3};"
        : "+f"(d[0]), "+f"(d[1]), "+f"(d[2]), "+f"(d[3])
        : "r"(a[0]), "r"(a[1]), "r"(a[2]), "r"(a[3]), "r"(b[0]), "r"(b[1]));
}
__device__ __forceinline__ uint32_t pk2(float lo, float hi) {
    uint32_t r;
    asm("cvt.rn.bf16x2.f32 %0, %1, %2;" : "=r"(r) : "f"(hi), "f"(lo));
    return r;
}
__device__ __forceinline__ float bfh(float x) {
    return __bfloat162float(__float2bfloat16(x));
}
// 128B-row XOR swizzle
__device__ __forceinline__ uint32_t isw(int row, int colb) {
    return (uint32_t)(row * 128 + ((((colb >> 4) ^ (row & 7)) << 4) | (colb & 15)));
}

// ---------------- split fp32 -> bf16 hi + bf16 lo (x + all 4 weights) ----
__global__ __launch_bounds__(256) void split_all_kernel(
    const float* __restrict__ x,
    const float* __restrict__ Wq, const float* __restrict__ Wk,
    const float* __restrict__ Wv, const float* __restrict__ Wo)
{
    const int XN = BB * LL * DD;
    long long i = ((long long)blockIdx.x * 256 + threadIdx.x) * 4;
    const float* src;
    __nv_bfloat16 *dh, *dl;
    long long off;
    if (i < XN) {
        src = x; dh = g_xh; dl = g_xl; off = i;
    } else {
        long long j = i - XN;
        int w = (int)(j >> 20);
        off = j & ((1 << 20) - 1);
        src = (w == 0) ? Wq : (w == 1) ? Wk : (w == 2) ? Wv : Wo;
        dh = g_wh + ((long long)w << 20);
        dl = g_wl + ((long long)w << 20);
    }
    float4 v = *reinterpret_cast<const float4*>(src + off);
    __nv_bfloat16 h0 = __float2bfloat16(v.x), h1 = __float2bfloat16(v.y);
    __nv_bfloat16 h2 = __float2bfloat16(v.z), h3 = __float2bfloat16(v.w);
    __nv_bfloat16 l0 = __float2bfloat16(v.x - __bfloat162float(h0));
    __nv_bfloat16 l1 = __float2bfloat16(v.y - __bfloat162float(h1));
    __nv_bfloat16 l2 = __float2bfloat16(v.z - __bfloat162float(h2));
    __nv_bfloat16 l3 = __float2bfloat16(v.w - __bfloat162float(h3));
    __nv_bfloat162 ph0; ph0.x = h0; ph0.y = h1;
    __nv_bfloat162 ph1; ph1.x = h2; ph1.y = h3;
    __nv_bfloat162 pl0; pl0.x = l0; pl0.y = l1;
    __nv_bfloat162 pl1; pl1.x = l2; pl1.y = l3;
    *reinterpret_cast<__nv_bfloat162*>(dh + off)     = ph0;
    *reinterpret_cast<__nv_bfloat162*>(dh + off + 2) = ph1;
    *reinterpret_cast<__nv_bfloat162*>(dl + off)     = pl0;
    *reinterpret_cast<__nv_bfloat162*>(dl + off + 2) = pl1;
}

// =======================================================================
// HMMA split-bf16 GEMM (unchanged from passing R13): 256 thr, 2 CTAs/SM
// =======================================================================
#define G_LDS 80
#define G_MAT (128 * G_LDS)
#define G_STG (4 * G_MAT)
#define GEMM_SMEM (2 * G_STG)      // 81920

__global__ __launch_bounds__(256, 2) void gemm_tc(
    const __nv_bfloat16* __restrict__ Ah0, const __nv_bfloat16* __restrict__ Al0,
    const float* __restrict__ bq, const float* __restrict__ bk, const float* __restrict__ bv,
    float* __restrict__ outp, int qkv_mode)
{
    extern __shared__ char smem[];
    const uint32_t sb = s2u(smem);
    const int tid = threadIdx.x;
    const int wid = tid >> 5, lane = tid & 31;
    const int wm = wid & 1, wn = wid >> 1;

    const __nv_bfloat16 *Ah, *Al, *Bh, *Bl;
    const float* bias;
    __nv_bfloat16 *ohp = nullptr, *olp = nullptr;
    int n0, do_silu;
    if (qkv_mode) {
        int w = blockIdx.x >> 3;
        Bh = g_wh + (size_t)w * (DD * DD);
        Bl = g_wl + (size_t)w * (DD * DD);
        bias = (w == 0) ? bq : (w == 1) ? bk : bv;
        ohp = (w == 0) ? g_qh : (w == 1) ? g_kh : g_vh;
        olp = (w == 0) ? g_ql : (w == 1) ? g_kl : g_vl;
        do_silu = (w < 2);
        n0 = (blockIdx.x & 7) * 128;
        Ah = Ah0; Al = Al0;
    } else {
        Bh = g_wh + 3 * (size_t)(DD * DD);
        Bl = g_wl + 3 * (size_t)(DD * DD);
        bias = bq; do_silu = 0;
        n0 = blockIdx.x * 128;
        Ah = g_oh; Al = g_ol;
    }
    const int m0 = blockIdx.y * 128;

    float acc[4][4][4];
#pragma unroll
    for (int a = 0; a < 4; a++)
#pragma unroll
        for (int b = 0; b < 4; b++)
#pragma unroll
            for (int c = 0; c < 4; c++) acc[a][b][c] = 0.f;

    auto load_chunk = [&](int cc) {
        const int kc = cc * 32;
        const uint32_t st = sb + (uint32_t)(cc & 1) * G_STG;
#pragma unroll
        for (int i = 0; i < 2; i++) {
            int idx = tid + i * 256;
            int r = idx >> 2, g = idx & 3;
            uint32_t so = (uint32_t)(r * G_LDS + g * 16);
            size_t ea = (size_t)(m0 + r) * DD + kc + g * 8;
            size_t eb = (size_t)(n0 + r) * DD + kc + g * 8;
            cp16(st + 0 * G_MAT + so, Ah + ea);
            cp16(st + 1 * G_MAT + so, Al + ea);
            cp16(st + 2 * G_MAT + so, Bh + eb);
            cp16(st + 3 * G_MAT + so, Bl + eb);
        }
        asm volatile("cp.async.commit_group;" ::: "memory");
    };

    load_chunk(0);

    const int arow = wm * 64 + (lane & 15);
    const int acol = (lane >> 4) * 8;
    const int brow = wn * 32 + ((lane >> 4) << 3) + (lane & 7);
    const int bcol = ((lane >> 3) & 1) * 8;

    const int NK = 1024 / 32;
    for (int c = 0; c < NK; c++) {
        asm volatile("cp.async.wait_group 0;" ::: "memory");
        __syncthreads();
        if (c + 1 < NK) load_chunk(c + 1);

        const uint32_t st  = sb + (uint32_t)(c & 1) * G_STG;
        const uint32_t aAh = st, aAl = st + G_MAT, aBh = st + 2 * G_MAT, aBl = st + 3 * G_MAT;

#pragma unroll
        for (int h = 0; h < 2; h++) {
            uint32_t bhf[2][4], blf[2][4];
#pragma unroll
            for (int p = 0; p < 2; p++) {
                uint32_t off = (uint32_t)((brow + p * 16) * G_LDS + (bcol + h * 16) * 2);
                ldm_x4(bhf[p], aBh + off);
                ldm_x4(blf[p], aBl + off);
            }
#pragma unroll
            for (int mt = 0; mt < 4; mt++) {
                uint32_t ah[4], al[4];
                uint32_t off = (uint32_t)((arow + mt * 16) * G_LDS + (acol + h * 16) * 2);
                ldm_x4(ah, aAh + off);
                ldm_x4(al, aAl + off);
#pragma unroll
                for (int nt = 0; nt < 4; nt++) {
                    const uint32_t* bh2 = &bhf[nt >> 1][(nt & 1) * 2];
                    const uint32_t* bl2 = &blf[nt >> 1][(nt & 1) * 2];
                    mma16816(acc[mt][nt], ah, bh2);
                    mma16816(acc[mt][nt], ah, bl2);
                    mma16816(acc[mt][nt], al, bh2);
                }
            }
        }
    }

    float bv2[4][2];
#pragma unroll
    for (int nt = 0; nt < 4; nt++) {
        int col = n0 + wn * 32 + nt * 8 + 2 * (lane & 3);
        bv2[nt][0] = bias[col];
        bv2[nt][1] = bias[col + 1];
    }
#pragma unroll
    for (int mt = 0; mt < 4; mt++) {
#pragma unroll
        for (int half = 0; half < 2; half++) {
            int m = m0 + wm * 64 + mt * 16 + (lane >> 2) + half * 8;
            int b = m >> 11, lpos = m & 2047;
#pragma unroll
            for (int nt = 0; nt < 4; nt++) {
                int col = n0 + wn * 32 + nt * 8 + 2 * (lane & 3);
                float v0 = acc[mt][nt][half * 2 + 0] + bv2[nt][0];
                float v1 = acc[mt][nt][half * 2 + 1] + bv2[nt][1];
                if (do_silu) {
                    v0 = v0 / (1.f + expf(-v0));
                    v1 = v1 / (1.f + expf(-v1));
                }
                if (qkv_mode) {
                    int hidx = col >> 6, i2 = col & 63;
                    size_t po = ((size_t)((b << 4) | hidx) * LL + lpos) * HD + i2;
                    *reinterpret_cast<uint32_t*>(ohp + po) = pk2(v0, v1);
                    *reinterpret_cast<uint32_t*>(olp + po) =
                        pk2(v0 - bfh(v0), v1 - bfh(v1));
                } else {
                    *reinterpret_cast<float2*>(outp + (size_t)m * DD + col) =
                        make_float2(v0, v1);
                }
            }
        }
    }
}

// =======================================================================
// Per-chunk state on tensor cores: C[d][e] = sum_t k[t][d] v[t][e].
// A = k^T via trans-A ldmatrix (lane: t=(L&7)|((L>>4)<<3), d=((L>>3)&1)*8),
// B = v via proven trans-B map. Split-bf16 3-term. smem 64KB.
// =======================================================================
#define CS_KH 0
#define CS_KL 16384
#define CS_VH 32768
#define CS_VL 49152
#define CS_SMEM 65536

__global__ __launch_bounds__(256, 3) void chunk_state_kernel()
{
    extern __shared__ char smc[];
    const uint32_t sb = s2u(smc);
    const int cid = blockIdx.x;
    const size_t base = (size_t)(cid >> 4) * LL * HD + (size_t)(cid & 15) * CH * HD;
    const int tid = threadIdx.x, wid = tid >> 5, lane = tid & 31;
    const int wm = wid & 3, wn = wid >> 2;

    // load k/v split-bf16 into swizzled smem
#pragma unroll
    for (int i = 0; i < 4; i++) {
        int idx = tid + i * 256;        // 0..1023
        int r = idx >> 3, g = idx & 7;
        uint32_t so = (uint32_t)(r * 128 + ((g ^ (r & 7)) << 4));
        size_t src = base + (size_t)r * HD + g * 8;
        cp16(sb + CS_KH + so, g_kh + src);
        cp16(sb + CS_KL + so, g_kl + src);
        cp16(sb + CS_VH + so, g_vh + src);
        cp16(sb + CS_VL + so, g_vl + src);
    }
    asm volatile("cp.async.commit_group;" ::: "memory");
    asm volatile("cp.async.wait_group 0;" ::: "memory");
    __syncthreads();

    // trans-A lane map (derived from A-fragment tile order m0k0,m1k0,m0k1,m1k1)
    const int kra = (lane & 7) | ((lane >> 4) << 3);
    const int dca = ((lane >> 3) & 1) * 8;
    // trans-B lane map (proven)
    const int tkr = (lane & 7) | (((lane >> 3) & 1) << 3);
    const int tnc = (lane >> 4) << 3;

    float acc[4][4];
#pragma unroll
    for (int a = 0; a < 4; a++)
#pragma unroll
        for (int b = 0; b < 4; b++) acc[a][b] = 0.f;

#pragma unroll
    for (int g = 0; g < 8; g++) {       // k16 steps over t=128
        uint32_t kah[4], kal[4];
        uint32_t offA = isw(g * 16 + kra, (wm * 16 + dca) * 2);
        ldm_x4_t(kah, sb + CS_KH + offA);
        ldm_x4_t(kal, sb + CS_KL + offA);
        uint32_t vbh[2][4], vbl[2][4];
#pragma unroll
        for (int p = 0; p < 2; p++) {
            uint32_t offB = isw(g * 16 + tkr, (wn * 32 + p * 16 + tnc) * 2);
            ldm_x4_t(vbh[p], sb + CS_VH + offB);
            ldm_x4_t(vbl[p], sb + CS_VL + offB);
        }
#pragma unroll
        for (int nt = 0; nt < 4; nt++) {
            const uint32_t* b1 = &vbh[nt >> 1][(nt & 1) * 2];
            const uint32_t* b2 = &vbl[nt >> 1][(nt & 1) * 2];
            mma16816(acc[nt], kah, b1);
            mma16816(acc[nt], kah, b2);
            mma16816(acc[nt], kal, b1);
        }
    }

    // store fp32 S
    float* Sp = g_S + (size_t)cid * 4096;
    const int r = lane >> 2, c2 = 2 * (lane & 3);
#pragma unroll
    for (int nt = 0; nt < 4; nt++) {
        int e = wn * 32 + nt * 8 + c2;
        int d0 = wm * 16 + r;
        Sp[d0 * 64 + e]           = acc[nt][0];
        Sp[d0 * 64 + e + 1]       = acc[nt][1];
        Sp[(d0 + 8) * 64 + e]     = acc[nt][2];
        Sp[(d0 + 8) * 64 + e + 1] = acc[nt][3];
    }

    // k_sum
    if (tid < 64) {
        float s = 0.f;
        int d2 = tid * 2;
#pragma unroll 8
        for (int t = 0; t < 128; t++) {
            uint32_t off = isw(t, d2);
            s += __bfloat162float(*(__nv_bfloat16*)(smc + CS_KH + off)) +
                 __bfloat162float(*(__nv_bfloat16*)(smc + CS_KL + off));
        }
        g_z[(size_t)cid * 64 + tid] = s;
    }
}

// =======================================================================
// Parallel exclusive prefix; emits split-bf16 S directly (no fp32 writeback)
// =======================================================================
__global__ __launch_bounds__(256) void prefix2_kernel()
{
    const int PER = 4096 + 64;
    int idx = blockIdx.x * 256 + threadIdx.x;
    if (idx >= 64 * PER) return;
    int bh = idx / PER, rme = idx - bh * PER;
    if (rme < 4096) {
        float run = 0.f;
        size_t p = (size_t)bh * NC * 4096 + rme;
#pragma unroll
        for (int n = 0; n < NC; n++) {
            float t = g_S[p];
            g_Sph[p] = __float2bfloat16(run);
            g_Spl[p] = __float2bfloat16(run - bfh(run));
            run += t; p += 4096;
        }
    } else {
        int e = rme - 4096;
        float run = 0.f;
        size_t p = (size_t)bh * NC * 64 + e;
#pragma unroll
        for (int n = 0; n < NC; n++) {
            float t = g_z[p]; g_z[p] = run; run += t; p += 64;
        }
    }
}

// =======================================================================
// Intra-chunk attention (2 CTAs/SM, causal-skip); S arrives pre-split via
// cp.async (no scalar convert pass).
// =======================================================================
#define OFF_QH 0
#define OFF_QL 16384
#define OFF_KH 32768
#define OFF_KL 49152
#define OFF_VH 65536
#define OFF_VL 81920
#define OFF_SH 98304
#define OFF_SL 106496
#define OFF_Z  114688
#define OFF_DEN 114944
#define OFF_NUM OFF_KH
#define INTRA2_SMEM 115456

__global__ __launch_bounds__(256, 2) void intra2_kernel()
{
    extern __shared__ char smc[];
    float* numb = (float*)(smc + OFF_NUM);
    float* zs   = (float*)(smc + OFF_Z);
    float* den  = (float*)(smc + OFF_DEN);
    const uint32_t sb = s2u(smc);

    const int cid = blockIdx.x;
    const int bh = cid >> 4, nch = cid & 15;
    const size_t base = ((size_t)bh * LL + (size_t)nch * CH) * HD;
    const int tid = threadIdx.x, wid = tid >> 5, lane = tid & 31;
    const int wm = wid & 3, wn = wid >> 2;

    const uint32_t sQH = sb + OFF_QH, sQL = sb + OFF_QL;
    const uint32_t sKH = sb + OFF_KH, sKL = sb + OFF_KL;
    const uint32_t sVH = sb + OFF_VH, sVL = sb + OFF_VL;
    const uint32_t sSH = sb + OFF_SH, sSL = sb + OFF_SL;

    // ---- cp.async loads: q/k/v (128 rows) + S (64 rows), all swizzled ----
#pragma unroll
    for (int i = 0; i < 4; i++) {
        int idx = tid + i * 256;
        int r = idx >> 3, g = idx & 7;
        uint32_t so = (uint32_t)(r * 128 + ((g ^ (r & 7)) << 4));
        size_t src = base + (size_t)r * HD + g * 8;
        cp16(sQH + so, g_qh + src);
        cp16(sQL + so, g_ql + src);
        cp16(sKH + so, g_kh + src);
        cp16(sKL + so, g_kl + src);
        cp16(sVH + so, g_vh + src);
        cp16(sVL + so, g_vl + src);
    }
#pragma unroll
    for (int i = 0; i < 2; i++) {
        int idx = tid + i * 256;        // 0..511 = 64 rows x 8 groups
        int d = idx >> 3, g = idx & 7;
        uint32_t so = (uint32_t)(d * 128 + ((g ^ (d & 7)) << 4));
        size_t src = (size_t)cid * 4096 + (size_t)d * 64 + g * 8;
        cp16(sSH + so, g_Sph + src);
        cp16(sSL + so, g_Spl + src);
    }
    asm volatile("cp.async.commit_group;" ::: "memory");

    if (tid < 64) zs[tid] = g_z[(size_t)cid * 64 + tid];
    if (tid < 128) den[tid] = 0.f;
    asm volatile("cp.async.wait_group 0;" ::: "memory");
    __syncthreads();

    const int r = lane >> 2, c2 = 2 * (lane & 3);
    const int arow = wm * 32 + (lane & 15);
    const int acol = (lane >> 4) * 8;
    const int brow = ((lane >> 4) << 3) + (lane & 7);
    const int bcol = ((lane >> 3) & 1) * 8;
    const int tkr = (lane & 7) | (((lane >> 3) & 1) << 3);
    const int tnc = (lane >> 4) << 3;
    const int rmax = wm * 32 + 31;

    // ---- phase 1: scores = q k^T (skip fully-masked tiles) ----
    float acc[2][8][4];
#pragma unroll
    for (int a = 0; a < 2; a++)
#pragma unroll
        for (int b = 0; b < 8; b++)
#pragma unroll
            for (int c = 0; c < 4; c++) acc[a][b][c] = 0.f;

    if (wn * 64 <= rmax) {
#pragma unroll
        for (int g = 0; g < 4; g++) {
            uint32_t qaf[2][4], qbf[2][4];
#pragma unroll
            for (int mt = 0; mt < 2; mt++) {
                uint32_t off = isw(arow + mt * 16, (acol + g * 16) * 2);
                ldm_x4(qaf[mt], sQH + off);
                ldm_x4(qbf[mt], sQL + off);
            }
            uint32_t kaf[4][4], kbf2[4][4];
#pragma unroll
            for (int p = 0; p < 4; p++) {
                if (wn * 64 + p * 16 <= rmax) {
                    uint32_t off = isw(wn * 64 + brow + p * 16, (bcol + g * 16) * 2);
                    ldm_x4(kaf[p], sKH + off);
                    ldm_x4(kbf2[p], sKL + off);
                }
            }
#pragma unroll
            for (int mt = 0; mt < 2; mt++)
#pragma unroll
                for (int nt = 0; nt < 8; nt++) {
                    if (wn * 64 + nt * 8 <= wm * 32 + mt * 16 + 15) {
                        const uint32_t* b1 = &kaf[nt >> 1][(nt & 1) * 2];
                        const uint32_t* b2 = &kbf2[nt >> 1][(nt & 1) * 2];
                        mma16816(acc[mt][nt], qaf[mt], b1);
                        mma16816(acc[mt][nt], qaf[mt], b2);
                        mma16816(acc[mt][nt], qbf[mt], b1);
                    }
                }
        }
    }

    // ---- mask + rowsum (den) + split scores ----
    uint32_t shf[2][4][4], slf[2][4][4];
#pragma unroll
    for (int mt = 0; mt < 2; mt++) {
        float rs0 = 0.f, rs1 = 0.f;
        int i0 = wm * 32 + mt * 16 + r, i1 = i0 + 8;
#pragma unroll
        for (int nt = 0; nt < 8; nt++) {
            int j0 = wn * 64 + nt * 8 + c2;
            float s00 = (j0     <= i0) ? acc[mt][nt][0] : 0.f;
            float s01 = (j0 + 1 <= i0) ? acc[mt][nt][1] : 0.f;
            float s10 = (j0     <= i1) ? acc[mt][nt][2] : 0.f;
            float s11 = (j0 + 1 <= i1) ? acc[mt][nt][3] : 0.f;
            rs0 += s00 + s01;
            rs1 += s10 + s11;
            int g = nt >> 1, hh = (nt & 1) * 2;
            shf[mt][g][hh]     = pk2(s00, s01);
            shf[mt][g][hh + 1] = pk2(s10, s11);
            slf[mt][g][hh]     = pk2(s00 - bfh(s00), s01 - bfh(s01));
            slf[mt][g][hh + 1] = pk2(s10 - bfh(s10), s11 - bfh(s11));
        }
        rs0 += __shfl_xor_sync(0xffffffffu, rs0, 1);
        rs0 += __shfl_xor_sync(0xffffffffu, rs0, 2);
        rs1 += __shfl_xor_sync(0xffffffffu, rs1, 1);
        rs1 += __shfl_xor_sync(0xffffffffu, rs1, 2);
        if ((lane & 3) == 0 && wn * 64 <= rmax) {
            atomicAdd(&den[i0], rs0);
            atomicAdd(&den[i1], rs1);
        }
    }

    // ---- den += q . z ----
    if (tid < 128) {
        float s = 0.f;
        int tmask = tid & 7;
#pragma unroll 8
        for (int d = 0; d < 64; d++) {
            uint32_t off = (uint32_t)(tid * 128 + ((((d >> 3) ^ tmask) << 4) | ((d & 7) * 2)));
            float qv = __bfloat162float(*(__nv_bfloat16*)(smc + OFF_QH + off)) +
                       __bfloat162float(*(__nv_bfloat16*)(smc + OFF_QL + off));
            s += qv * zs[d];
        }
        atomicAdd(&den[tid], s);
    }

    // ---- phase 2 in two output-column halves ----
    const int bidx = bh >> 4, hd = bh & 15;
#pragma unroll 1
    for (int eh = 0; eh < 2; eh++) {
        float acc2[2][4][4];
#pragma unroll
        for (int a = 0; a < 2; a++)
#pragma unroll
            for (int b = 0; b < 4; b++)
#pragma unroll
                for (int c = 0; c < 4; c++) acc2[a][b][c] = 0.f;

#pragma unroll
        for (int g = 0; g < 4; g++) {
            if (wn * 64 + g * 16 <= rmax) {
                uint32_t vaf[2][4], vbf2[2][4];
#pragma unroll
                for (int p2 = 0; p2 < 2; p2++) {
                    int pg = eh * 2 + p2;
                    uint32_t off = isw(wn * 64 + g * 16 + tkr, (pg * 16 + tnc) * 2);
                    ldm_x4_t(vaf[p2], sVH + off);
                    ldm_x4_t(vbf2[p2], sVL + off);
                }
#pragma unroll
                for (int mt = 0; mt < 2; mt++) {
                    if (wn * 64 + g * 16 <= wm * 32 + mt * 16 + 15) {
#pragma unroll
                        for (int nt = 0; nt < 4; nt++) {
                            const uint32_t* b1 = &vaf[nt >> 1][(nt & 1) * 2];
                            const uint32_t* b2 = &vbf2[nt >> 1][(nt & 1) * 2];
                            mma16816(acc2[mt][nt], shf[mt][g], b1);
                            mma16816(acc2[mt][nt], shf[mt][g], b2);
                            mma16816(acc2[mt][nt], slf[mt][g], b1);
                        }
                    }
                }
            }
        }
#pragma unroll
        for (int g2 = 0; g2 < 2; g2++) {
            int gd = wn * 2 + g2;
            uint32_t qaf[2][4], qbf[2][4];
#pragma unroll
            for (int mt = 0; mt < 2; mt++) {
                uint32_t off = isw(arow + mt * 16, (acol + gd * 16) * 2);
                ldm_x4(qaf[mt], sQH + off);
                ldm_x4(qbf[mt], sQL + off);
            }
            uint32_t Saf[2][4], Sbf2[2][4];
#pragma unroll
            for (int p2 = 0; p2 < 2; p2++) {
                int pg = eh * 2 + p2;
                uint32_t off = isw(gd * 16 + tkr, (pg * 16 + tnc) * 2);
                ldm_x4_t(Saf[p2], sSH + off);
                ldm_x4_t(Sbf2[p2], sSL + off);
            }
#pragma unroll
            for (int mt = 0; mt < 2; mt++)
#pragma unroll
                for (int nt = 0; nt < 4; nt++) {
                    const uint32_t* b1 = &Saf[nt >> 1][(nt & 1) * 2];
                    const uint32_t* b2 = &Sbf2[nt >> 1][(nt & 1) * 2];
                    mma16816(acc2[mt][nt], qaf[mt], b1);
                    mma16816(acc2[mt][nt], qaf[mt], b2);
                    mma16816(acc2[mt][nt], qbf[mt], b1);
                }
        }

        __syncthreads();
        if (wn == 0) {
#pragma unroll
            for (int mt = 0; mt < 2; mt++) {
                int i0 = wm * 32 + mt * 16 + r;
#pragma unroll
                for (int nt = 0; nt < 4; nt++) {
                    int cl = nt * 8 + c2;
                    numb[i0 * 32 + cl]           = acc2[mt][nt][0];
                    numb[i0 * 32 + cl + 1]       = acc2[mt][nt][1];
                    numb[(i0 + 8) * 32 + cl]     = acc2[mt][nt][2];
                    numb[(i0 + 8) * 32 + cl + 1] = acc2[mt][nt][3];
                }
            }
        }
        __syncthreads();
        if (wn == 1) {
#pragma unroll
            for (int mt = 0; mt < 2; mt++) {
                int i0 = wm * 32 + mt * 16 + r;
                float dr0 = 1.f / fmaxf(den[i0], 1e-3f);
                float dr1 = 1.f / fmaxf(den[i0 + 8], 1e-3f);
                int l0 = nch * CH + i0;
                size_t ob0 = ((size_t)bidx * LL + l0) * DD + hd * 64 + eh * 32;
                size_t ob1 = ((size_t)bidx * LL + l0 + 8) * DD + hd * 64 + eh * 32;
#pragma unroll
                for (int nt = 0; nt < 4; nt++) {
                    int cl = nt * 8 + c2;
                    float o00 = (acc2[mt][nt][0] + numb[i0 * 32 + cl])           * dr0;
                    float o01 = (acc2[mt][nt][1] + numb[i0 * 32 + cl + 1])       * dr0;
                    float o10 = (acc2[mt][nt][2] + numb[(i0 + 8) * 32 + cl])     * dr1;
                    float o11 = (acc2[mt][nt][3] + numb[(i0 + 8) * 32 + cl + 1]) * dr1;
                    *reinterpret_cast<uint32_t*>(g_oh + ob0 + cl) = pk2(o00, o01);
                    *reinterpret_cast<uint32_t*>(g_oh + ob1 + cl) = pk2(o10, o11);
                    *reinterpret_cast<uint32_t*>(g_ol + ob0 + cl) =
                        pk2(o00 - bfh(o00), o01 - bfh(o01));
                    *reinterpret_cast<uint32_t*>(g_ol + ob1 + cl) =
                        pk2(o10 - bfh(o10), o11 - bfh(o11));
                }
            }
        }
        __syncthreads();
    }
}

// =======================================================================
extern "C" void kernel_launch(void* const* d_in, const int* in_sizes, int n_in,
                              void* d_out, int out_size)
{
    const float* x  = (const float*)d_in[0];
    const float* Wq = (const float*)d_in[1];
    const float* bq = (const float*)d_in[2];
    const float* Wk = (const float*)d_in[3];
    const float* bk = (const float*)d_in[4];
    const float* Wv = (const float*)d_in[5];
    const float* bv = (const float*)d_in[6];
    const float* Wo = (const float*)d_in[7];
    const float* bo = (const float*)d_in[8];
    float* out = (float*)d_out;

    cudaFuncSetAttribute(chunk_state_kernel, cudaFuncAttributeMaxDynamicSharedMemorySize, CS_SMEM);
    cudaFuncSetAttribute(intra2_kernel, cudaFuncAttributeMaxDynamicSharedMemorySize, INTRA2_SMEM);
    cudaFuncSetAttribute(gemm_tc, cudaFuncAttributeMaxDynamicSharedMemorySize, GEMM_SMEM);

    __nv_bfloat16 *xh, *xl;
    cudaGetSymbolAddress((void**)&xh, g_xh);
    cudaGetSymbolAddress((void**)&xl, g_xl);

    // 0) split fp32 inputs into bf16 hi/lo pairs
    split_all_kernel<<<(BB*LL*DD + 4*DD*DD) / 1024, 256>>>(x, Wq, Wk, Wv, Wo);

    // 1) fused QKV projection (2 CTAs/SM)
    gemm_tc<<<dim3(24, 64), 256, GEMM_SMEM>>>(xh, xl, bq, bk, bv, nullptr, 1);

    // 2) per-chunk kv state + k sums (tensor cores)
    chunk_state_kernel<<<BB * HH * NC, 256, CS_SMEM>>>();

    // 3) exclusive prefix; emits split-bf16 S
    prefix2_kernel<<<(64 * (4096 + 64) + 255) / 256, 256>>>();

    // 4) intra-chunk attention (2 CTAs/SM, causal-skip)
    intra2_kernel<<<BB * HH * NC, 256, INTRA2_SMEM>>>();

    // 5) output projection
    gemm_tc<<<dim3(8, 64), 256, GEMM_SMEM>>>(nullptr, nullptr, bo, bo, bo, out, 0);
}